// round 3
// baseline (speedup 1.0000x reference)
#include <cuda_runtime.h>
#include <cstdint>

#define N_NODES 100000
#define N_EDGES 800000
#define H 128
#define HH (H*H)

// ---- scratch (no cudaMalloc allowed) ----
__device__ float g_bufA[N_NODES * H];
__device__ float g_bufB[N_NODES * H];
__device__ float g_Pl[N_NODES * H];
__device__ float g_Pr[N_NODES * H];
__device__ float g_inv[N_NODES];

// ---------------- degree ----------------
__global__ void k_deg(const int* __restrict__ dst, float* __restrict__ deg) {
    int e = blockIdx.x * 256 + threadIdx.x;
    if (e < N_EDGES) atomicAdd(deg + dst[e], 1.0f);
}
__global__ void k_inv(float* __restrict__ d) {
    int i = blockIdx.x * 256 + threadIdx.x;
    if (i < N_NODES) { float v = d[i]; d[i] = v > 0.f ? 1.f / v : 0.f; }
}

// ---------------- node projection: h = x @ W + b  (K=5) ----------------
__global__ void k_nodeproj(const float* __restrict__ x, const float* __restrict__ W,
                           const float* __restrict__ b, float* __restrict__ h) {
    int idx = blockIdx.x * 256 + threadIdx.x;
    if (idx >= N_NODES * H) return;
    int n = idx >> 7, j = idx & 127;
    float acc = b[j];
#pragma unroll
    for (int k = 0; k < 5; k++) acc = fmaf(x[n * 5 + k], W[k * H + j], acc);
    h[idx] = acc;
}

// ---------------- scatter-add: agg[dst] += h[src], warp per edge ----------------
__global__ void k_scatter(const int* __restrict__ src, const int* __restrict__ dst,
                          const float* __restrict__ h, float* __restrict__ agg) {
    int w = (blockIdx.x * blockDim.x + threadIdx.x) >> 5;
    int lane = threadIdx.x & 31;
    if (w >= N_EDGES) return;
    int s = src[w], d = dst[w];
    float4 v = ((const float4*)(h + (size_t)s * H))[lane];
    float* p = agg + (size_t)d * H + lane * 4;
    asm volatile("red.global.add.v4.f32 [%0], {%1,%2,%3,%4};"
                 :: "l"(p), "f"(v.x), "f"(v.y), "f"(v.z), "f"(v.w) : "memory");
}

// ---------------- fused SAGE GEMM: t = (agg*inv)@Wl + bl + h@Wr, in-place into agg ----
// BM=64, BN=128, K=256 (4 chunks mean + 4 chunks h), 256 threads, thread tile 8x4
__global__ void __launch_bounds__(256) k_sage(
    const float* __restrict__ hX, float* __restrict__ aggY,
    const float* __restrict__ Wl, const float* __restrict__ bl,
    const float* __restrict__ Wr, const float* __restrict__ inv)
{
    __shared__ float Us[32 * 64];
    __shared__ float Vs[32 * 128];
    int t = threadIdx.x;
    int tx = t & 31, ty = t >> 5;
    int row0 = blockIdx.x * 64;
    float acc[8][4];
#pragma unroll
    for (int i = 0; i < 8; i++)
#pragma unroll
        for (int m = 0; m < 4; m++) acc[i][m] = 0.f;

    for (int c = 0; c < 8; c++) {
        const float* Usrc = (c < 4) ? aggY : hX;
        const float* Wp = (c < 4) ? Wl : Wr;
        int kbase = (c & 3) * 32;
#pragma unroll
        for (int p0 = 0; p0 < 2; p0++) {
            int p = t + p0 * 256;
            int r = p >> 3, kq = p & 7;
            int row = row0 + r;
            float4 u = make_float4(0.f, 0.f, 0.f, 0.f);
            if (row < N_NODES) {
                u = *(const float4*)(Usrc + (size_t)row * H + kbase + kq * 4);
                if (c < 4) { float iv = inv[row]; u.x *= iv; u.y *= iv; u.z *= iv; u.w *= iv; }
            }
            Us[(kq * 4 + 0) * 64 + r] = u.x;
            Us[(kq * 4 + 1) * 64 + r] = u.y;
            Us[(kq * 4 + 2) * 64 + r] = u.z;
            Us[(kq * 4 + 3) * 64 + r] = u.w;
        }
#pragma unroll
        for (int p0 = 0; p0 < 4; p0++) {
            int p = t + p0 * 256;
            int k = p >> 5, jq = p & 31;
            *(float4*)&Vs[k * 128 + jq * 4] = *(const float4*)(Wp + (kbase + k) * H + jq * 4);
        }
        __syncthreads();
#pragma unroll
        for (int kk = 0; kk < 32; kk++) {
            float4 va = *(float4*)&Vs[kk * 128 + tx * 4];
            float4 ua = *(float4*)&Us[kk * 64 + ty * 8];
            float4 ub = *(float4*)&Us[kk * 64 + ty * 8 + 4];
            float u[8] = {ua.x, ua.y, ua.z, ua.w, ub.x, ub.y, ub.z, ub.w};
#pragma unroll
            for (int i = 0; i < 8; i++) {
                acc[i][0] = fmaf(u[i], va.x, acc[i][0]);
                acc[i][1] = fmaf(u[i], va.y, acc[i][1]);
                acc[i][2] = fmaf(u[i], va.z, acc[i][2]);
                acc[i][3] = fmaf(u[i], va.w, acc[i][3]);
            }
        }
        __syncthreads();
    }
    float4 bb = *(const float4*)(bl + tx * 4);
#pragma unroll
    for (int i = 0; i < 8; i++) {
        int row = row0 + ty * 8 + i;
        if (row < N_NODES) {
            float4 o;
            o.x = acc[i][0] + bb.x; o.y = acc[i][1] + bb.y;
            o.z = acc[i][2] + bb.z; o.w = acc[i][3] + bb.w;
            *(float4*)(aggY + (size_t)row * H + tx * 4) = o;
        }
    }
}

// ---------------- LayerNorm + ReLU, warp per row ----------------
__global__ void k_ln(float* __restrict__ h, const float* __restrict__ g,
                     const float* __restrict__ b) {
    int w = (blockIdx.x * blockDim.x + threadIdx.x) >> 5;
    int lane = threadIdx.x & 31;
    if (w >= N_NODES) return;
    float4* p = (float4*)(h + (size_t)w * H);
    float4 v = p[lane];
    float s = v.x + v.y + v.z + v.w;
#pragma unroll
    for (int o = 16; o; o >>= 1) s += __shfl_xor_sync(0xffffffffu, s, o);
    float mu = s * (1.f / 128.f);
    float dx = v.x - mu, dy = v.y - mu, dz = v.z - mu, dw = v.w - mu;
    float q = dx * dx + dy * dy + dz * dz + dw * dw;
#pragma unroll
    for (int o = 16; o; o >>= 1) q += __shfl_xor_sync(0xffffffffu, q, o);
    float rs = rsqrtf(q * (1.f / 128.f) + 1e-5f);
    float4 gg = *(const float4*)(g + lane * 4);
    float4 bv = *(const float4*)(b + lane * 4);
    v.x = fmaxf(fmaf(dx * rs, gg.x, bv.x), 0.f);
    v.y = fmaxf(fmaf(dy * rs, gg.y, bv.y), 0.f);
    v.z = fmaxf(fmaf(dz * rs, gg.z, bv.z), 0.f);
    v.w = fmaxf(fmaf(dw * rs, gg.w, bv.w), 0.f);
    p[lane] = v;
}

// ---------------- Pl = h@W1[0:128]+b1 ; Pr = h@W1[128:256]  (dual GEMM) ----------------
__global__ void __launch_bounds__(256) k_plpr(
    const float* __restrict__ h, const float* __restrict__ W1, const float* __restrict__ b1,
    float* __restrict__ Pl, float* __restrict__ Pr)
{
    __shared__ float Us[32 * 64];
    __shared__ float Vl[32 * 128];
    __shared__ float Vr[32 * 128];
    int t = threadIdx.x;
    int tx = t & 31, ty = t >> 5;
    int row0 = blockIdx.x * 64;
    float accl[8][4], accr[8][4];
#pragma unroll
    for (int i = 0; i < 8; i++)
#pragma unroll
        for (int m = 0; m < 4; m++) { accl[i][m] = 0.f; accr[i][m] = 0.f; }

    for (int c = 0; c < 4; c++) {
        int kbase = c * 32;
#pragma unroll
        for (int p0 = 0; p0 < 2; p0++) {
            int p = t + p0 * 256;
            int r = p >> 3, kq = p & 7;
            int row = row0 + r;
            float4 u = make_float4(0.f, 0.f, 0.f, 0.f);
            if (row < N_NODES)
                u = *(const float4*)(h + (size_t)row * H + kbase + kq * 4);
            Us[(kq * 4 + 0) * 64 + r] = u.x;
            Us[(kq * 4 + 1) * 64 + r] = u.y;
            Us[(kq * 4 + 2) * 64 + r] = u.z;
            Us[(kq * 4 + 3) * 64 + r] = u.w;
        }
#pragma unroll
        for (int p0 = 0; p0 < 4; p0++) {
            int p = t + p0 * 256;
            int k = p >> 5, jq = p & 31;
            *(float4*)&Vl[k * 128 + jq * 4] = *(const float4*)(W1 + (kbase + k) * H + jq * 4);
            *(float4*)&Vr[k * 128 + jq * 4] = *(const float4*)(W1 + (128 + kbase + k) * H + jq * 4);
        }
        __syncthreads();
#pragma unroll
        for (int kk = 0; kk < 32; kk++) {
            float4 va = *(float4*)&Vl[kk * 128 + tx * 4];
            float4 vb = *(float4*)&Vr[kk * 128 + tx * 4];
            float4 ua = *(float4*)&Us[kk * 64 + ty * 8];
            float4 ub = *(float4*)&Us[kk * 64 + ty * 8 + 4];
            float u[8] = {ua.x, ua.y, ua.z, ua.w, ub.x, ub.y, ub.z, ub.w};
#pragma unroll
            for (int i = 0; i < 8; i++) {
                accl[i][0] = fmaf(u[i], va.x, accl[i][0]);
                accl[i][1] = fmaf(u[i], va.y, accl[i][1]);
                accl[i][2] = fmaf(u[i], va.z, accl[i][2]);
                accl[i][3] = fmaf(u[i], va.w, accl[i][3]);
                accr[i][0] = fmaf(u[i], vb.x, accr[i][0]);
                accr[i][1] = fmaf(u[i], vb.y, accr[i][1]);
                accr[i][2] = fmaf(u[i], vb.z, accr[i][2]);
                accr[i][3] = fmaf(u[i], vb.w, accr[i][3]);
            }
        }
        __syncthreads();
    }
    float4 bb = *(const float4*)(b1 + tx * 4);
#pragma unroll
    for (int i = 0; i < 8; i++) {
        int row = row0 + ty * 8 + i;
        if (row < N_NODES) {
            float4 ol, orr;
            ol.x = accl[i][0] + bb.x; ol.y = accl[i][1] + bb.y;
            ol.z = accl[i][2] + bb.z; ol.w = accl[i][3] + bb.w;
            orr.x = accr[i][0]; orr.y = accr[i][1]; orr.z = accr[i][2]; orr.w = accr[i][3];
            *(float4*)(Pl + (size_t)row * H + tx * 4) = ol;
            *(float4*)(Pr + (size_t)row * H + tx * 4) = orr;
        }
    }
}

// ---------------- fused edge MLP ----------------
// TE=64 edges per block, 256 threads.
// Phase1: z1[e][j] = relu(Pl[src]+Pr[dst]+ea@W1e)  -> smem (row stride 132)
// Phase2: warp w owns edges w*8..w*8+7; lane computes outputs {lane, lane+32};
//         z1 loads are warp-broadcast -> FMA-pipe bound.
#define TE 64
#define Z1S (TE * 132)
__global__ void __launch_bounds__(256) k_edge(
    const int* __restrict__ src, const int* __restrict__ dst,
    const float* __restrict__ ea, const float* __restrict__ Pl,
    const float* __restrict__ Pr, const float* __restrict__ W1,
    const float* __restrict__ W2, const float* __restrict__ b2,
    const float* __restrict__ W3, const float* __restrict__ b3,
    float* __restrict__ out)
{
    extern __shared__ float sm[];
    float* z1s = sm;                  // TE*132
    float* W2s = sm + Z1S;            // 128*64
    float* W1es = W2s + 128 * 64;     // 12*128
    float* W3s = W1es + 12 * 128;     // 64
    float* b2s = W3s + 64;            // 64

    int t = threadIdx.x;
    for (int i = t; i < 128 * 64 / 4; i += 256)
        ((float4*)W2s)[i] = ((const float4*)W2)[i];
    for (int i = t; i < 12 * 128 / 4; i += 256)
        ((float4*)W1es)[i] = ((const float4*)(W1 + 256 * H))[i];
    if (t < 64) { W3s[t] = W3[t]; b2s[t] = b2[t]; }

    int e0 = blockIdx.x * TE;
    int el = t >> 2;               // 0..63 local edge
    int jq0 = (t & 3) * 8;         // float4 group base (covers 32 features)
    int eg = e0 + el;
    int s = src[eg], d = dst[eg];
    float eav[12];
#pragma unroll
    for (int k = 0; k < 12; k++) eav[k] = ea[(size_t)eg * 12 + k];
    __syncthreads();   // weights ready

    const float4* pl4 = (const float4*)(Pl + (size_t)s * H);
    const float4* pr4 = (const float4*)(Pr + (size_t)d * H);
#pragma unroll
    for (int jj = 0; jj < 8; jj++) {
        int jqi = jq0 + jj;
        float4 a = pl4[jqi];
        float4 bq = pr4[jqi];
        float4 sv = make_float4(a.x + bq.x, a.y + bq.y, a.z + bq.z, a.w + bq.w);
#pragma unroll
        for (int k = 0; k < 12; k++) {
            float4 w = *(const float4*)&W1es[k * 128 + jqi * 4];
            sv.x = fmaf(eav[k], w.x, sv.x);
            sv.y = fmaf(eav[k], w.y, sv.y);
            sv.z = fmaf(eav[k], w.z, sv.z);
            sv.w = fmaf(eav[k], w.w, sv.w);
        }
        sv.x = fmaxf(sv.x, 0.f); sv.y = fmaxf(sv.y, 0.f);
        sv.z = fmaxf(sv.z, 0.f); sv.w = fmaxf(sv.w, 0.f);
        *(float4*)&z1s[el * 132 + jqi * 4] = sv;
    }
    __syncthreads();

    int warp = t >> 5, lane = t & 31;
    int eb = warp * 8;
    float acc[8][2];
#pragma unroll
    for (int i = 0; i < 8; i++) { acc[i][0] = 0.f; acc[i][1] = 0.f; }
    int o0 = lane, o1 = lane + 32;
#pragma unroll 4
    for (int k = 0; k < 128; k++) {
        float w0 = W2s[k * 64 + o0];
        float w1 = W2s[k * 64 + o1];
#pragma unroll
        for (int i = 0; i < 8; i++) {
            float z = z1s[(eb + i) * 132 + k];
            acc[i][0] = fmaf(z, w0, acc[i][0]);
            acc[i][1] = fmaf(z, w1, acc[i][1]);
        }
    }
    float w3a = W3s[o0], w3b = W3s[o1];
    float bb0 = b2s[o0], bb1 = b2s[o1];
    float pred[8];
#pragma unroll
    for (int i = 0; i < 8; i++) {
        float z2a = fmaxf(acc[i][0] + bb0, 0.f);
        float z2b = fmaxf(acc[i][1] + bb1, 0.f);
        float part = z2a * w3a + z2b * w3b;
#pragma unroll
        for (int o = 16; o; o >>= 1) part += __shfl_xor_sync(0xffffffffu, part, o);
        pred[i] = part;
    }
    if (lane == 0) {
        float b3v = b3[0];
#pragma unroll
        for (int i = 0; i < 8; i++) {
            float x = pred[i] + b3v;
            out[e0 + eb + i] = fmaxf(x, 0.f) + log1pf(expf(-fabsf(x)));
        }
    }
}

// ---------------- launch ----------------
extern "C" void kernel_launch(void* const* d_in, const int* in_sizes, int n_in,
                              void* d_out, int out_size) {
    const float* x      = (const float*)d_in[0];
    const int*   ei     = (const int*)d_in[1];
    const float* ea     = (const float*)d_in[2];
    const float* node_W = (const float*)d_in[3];
    const float* node_b = (const float*)d_in[4];
    const float* sWl    = (const float*)d_in[5];
    const float* sbl    = (const float*)d_in[6];
    const float* sWr    = (const float*)d_in[7];
    const float* ln_g   = (const float*)d_in[8];
    const float* ln_b   = (const float*)d_in[9];
    const float* W1     = (const float*)d_in[10];
    const float* b1     = (const float*)d_in[11];
    const float* W2     = (const float*)d_in[12];
    const float* b2     = (const float*)d_in[13];
    const float* W3     = (const float*)d_in[14];
    const float* b3     = (const float*)d_in[15];
    float* out = (float*)d_out;
    const int* src = ei;
    const int* dstp = ei + N_EDGES;

    float *pA, *pB, *pPl, *pPr, *pInv;
    cudaGetSymbolAddress((void**)&pA, g_bufA);
    cudaGetSymbolAddress((void**)&pB, g_bufB);
    cudaGetSymbolAddress((void**)&pPl, g_Pl);
    cudaGetSymbolAddress((void**)&pPr, g_Pr);
    cudaGetSymbolAddress((void**)&pInv, g_inv);

    cudaMemsetAsync(pInv, 0, N_NODES * sizeof(float));
    k_deg<<<(N_EDGES + 255) / 256, 256>>>(dstp, pInv);
    k_inv<<<(N_NODES + 255) / 256, 256>>>(pInv);

    k_nodeproj<<<(N_NODES * H + 255) / 256, 256>>>(x, node_W, node_b, pA);

    float* hcur = pA;
    float* other = pB;
    for (int l = 0; l < 3; l++) {
        cudaMemsetAsync(other, 0, (size_t)N_NODES * H * sizeof(float));
        k_scatter<<<N_EDGES / 8, 256>>>(src, dstp, hcur, other);
        k_sage<<<(N_NODES + 63) / 64, 256>>>(hcur, other, sWl + l * HH, sbl + l * H,
                                             sWr + l * HH, pInv);
        k_ln<<<(N_NODES + 7) / 8, 256>>>(other, ln_g + l * H, ln_b + l * H);
        float* tmp = hcur; hcur = other; other = tmp;
    }

    k_plpr<<<(N_NODES + 63) / 64, 256>>>(hcur, W1, b1, pPl, pPr);

    int smem_edge = (Z1S + 128 * 64 + 12 * 128 + 128) * sizeof(float);
    cudaFuncSetAttribute(k_edge, cudaFuncAttributeMaxDynamicSharedMemorySize, smem_edge);
    k_edge<<<N_EDGES / TE, 256, smem_edge>>>(src, dstp, ea, pPl, pPr, W1, W2, b2, W3, b3, out);
}

// round 4
// speedup vs baseline: 1.3133x; 1.3133x over previous
#include <cuda_runtime.h>
#include <cstdint>

#define N_NODES 100000
#define N_EDGES 800000
#define H 128
#define HH (H*H)

// ---- scratch (no cudaMalloc allowed) ----
__device__ float g_bufA[N_NODES * H];
__device__ float g_bufB[N_NODES * H];
__device__ float g_Pl[N_NODES * H];
__device__ float g_Pr[N_NODES * H];
__device__ float g_inv[N_NODES];

// ---- packed fp32x2 helpers (B300: fma.rn.f32x2 doubles fp32 FMA throughput) ----
__device__ __forceinline__ unsigned long long pk2(float x, float y) {
    unsigned long long r;
    asm("mov.b64 %0, {%1, %2};" : "=l"(r) : "f"(x), "f"(y));
    return r;
}
__device__ __forceinline__ unsigned long long dup2(float x) { return pk2(x, x); }
__device__ __forceinline__ void fma2(unsigned long long& d, unsigned long long a,
                                     unsigned long long b) {
    asm("fma.rn.f32x2 %0, %1, %2, %0;" : "+l"(d) : "l"(a), "l"(b));
}
__device__ __forceinline__ float2 upk2(unsigned long long v) {
    float2 f;
    asm("mov.b64 {%0, %1}, %2;" : "=f"(f.x), "=f"(f.y) : "l"(v));
    return f;
}

// ---------------- degree ----------------
__global__ void k_deg(const int* __restrict__ dst, float* __restrict__ deg) {
    int e = blockIdx.x * 256 + threadIdx.x;
    if (e < N_EDGES) atomicAdd(deg + dst[e], 1.0f);
}
__global__ void k_inv(float* __restrict__ d) {
    int i = blockIdx.x * 256 + threadIdx.x;
    if (i < N_NODES) { float v = d[i]; d[i] = v > 0.f ? 1.f / v : 0.f; }
}

// ---------------- node projection: h = x @ W + b  (K=5) ----------------
__global__ void k_nodeproj(const float* __restrict__ x, const float* __restrict__ W,
                           const float* __restrict__ b, float* __restrict__ h) {
    int idx = blockIdx.x * 256 + threadIdx.x;
    if (idx >= N_NODES * H) return;
    int n = idx >> 7, j = idx & 127;
    float acc = b[j];
#pragma unroll
    for (int k = 0; k < 5; k++) acc = fmaf(x[n * 5 + k], W[k * H + j], acc);
    h[idx] = acc;
}

// ---------------- scatter-add: agg[dst] += h[src], warp per edge ----------------
__global__ void k_scatter(const int* __restrict__ src, const int* __restrict__ dst,
                          const float* __restrict__ h, float* __restrict__ agg) {
    int w = (blockIdx.x * blockDim.x + threadIdx.x) >> 5;
    int lane = threadIdx.x & 31;
    if (w >= N_EDGES) return;
    int s = src[w], d = dst[w];
    float4 v = ((const float4*)(h + (size_t)s * H))[lane];
    float* p = agg + (size_t)d * H + lane * 4;
    asm volatile("red.global.add.v4.f32 [%0], {%1,%2,%3,%4};"
                 :: "l"(p), "f"(v.x), "f"(v.y), "f"(v.z), "f"(v.w) : "memory");
}

// ---------------- fused SAGE GEMM: t = (agg*inv)@Wl + bl + h@Wr, in-place into agg ----
// BM=64, BN=128, K=256 (4 chunks mean + 4 chunks h), 256 threads, thread tile 8x4.
// Mainloop in packed f32x2: row pairs come packed straight out of smem.
__global__ void __launch_bounds__(256) k_sage(
    const float* __restrict__ hX, float* __restrict__ aggY,
    const float* __restrict__ Wl, const float* __restrict__ bl,
    const float* __restrict__ Wr, const float* __restrict__ inv)
{
    __shared__ float Us[32 * 64];
    __shared__ float Vs[32 * 128];
    int t = threadIdx.x;
    int tx = t & 31, ty = t >> 5;
    int row0 = blockIdx.x * 64;
    unsigned long long acc[4][4];  // [rowpair][col]
#pragma unroll
    for (int i = 0; i < 4; i++)
#pragma unroll
        for (int m = 0; m < 4; m++) acc[i][m] = 0ull;

    for (int c = 0; c < 8; c++) {
        const float* Usrc = (c < 4) ? aggY : hX;
        const float* Wp = (c < 4) ? Wl : Wr;
        int kbase = (c & 3) * 32;
#pragma unroll
        for (int p0 = 0; p0 < 2; p0++) {
            int p = t + p0 * 256;
            int r = p >> 3, kq = p & 7;
            int row = row0 + r;
            float4 u = make_float4(0.f, 0.f, 0.f, 0.f);
            if (row < N_NODES) {
                u = *(const float4*)(Usrc + (size_t)row * H + kbase + kq * 4);
                if (c < 4) { float iv = inv[row]; u.x *= iv; u.y *= iv; u.z *= iv; u.w *= iv; }
            }
            Us[(kq * 4 + 0) * 64 + r] = u.x;
            Us[(kq * 4 + 1) * 64 + r] = u.y;
            Us[(kq * 4 + 2) * 64 + r] = u.z;
            Us[(kq * 4 + 3) * 64 + r] = u.w;
        }
#pragma unroll
        for (int p0 = 0; p0 < 4; p0++) {
            int p = t + p0 * 256;
            int k = p >> 5, jq = p & 31;
            *(float4*)&Vs[k * 128 + jq * 4] = *(const float4*)(Wp + (kbase + k) * H + jq * 4);
        }
        __syncthreads();
#pragma unroll
        for (int kk = 0; kk < 32; kk++) {
            float4 va = *(float4*)&Vs[kk * 128 + tx * 4];
            ulonglong2 p0 = *(ulonglong2*)&Us[kk * 64 + ty * 8];
            ulonglong2 p1 = *(ulonglong2*)&Us[kk * 64 + ty * 8 + 4];
            unsigned long long d0 = dup2(va.x), d1 = dup2(va.y);
            unsigned long long d2 = dup2(va.z), d3 = dup2(va.w);
            fma2(acc[0][0], p0.x, d0); fma2(acc[1][0], p0.y, d0);
            fma2(acc[2][0], p1.x, d0); fma2(acc[3][0], p1.y, d0);
            fma2(acc[0][1], p0.x, d1); fma2(acc[1][1], p0.y, d1);
            fma2(acc[2][1], p1.x, d1); fma2(acc[3][1], p1.y, d1);
            fma2(acc[0][2], p0.x, d2); fma2(acc[1][2], p0.y, d2);
            fma2(acc[2][2], p1.x, d2); fma2(acc[3][2], p1.y, d2);
            fma2(acc[0][3], p0.x, d3); fma2(acc[1][3], p0.y, d3);
            fma2(acc[2][3], p1.x, d3); fma2(acc[3][3], p1.y, d3);
        }
        __syncthreads();
    }
    float4 bb = *(const float4*)(bl + tx * 4);
    float v[8][4];
#pragma unroll
    for (int rp = 0; rp < 4; rp++)
#pragma unroll
        for (int m = 0; m < 4; m++) {
            float2 f = upk2(acc[rp][m]);
            v[2 * rp][m] = f.x; v[2 * rp + 1][m] = f.y;
        }
#pragma unroll
    for (int i = 0; i < 8; i++) {
        int row = row0 + ty * 8 + i;
        if (row < N_NODES) {
            float4 o;
            o.x = v[i][0] + bb.x; o.y = v[i][1] + bb.y;
            o.z = v[i][2] + bb.z; o.w = v[i][3] + bb.w;
            *(float4*)(aggY + (size_t)row * H + tx * 4) = o;
        }
    }
}

// ---------------- LayerNorm + ReLU, warp per row ----------------
__global__ void k_ln(float* __restrict__ h, const float* __restrict__ g,
                     const float* __restrict__ b) {
    int w = (blockIdx.x * blockDim.x + threadIdx.x) >> 5;
    int lane = threadIdx.x & 31;
    if (w >= N_NODES) return;
    float4* p = (float4*)(h + (size_t)w * H);
    float4 v = p[lane];
    float s = v.x + v.y + v.z + v.w;
#pragma unroll
    for (int o = 16; o; o >>= 1) s += __shfl_xor_sync(0xffffffffu, s, o);
    float mu = s * (1.f / 128.f);
    float dx = v.x - mu, dy = v.y - mu, dz = v.z - mu, dw = v.w - mu;
    float q = dx * dx + dy * dy + dz * dz + dw * dw;
#pragma unroll
    for (int o = 16; o; o >>= 1) q += __shfl_xor_sync(0xffffffffu, q, o);
    float rs = rsqrtf(q * (1.f / 128.f) + 1e-5f);
    float4 gg = *(const float4*)(g + lane * 4);
    float4 bv = *(const float4*)(b + lane * 4);
    v.x = fmaxf(fmaf(dx * rs, gg.x, bv.x), 0.f);
    v.y = fmaxf(fmaf(dy * rs, gg.y, bv.y), 0.f);
    v.z = fmaxf(fmaf(dz * rs, gg.z, bv.z), 0.f);
    v.w = fmaxf(fmaf(dw * rs, gg.w, bv.w), 0.f);
    p[lane] = v;
}

// ---------------- Pl = h@W1[0:128]+b1 ; Pr = h@W1[128:256]  (dual GEMM, f32x2) ----------
__global__ void __launch_bounds__(256) k_plpr(
    const float* __restrict__ h, const float* __restrict__ W1, const float* __restrict__ b1,
    float* __restrict__ Pl, float* __restrict__ Pr)
{
    __shared__ float Us[32 * 64];
    __shared__ float Vl[32 * 128];
    __shared__ float Vr[32 * 128];
    int t = threadIdx.x;
    int tx = t & 31, ty = t >> 5;
    int row0 = blockIdx.x * 64;
    unsigned long long accl[4][4], accr[4][4];
#pragma unroll
    for (int i = 0; i < 4; i++)
#pragma unroll
        for (int m = 0; m < 4; m++) { accl[i][m] = 0ull; accr[i][m] = 0ull; }

    for (int c = 0; c < 4; c++) {
        int kbase = c * 32;
#pragma unroll
        for (int p0 = 0; p0 < 2; p0++) {
            int p = t + p0 * 256;
            int r = p >> 3, kq = p & 7;
            int row = row0 + r;
            float4 u = make_float4(0.f, 0.f, 0.f, 0.f);
            if (row < N_NODES)
                u = *(const float4*)(h + (size_t)row * H + kbase + kq * 4);
            Us[(kq * 4 + 0) * 64 + r] = u.x;
            Us[(kq * 4 + 1) * 64 + r] = u.y;
            Us[(kq * 4 + 2) * 64 + r] = u.z;
            Us[(kq * 4 + 3) * 64 + r] = u.w;
        }
#pragma unroll
        for (int p0 = 0; p0 < 4; p0++) {
            int p = t + p0 * 256;
            int k = p >> 5, jq = p & 31;
            *(float4*)&Vl[k * 128 + jq * 4] = *(const float4*)(W1 + (kbase + k) * H + jq * 4);
            *(float4*)&Vr[k * 128 + jq * 4] = *(const float4*)(W1 + (128 + kbase + k) * H + jq * 4);
        }
        __syncthreads();
#pragma unroll
        for (int kk = 0; kk < 32; kk++) {
            ulonglong2 p0 = *(ulonglong2*)&Us[kk * 64 + ty * 8];
            ulonglong2 p1 = *(ulonglong2*)&Us[kk * 64 + ty * 8 + 4];
            float4 va = *(float4*)&Vl[kk * 128 + tx * 4];
            float4 vb = *(float4*)&Vr[kk * 128 + tx * 4];
            unsigned long long a0 = dup2(va.x), a1 = dup2(va.y);
            unsigned long long a2 = dup2(va.z), a3 = dup2(va.w);
            fma2(accl[0][0], p0.x, a0); fma2(accl[1][0], p0.y, a0);
            fma2(accl[2][0], p1.x, a0); fma2(accl[3][0], p1.y, a0);
            fma2(accl[0][1], p0.x, a1); fma2(accl[1][1], p0.y, a1);
            fma2(accl[2][1], p1.x, a1); fma2(accl[3][1], p1.y, a1);
            fma2(accl[0][2], p0.x, a2); fma2(accl[1][2], p0.y, a2);
            fma2(accl[2][2], p1.x, a2); fma2(accl[3][2], p1.y, a2);
            fma2(accl[0][3], p0.x, a3); fma2(accl[1][3], p0.y, a3);
            fma2(accl[2][3], p1.x, a3); fma2(accl[3][3], p1.y, a3);
            unsigned long long c0 = dup2(vb.x), c1 = dup2(vb.y);
            unsigned long long c2 = dup2(vb.z), c3 = dup2(vb.w);
            fma2(accr[0][0], p0.x, c0); fma2(accr[1][0], p0.y, c0);
            fma2(accr[2][0], p1.x, c0); fma2(accr[3][0], p1.y, c0);
            fma2(accr[0][1], p0.x, c1); fma2(accr[1][1], p0.y, c1);
            fma2(accr[2][1], p1.x, c1); fma2(accr[3][1], p1.y, c1);
            fma2(accr[0][2], p0.x, c2); fma2(accr[1][2], p0.y, c2);
            fma2(accr[2][2], p1.x, c2); fma2(accr[3][2], p1.y, c2);
            fma2(accr[0][3], p0.x, c3); fma2(accr[1][3], p0.y, c3);
            fma2(accr[2][3], p1.x, c3); fma2(accr[3][3], p1.y, c3);
        }
        __syncthreads();
    }
    float4 bb = *(const float4*)(b1 + tx * 4);
    float vl[8][4], vr[8][4];
#pragma unroll
    for (int rp = 0; rp < 4; rp++)
#pragma unroll
        for (int m = 0; m < 4; m++) {
            float2 f = upk2(accl[rp][m]);
            vl[2 * rp][m] = f.x; vl[2 * rp + 1][m] = f.y;
            float2 g2 = upk2(accr[rp][m]);
            vr[2 * rp][m] = g2.x; vr[2 * rp + 1][m] = g2.y;
        }
#pragma unroll
    for (int i = 0; i < 8; i++) {
        int row = row0 + ty * 8 + i;
        if (row < N_NODES) {
            float4 ol, orr;
            ol.x = vl[i][0] + bb.x; ol.y = vl[i][1] + bb.y;
            ol.z = vl[i][2] + bb.z; ol.w = vl[i][3] + bb.w;
            orr.x = vr[i][0]; orr.y = vr[i][1]; orr.z = vr[i][2]; orr.w = vr[i][3];
            *(float4*)(Pl + (size_t)row * H + tx * 4) = ol;
            *(float4*)(Pr + (size_t)row * H + tx * 4) = orr;
        }
    }
}

// ---------------- fused edge MLP ----------------
// TE=128 edges/block, 256 threads.
// Phase1: 2 threads/edge compute z1 = relu(Pl[src]+Pr[dst]+ea@W1e), store TRANSPOSED
//         z1T[k][e] (stride 136) for a clean GEMM phase2.
// Phase2: register-tiled GEMM M=128(edges) x N=64 x K=128 in packed f32x2,
//         then fused relu/W3 dot/softplus with 16-lane butterfly reduce.
#define TE 128
#define ST 136
__global__ void __launch_bounds__(256) k_edge(
    const int* __restrict__ src, const int* __restrict__ dst,
    const float* __restrict__ ea, const float* __restrict__ Pl,
    const float* __restrict__ Pr, const float* __restrict__ W1,
    const float* __restrict__ W2, const float* __restrict__ b2,
    const float* __restrict__ W3, const float* __restrict__ b3,
    float* __restrict__ out)
{
    extern __shared__ float sm[];
    float* z1T = sm;                       // 128 * 136
    float* W2s = z1T + 128 * ST;           // 128*64
    float* W1es = W2s + 128 * 64;          // 12*128
    float* W3s = W1es + 12 * 128;          // 64
    float* b2s = W3s + 64;                 // 64

    int t = threadIdx.x;
    for (int i = t; i < 128 * 64 / 4; i += 256)
        ((float4*)W2s)[i] = ((const float4*)W2)[i];
    for (int i = t; i < 12 * 128 / 4; i += 256)
        ((float4*)W1es)[i] = ((const float4*)(W1 + 256 * H))[i];
    if (t < 64) { W3s[t] = W3[t]; b2s[t] = b2[t]; }

    int e0 = blockIdx.x * TE;
    // ---- phase 1: two threads per edge, each 64 features (16 float4 groups)
    {
        int el = t >> 1;               // 0..127
        int jh = t & 1;                // feature half
        int eg = e0 + el;
        int s = src[eg], d = dst[eg];
        unsigned long long eadup[12];
#pragma unroll
        for (int k = 0; k < 12; k++) eadup[k] = dup2(ea[(size_t)eg * 12 + k]);
        __syncthreads();   // weights ready

        const float4* pl4 = (const float4*)(Pl + (size_t)s * H);
        const float4* pr4 = (const float4*)(Pr + (size_t)d * H);
#pragma unroll
        for (int g = 0; g < 16; g++) {
            int jqi = jh * 16 + g;
            float4 a = pl4[jqi];
            float4 bq = pr4[jqi];
            unsigned long long s01 = pk2(a.x + bq.x, a.y + bq.y);
            unsigned long long s23 = pk2(a.z + bq.z, a.w + bq.w);
#pragma unroll
            for (int k = 0; k < 12; k++) {
                ulonglong2 wp = *(const ulonglong2*)&W1es[k * 128 + jqi * 4];
                fma2(s01, wp.x, eadup[k]);
                fma2(s23, wp.y, eadup[k]);
            }
            float2 f01 = upk2(s01), f23 = upk2(s23);
            int kb = jqi * 4;
            z1T[(kb + 0) * ST + el] = fmaxf(f01.x, 0.f);
            z1T[(kb + 1) * ST + el] = fmaxf(f01.y, 0.f);
            z1T[(kb + 2) * ST + el] = fmaxf(f23.x, 0.f);
            z1T[(kb + 3) * ST + el] = fmaxf(f23.y, 0.f);
        }
    }
    __syncthreads();

    // ---- phase 2: GEMM 128x64x128, thread tile 8 rows x 4 cols
    int tx = t & 15;       // col group (cols tx*4..+3)
    int ty = t >> 4;       // row group (edges ty*8..+7)
    unsigned long long acc[4][4];
#pragma unroll
    for (int i = 0; i < 4; i++)
#pragma unroll
        for (int m = 0; m < 4; m++) acc[i][m] = 0ull;

#pragma unroll 4
    for (int kk = 0; kk < 128; kk++) {
        float4 w = *(float4*)&W2s[kk * 64 + tx * 4];
        ulonglong2 p0 = *(ulonglong2*)&z1T[kk * ST + ty * 8];
        ulonglong2 p1 = *(ulonglong2*)&z1T[kk * ST + ty * 8 + 4];
        unsigned long long d0 = dup2(w.x), d1 = dup2(w.y);
        unsigned long long d2 = dup2(w.z), d3 = dup2(w.w);
        fma2(acc[0][0], p0.x, d0); fma2(acc[1][0], p0.y, d0);
        fma2(acc[2][0], p1.x, d0); fma2(acc[3][0], p1.y, d0);
        fma2(acc[0][1], p0.x, d1); fma2(acc[1][1], p0.y, d1);
        fma2(acc[2][1], p1.x, d1); fma2(acc[3][1], p1.y, d1);
        fma2(acc[0][2], p0.x, d2); fma2(acc[1][2], p0.y, d2);
        fma2(acc[2][2], p1.x, d2); fma2(acc[3][2], p1.y, d2);
        fma2(acc[0][3], p0.x, d3); fma2(acc[1][3], p0.y, d3);
        fma2(acc[2][3], p1.x, d3); fma2(acc[3][3], p1.y, d3);
    }

    // epilogue: z2 = relu(acc + b2), partial = z2 . W3 over this thread's 4 cols
    float4 b2v = *(float4*)&b2s[tx * 4];
    float4 w3v = *(float4*)&W3s[tx * 4];
    float part[8];
#pragma unroll
    for (int rp = 0; rp < 4; rp++) {
        float2 f0 = upk2(acc[rp][0]);
        float2 f1 = upk2(acc[rp][1]);
        float2 f2 = upk2(acc[rp][2]);
        float2 f3 = upk2(acc[rp][3]);
        part[2 * rp] =
            fmaxf(f0.x + b2v.x, 0.f) * w3v.x + fmaxf(f1.x + b2v.y, 0.f) * w3v.y +
            fmaxf(f2.x + b2v.z, 0.f) * w3v.z + fmaxf(f3.x + b2v.w, 0.f) * w3v.w;
        part[2 * rp + 1] =
            fmaxf(f0.y + b2v.x, 0.f) * w3v.x + fmaxf(f1.y + b2v.y, 0.f) * w3v.y +
            fmaxf(f2.y + b2v.z, 0.f) * w3v.z + fmaxf(f3.y + b2v.w, 0.f) * w3v.w;
    }
#pragma unroll
    for (int i = 0; i < 8; i++) {
#pragma unroll
        for (int o = 8; o; o >>= 1)
            part[i] += __shfl_xor_sync(0xffffffffu, part[i], o);
    }
    if (tx == 0) {
        float b3v = b3[0];
#pragma unroll
        for (int i = 0; i < 8; i++) {
            float x = part[i] + b3v;
            out[e0 + ty * 8 + i] = fmaxf(x, 0.f) + log1pf(expf(-fabsf(x)));
        }
    }
}

// ---------------- launch ----------------
extern "C" void kernel_launch(void* const* d_in, const int* in_sizes, int n_in,
                              void* d_out, int out_size) {
    const float* x      = (const float*)d_in[0];
    const int*   ei     = (const int*)d_in[1];
    const float* ea     = (const float*)d_in[2];
    const float* node_W = (const float*)d_in[3];
    const float* node_b = (const float*)d_in[4];
    const float* sWl    = (const float*)d_in[5];
    const float* sbl    = (const float*)d_in[6];
    const float* sWr    = (const float*)d_in[7];
    const float* ln_g   = (const float*)d_in[8];
    const float* ln_b   = (const float*)d_in[9];
    const float* W1     = (const float*)d_in[10];
    const float* b1     = (const float*)d_in[11];
    const float* W2     = (const float*)d_in[12];
    const float* b2     = (const float*)d_in[13];
    const float* W3     = (const float*)d_in[14];
    const float* b3     = (const float*)d_in[15];
    float* out = (float*)d_out;
    const int* src = ei;
    const int* dstp = ei + N_EDGES;

    float *pA, *pB, *pPl, *pPr, *pInv;
    cudaGetSymbolAddress((void**)&pA, g_bufA);
    cudaGetSymbolAddress((void**)&pB, g_bufB);
    cudaGetSymbolAddress((void**)&pPl, g_Pl);
    cudaGetSymbolAddress((void**)&pPr, g_Pr);
    cudaGetSymbolAddress((void**)&pInv, g_inv);

    cudaMemsetAsync(pInv, 0, N_NODES * sizeof(float));
    k_deg<<<(N_EDGES + 255) / 256, 256>>>(dstp, pInv);
    k_inv<<<(N_NODES + 255) / 256, 256>>>(pInv);

    k_nodeproj<<<(N_NODES * H + 255) / 256, 256>>>(x, node_W, node_b, pA);

    float* hcur = pA;
    float* other = pB;
    for (int l = 0; l < 3; l++) {
        cudaMemsetAsync(other, 0, (size_t)N_NODES * H * sizeof(float));
        k_scatter<<<N_EDGES / 8, 256>>>(src, dstp, hcur, other);
        k_sage<<<(N_NODES + 63) / 64, 256>>>(hcur, other, sWl + l * HH, sbl + l * H,
                                             sWr + l * HH, pInv);
        k_ln<<<(N_NODES + 7) / 8, 256>>>(other, ln_g + l * H, ln_b + l * H);
        float* tmp = hcur; hcur = other; other = tmp;
    }

    k_plpr<<<(N_NODES + 63) / 64, 256>>>(hcur, W1, b1, pPl, pPr);

    int smem_edge = (128 * ST + 128 * 64 + 12 * 128 + 128) * sizeof(float);
    cudaFuncSetAttribute(k_edge, cudaFuncAttributeMaxDynamicSharedMemorySize, smem_edge);
    k_edge<<<N_EDGES / TE, 256, smem_edge>>>(src, dstp, ea, pPl, pPr, W1, W2, b2, W3, b3, out);
}

// round 5
// speedup vs baseline: 1.4848x; 1.1306x over previous
#include <cuda_runtime.h>
#include <cuda_bf16.h>
#include <cstdint>

#define N_NODES 100000
#define N_EDGES 800000
#define H 128
#define HH (H*H)

// ---- scratch (no cudaMalloc allowed) ----
__device__ float g_bufA[N_NODES * H];
__device__ float g_bufB[N_NODES * H];
__device__ __nv_bfloat16 g_Plh[N_NODES * H];
__device__ __nv_bfloat16 g_Prh[N_NODES * H];
__device__ float g_inv[N_NODES];

// ---- packed fp32x2 helpers (B300: fma.rn.f32x2 doubles fp32 FMA throughput) ----
__device__ __forceinline__ unsigned long long pk2(float x, float y) {
    unsigned long long r;
    asm("mov.b64 %0, {%1, %2};" : "=l"(r) : "f"(x), "f"(y));
    return r;
}
__device__ __forceinline__ unsigned long long dup2(float x) { return pk2(x, x); }
__device__ __forceinline__ void fma2(unsigned long long& d, unsigned long long a,
                                     unsigned long long b) {
    asm("fma.rn.f32x2 %0, %1, %2, %0;" : "+l"(d) : "l"(a), "l"(b));
}
__device__ __forceinline__ float2 upk2(unsigned long long v) {
    float2 f;
    asm("mov.b64 {%0, %1}, %2;" : "=f"(f.x), "=f"(f.y) : "l"(v));
    return f;
}
__device__ __forceinline__ float2 bf2f(unsigned int u) {
    __nv_bfloat162 b = *reinterpret_cast<__nv_bfloat162*>(&u);
    return __bfloat1622float2(b);
}

// ---------------- degree ----------------
__global__ void k_deg(const int* __restrict__ dst, float* __restrict__ deg) {
    int e = blockIdx.x * 256 + threadIdx.x;
    if (e < N_EDGES) atomicAdd(deg + dst[e], 1.0f);
}
__global__ void k_inv(float* __restrict__ d) {
    int i = blockIdx.x * 256 + threadIdx.x;
    if (i < N_NODES) { float v = d[i]; d[i] = v > 0.f ? 1.f / v : 0.f; }
}

// ---------------- node projection: h = x @ W + b  (K=5) ----------------
__global__ void k_nodeproj(const float* __restrict__ x, const float* __restrict__ W,
                           const float* __restrict__ b, float* __restrict__ h) {
    int idx = blockIdx.x * 256 + threadIdx.x;
    if (idx >= N_NODES * H) return;
    int n = idx >> 7, j = idx & 127;
    float acc = b[j];
#pragma unroll
    for (int k = 0; k < 5; k++) acc = fmaf(x[n * 5 + k], W[k * H + j], acc);
    h[idx] = acc;
}

// ---------------- scatter-add: agg[dst] += h[src], warp per edge ----------------
__global__ void k_scatter(const int* __restrict__ src, const int* __restrict__ dst,
                          const float* __restrict__ h, float* __restrict__ agg) {
    int w = (blockIdx.x * blockDim.x + threadIdx.x) >> 5;
    int lane = threadIdx.x & 31;
    if (w >= N_EDGES) return;
    int s = src[w], d = dst[w];
    float4 v = ((const float4*)(h + (size_t)s * H))[lane];
    float* p = agg + (size_t)d * H + lane * 4;
    asm volatile("red.global.add.v4.f32 [%0], {%1,%2,%3,%4};"
                 :: "l"(p), "f"(v.x), "f"(v.y), "f"(v.z), "f"(v.w) : "memory");
}

// ---------------- fused SAGE GEMM + LayerNorm + ReLU ----------------
// t = (agg*inv)@Wl + bl + h@Wr, then LN+ReLU, in-place into agg.
// BM=64, BN=128 (= full H, so each row is warp-owned -> warp-shuffle LN).
__global__ void __launch_bounds__(256) k_sage(
    const float* __restrict__ hX, float* __restrict__ aggY,
    const float* __restrict__ Wl, const float* __restrict__ bl,
    const float* __restrict__ Wr, const float* __restrict__ inv,
    const float* __restrict__ lg, const float* __restrict__ lb)
{
    __shared__ float Us[32 * 64];
    __shared__ float Vs[32 * 128];
    int t = threadIdx.x;
    int tx = t & 31, ty = t >> 5;
    int row0 = blockIdx.x * 64;
    unsigned long long acc[4][4];  // [rowpair][col]
#pragma unroll
    for (int i = 0; i < 4; i++)
#pragma unroll
        for (int m = 0; m < 4; m++) acc[i][m] = 0ull;

    for (int c = 0; c < 8; c++) {
        const float* Usrc = (c < 4) ? aggY : hX;
        const float* Wp = (c < 4) ? Wl : Wr;
        int kbase = (c & 3) * 32;
#pragma unroll
        for (int p0 = 0; p0 < 2; p0++) {
            int p = t + p0 * 256;
            int r = p >> 3, kq = p & 7;
            int row = row0 + r;
            float4 u = make_float4(0.f, 0.f, 0.f, 0.f);
            if (row < N_NODES) {
                u = *(const float4*)(Usrc + (size_t)row * H + kbase + kq * 4);
                if (c < 4) { float iv = inv[row]; u.x *= iv; u.y *= iv; u.z *= iv; u.w *= iv; }
            }
            Us[(kq * 4 + 0) * 64 + r] = u.x;
            Us[(kq * 4 + 1) * 64 + r] = u.y;
            Us[(kq * 4 + 2) * 64 + r] = u.z;
            Us[(kq * 4 + 3) * 64 + r] = u.w;
        }
#pragma unroll
        for (int p0 = 0; p0 < 4; p0++) {
            int p = t + p0 * 256;
            int k = p >> 5, jq = p & 31;
            *(float4*)&Vs[k * 128 + jq * 4] = *(const float4*)(Wp + (kbase + k) * H + jq * 4);
        }
        __syncthreads();
#pragma unroll
        for (int kk = 0; kk < 32; kk++) {
            float4 va = *(float4*)&Vs[kk * 128 + tx * 4];
            ulonglong2 p0 = *(ulonglong2*)&Us[kk * 64 + ty * 8];
            ulonglong2 p1 = *(ulonglong2*)&Us[kk * 64 + ty * 8 + 4];
            unsigned long long d0 = dup2(va.x), d1 = dup2(va.y);
            unsigned long long d2 = dup2(va.z), d3 = dup2(va.w);
            fma2(acc[0][0], p0.x, d0); fma2(acc[1][0], p0.y, d0);
            fma2(acc[2][0], p1.x, d0); fma2(acc[3][0], p1.y, d0);
            fma2(acc[0][1], p0.x, d1); fma2(acc[1][1], p0.y, d1);
            fma2(acc[2][1], p1.x, d1); fma2(acc[3][1], p1.y, d1);
            fma2(acc[0][2], p0.x, d2); fma2(acc[1][2], p0.y, d2);
            fma2(acc[2][2], p1.x, d2); fma2(acc[3][2], p1.y, d2);
            fma2(acc[0][3], p0.x, d3); fma2(acc[1][3], p0.y, d3);
            fma2(acc[2][3], p1.x, d3); fma2(acc[3][3], p1.y, d3);
        }
        __syncthreads();
    }
    // epilogue: +bias, LayerNorm (warp reduce over the 32 lanes owning each row),
    // affine, ReLU, store.
    float4 bb = *(const float4*)(bl + tx * 4);
    float4 gg = *(const float4*)(lg + tx * 4);
    float4 gbv = *(const float4*)(lb + tx * 4);
#pragma unroll
    for (int rp = 0; rp < 4; rp++) {
        float2 f0 = upk2(acc[rp][0]);
        float2 f1 = upk2(acc[rp][1]);
        float2 f2 = upk2(acc[rp][2]);
        float2 f3 = upk2(acc[rp][3]);
        float r0[4] = {f0.x + bb.x, f1.x + bb.y, f2.x + bb.z, f3.x + bb.w};
        float r1[4] = {f0.y + bb.x, f1.y + bb.y, f2.y + bb.z, f3.y + bb.w};
        float s0 = r0[0] + r0[1] + r0[2] + r0[3];
        float s1 = r1[0] + r1[1] + r1[2] + r1[3];
#pragma unroll
        for (int o = 16; o; o >>= 1) {
            s0 += __shfl_xor_sync(0xffffffffu, s0, o);
            s1 += __shfl_xor_sync(0xffffffffu, s1, o);
        }
        float mu0 = s0 * (1.f / 128.f), mu1 = s1 * (1.f / 128.f);
        float q0 = 0.f, q1 = 0.f;
#pragma unroll
        for (int m = 0; m < 4; m++) {
            r0[m] -= mu0; r1[m] -= mu1;
            q0 = fmaf(r0[m], r0[m], q0);
            q1 = fmaf(r1[m], r1[m], q1);
        }
#pragma unroll
        for (int o = 16; o; o >>= 1) {
            q0 += __shfl_xor_sync(0xffffffffu, q0, o);
            q1 += __shfl_xor_sync(0xffffffffu, q1, o);
        }
        float rs0 = rsqrtf(q0 * (1.f / 128.f) + 1e-5f);
        float rs1 = rsqrtf(q1 * (1.f / 128.f) + 1e-5f);
        int rowa = row0 + ty * 8 + 2 * rp;
        int rowb = rowa + 1;
        if (rowa < N_NODES) {
            float4 o;
            o.x = fmaxf(fmaf(r0[0] * rs0, gg.x, gbv.x), 0.f);
            o.y = fmaxf(fmaf(r0[1] * rs0, gg.y, gbv.y), 0.f);
            o.z = fmaxf(fmaf(r0[2] * rs0, gg.z, gbv.z), 0.f);
            o.w = fmaxf(fmaf(r0[3] * rs0, gg.w, gbv.w), 0.f);
            *(float4*)(aggY + (size_t)rowa * H + tx * 4) = o;
        }
        if (rowb < N_NODES) {
            float4 o;
            o.x = fmaxf(fmaf(r1[0] * rs1, gg.x, gbv.x), 0.f);
            o.y = fmaxf(fmaf(r1[1] * rs1, gg.y, gbv.y), 0.f);
            o.z = fmaxf(fmaf(r1[2] * rs1, gg.z, gbv.z), 0.f);
            o.w = fmaxf(fmaf(r1[3] * rs1, gg.w, gbv.w), 0.f);
            *(float4*)(aggY + (size_t)rowb * H + tx * 4) = o;
        }
    }
}

// ---------------- Pl = h@W1[0:128]+b1 ; Pr = h@W1[128:256]  (dual GEMM, f32x2) ----------
// Outputs stored in bf16 so the edge-gather working set (51 MB) stays L2-resident.
__global__ void __launch_bounds__(256) k_plpr(
    const float* __restrict__ h, const float* __restrict__ W1, const float* __restrict__ b1,
    __nv_bfloat16* __restrict__ Pl, __nv_bfloat16* __restrict__ Pr)
{
    __shared__ float Us[32 * 64];
    __shared__ float Vl[32 * 128];
    __shared__ float Vr[32 * 128];
    int t = threadIdx.x;
    int tx = t & 31, ty = t >> 5;
    int row0 = blockIdx.x * 64;
    unsigned long long accl[4][4], accr[4][4];
#pragma unroll
    for (int i = 0; i < 4; i++)
#pragma unroll
        for (int m = 0; m < 4; m++) { accl[i][m] = 0ull; accr[i][m] = 0ull; }

    for (int c = 0; c < 4; c++) {
        int kbase = c * 32;
#pragma unroll
        for (int p0 = 0; p0 < 2; p0++) {
            int p = t + p0 * 256;
            int r = p >> 3, kq = p & 7;
            int row = row0 + r;
            float4 u = make_float4(0.f, 0.f, 0.f, 0.f);
            if (row < N_NODES)
                u = *(const float4*)(h + (size_t)row * H + kbase + kq * 4);
            Us[(kq * 4 + 0) * 64 + r] = u.x;
            Us[(kq * 4 + 1) * 64 + r] = u.y;
            Us[(kq * 4 + 2) * 64 + r] = u.z;
            Us[(kq * 4 + 3) * 64 + r] = u.w;
        }
#pragma unroll
        for (int p0 = 0; p0 < 4; p0++) {
            int p = t + p0 * 256;
            int k = p >> 5, jq = p & 31;
            *(float4*)&Vl[k * 128 + jq * 4] = *(const float4*)(W1 + (kbase + k) * H + jq * 4);
            *(float4*)&Vr[k * 128 + jq * 4] = *(const float4*)(W1 + (128 + kbase + k) * H + jq * 4);
        }
        __syncthreads();
#pragma unroll
        for (int kk = 0; kk < 32; kk++) {
            ulonglong2 p0 = *(ulonglong2*)&Us[kk * 64 + ty * 8];
            ulonglong2 p1 = *(ulonglong2*)&Us[kk * 64 + ty * 8 + 4];
            float4 va = *(float4*)&Vl[kk * 128 + tx * 4];
            float4 vb = *(float4*)&Vr[kk * 128 + tx * 4];
            unsigned long long a0 = dup2(va.x), a1 = dup2(va.y);
            unsigned long long a2 = dup2(va.z), a3 = dup2(va.w);
            fma2(accl[0][0], p0.x, a0); fma2(accl[1][0], p0.y, a0);
            fma2(accl[2][0], p1.x, a0); fma2(accl[3][0], p1.y, a0);
            fma2(accl[0][1], p0.x, a1); fma2(accl[1][1], p0.y, a1);
            fma2(accl[2][1], p1.x, a1); fma2(accl[3][1], p1.y, a1);
            fma2(accl[0][2], p0.x, a2); fma2(accl[1][2], p0.y, a2);
            fma2(accl[2][2], p1.x, a2); fma2(accl[3][2], p1.y, a2);
            fma2(accl[0][3], p0.x, a3); fma2(accl[1][3], p0.y, a3);
            fma2(accl[2][3], p1.x, a3); fma2(accl[3][3], p1.y, a3);
            unsigned long long c0 = dup2(vb.x), c1 = dup2(vb.y);
            unsigned long long c2 = dup2(vb.z), c3 = dup2(vb.w);
            fma2(accr[0][0], p0.x, c0); fma2(accr[1][0], p0.y, c0);
            fma2(accr[2][0], p1.x, c0); fma2(accr[3][0], p1.y, c0);
            fma2(accr[0][1], p0.x, c1); fma2(accr[1][1], p0.y, c1);
            fma2(accr[2][1], p1.x, c1); fma2(accr[3][1], p1.y, c1);
            fma2(accr[0][2], p0.x, c2); fma2(accr[1][2], p0.y, c2);
            fma2(accr[2][2], p1.x, c2); fma2(accr[3][2], p1.y, c2);
            fma2(accr[0][3], p0.x, c3); fma2(accr[1][3], p0.y, c3);
            fma2(accr[2][3], p1.x, c3); fma2(accr[3][3], p1.y, c3);
        }
        __syncthreads();
    }
    float4 bb = *(const float4*)(b1 + tx * 4);
#pragma unroll
    for (int rp = 0; rp < 4; rp++) {
        float2 f0 = upk2(accl[rp][0]);
        float2 f1 = upk2(accl[rp][1]);
        float2 f2 = upk2(accl[rp][2]);
        float2 f3 = upk2(accl[rp][3]);
        float2 g0 = upk2(accr[rp][0]);
        float2 g1 = upk2(accr[rp][1]);
        float2 g2 = upk2(accr[rp][2]);
        float2 g3 = upk2(accr[rp][3]);
        int rowa = row0 + ty * 8 + 2 * rp;
        int rowb = rowa + 1;
        if (rowa < N_NODES) {
            __nv_bfloat162 l01 = __float22bfloat162_rn(make_float2(f0.x + bb.x, f1.x + bb.y));
            __nv_bfloat162 l23 = __float22bfloat162_rn(make_float2(f2.x + bb.z, f3.x + bb.w));
            __nv_bfloat162 r01 = __float22bfloat162_rn(make_float2(g0.x, g1.x));
            __nv_bfloat162 r23 = __float22bfloat162_rn(make_float2(g2.x, g3.x));
            *(__nv_bfloat162*)(Pl + (size_t)rowa * H + tx * 4) = l01;
            *(__nv_bfloat162*)(Pl + (size_t)rowa * H + tx * 4 + 2) = l23;
            *(__nv_bfloat162*)(Pr + (size_t)rowa * H + tx * 4) = r01;
            *(__nv_bfloat162*)(Pr + (size_t)rowa * H + tx * 4 + 2) = r23;
        }
        if (rowb < N_NODES) {
            __nv_bfloat162 l01 = __float22bfloat162_rn(make_float2(f0.y + bb.x, f1.y + bb.y));
            __nv_bfloat162 l23 = __float22bfloat162_rn(make_float2(f2.y + bb.z, f3.y + bb.w));
            __nv_bfloat162 r01 = __float22bfloat162_rn(make_float2(g0.y, g1.y));
            __nv_bfloat162 r23 = __float22bfloat162_rn(make_float2(g2.y, g3.y));
            *(__nv_bfloat162*)(Pl + (size_t)rowb * H + tx * 4) = l01;
            *(__nv_bfloat162*)(Pl + (size_t)rowb * H + tx * 4 + 2) = l23;
            *(__nv_bfloat162*)(Pr + (size_t)rowb * H + tx * 4) = r01;
            *(__nv_bfloat162*)(Pr + (size_t)rowb * H + tx * 4 + 2) = r23;
        }
    }
}

// ---------------- fused edge MLP ----------------
// TE=128 edges/block, 256 threads.
// Phase1: 2 threads/edge; gather bf16 Pl[src], Pr[dst] (128B/edge total each),
//         z1 = relu(Pl+Pr+ea@W1e) stored TRANSPOSED z1T[k][e] (stride 136).
// Phase2: register-tiled GEMM M=128(edges) x N=64 x K=128 in packed f32x2,
//         then fused relu/W3 dot/softplus with 16-lane butterfly reduce.
#define TE 128
#define ST 136
__global__ void __launch_bounds__(256) k_edge(
    const int* __restrict__ src, const int* __restrict__ dst,
    const float* __restrict__ ea, const __nv_bfloat16* __restrict__ Pl,
    const __nv_bfloat16* __restrict__ Pr, const float* __restrict__ W1,
    const float* __restrict__ W2, const float* __restrict__ b2,
    const float* __restrict__ W3, const float* __restrict__ b3,
    float* __restrict__ out)
{
    extern __shared__ float sm[];
    float* z1T = sm;                       // 128 * 136
    float* W2s = z1T + 128 * ST;           // 128*64
    float* W1es = W2s + 128 * 64;          // 12*128
    float* W3s = W1es + 12 * 128;          // 64
    float* b2s = W3s + 64;                 // 64

    int t = threadIdx.x;
    for (int i = t; i < 128 * 64 / 4; i += 256)
        ((float4*)W2s)[i] = ((const float4*)W2)[i];
    for (int i = t; i < 12 * 128 / 4; i += 256)
        ((float4*)W1es)[i] = ((const float4*)(W1 + 256 * H))[i];
    if (t < 64) { W3s[t] = W3[t]; b2s[t] = b2[t]; }

    int e0 = blockIdx.x * TE;
    // ---- phase 1: two threads per edge, each 64 features (8 uint4 bf16 groups)
    {
        int el = t >> 1;               // 0..127
        int jh = t & 1;                // feature half
        int eg = e0 + el;
        int s = src[eg], d = dst[eg];
        unsigned long long eadup[12];
#pragma unroll
        for (int k = 0; k < 12; k++) eadup[k] = dup2(ea[(size_t)eg * 12 + k]);
        __syncthreads();   // weights ready

        const uint4* pl4 = (const uint4*)(Pl + (size_t)s * H);
        const uint4* pr4 = (const uint4*)(Pr + (size_t)d * H);
#pragma unroll
        for (int g = 0; g < 8; g++) {
            int grp = jh * 8 + g;      // uint4 index: cols grp*8 .. grp*8+7
            int jb = grp * 8;
            uint4 a = pl4[grp];
            uint4 b = pr4[grp];
            float2 pa, pb;
            unsigned long long s01, s23, s45, s67;
            pa = bf2f(a.x); pb = bf2f(b.x); s01 = pk2(pa.x + pb.x, pa.y + pb.y);
            pa = bf2f(a.y); pb = bf2f(b.y); s23 = pk2(pa.x + pb.x, pa.y + pb.y);
            pa = bf2f(a.z); pb = bf2f(b.z); s45 = pk2(pa.x + pb.x, pa.y + pb.y);
            pa = bf2f(a.w); pb = bf2f(b.w); s67 = pk2(pa.x + pb.x, pa.y + pb.y);
#pragma unroll
            for (int k = 0; k < 12; k++) {
                ulonglong2 w0 = *(const ulonglong2*)&W1es[k * 128 + jb];
                ulonglong2 w1 = *(const ulonglong2*)&W1es[k * 128 + jb + 4];
                fma2(s01, w0.x, eadup[k]);
                fma2(s23, w0.y, eadup[k]);
                fma2(s45, w1.x, eadup[k]);
                fma2(s67, w1.y, eadup[k]);
            }
            float2 f01 = upk2(s01), f23 = upk2(s23), f45 = upk2(s45), f67 = upk2(s67);
            z1T[(jb + 0) * ST + el] = fmaxf(f01.x, 0.f);
            z1T[(jb + 1) * ST + el] = fmaxf(f01.y, 0.f);
            z1T[(jb + 2) * ST + el] = fmaxf(f23.x, 0.f);
            z1T[(jb + 3) * ST + el] = fmaxf(f23.y, 0.f);
            z1T[(jb + 4) * ST + el] = fmaxf(f45.x, 0.f);
            z1T[(jb + 5) * ST + el] = fmaxf(f45.y, 0.f);
            z1T[(jb + 6) * ST + el] = fmaxf(f67.x, 0.f);
            z1T[(jb + 7) * ST + el] = fmaxf(f67.y, 0.f);
        }
    }
    __syncthreads();

    // ---- phase 2: GEMM 128x64x128, thread tile 8 rows x 4 cols
    int tx = t & 15;       // col group (cols tx*4..+3)
    int ty = t >> 4;       // row group (edges ty*8..+7)
    unsigned long long acc[4][4];
#pragma unroll
    for (int i = 0; i < 4; i++)
#pragma unroll
        for (int m = 0; m < 4; m++) acc[i][m] = 0ull;

#pragma unroll 4
    for (int kk = 0; kk < 128; kk++) {
        float4 w = *(float4*)&W2s[kk * 64 + tx * 4];
        ulonglong2 p0 = *(ulonglong2*)&z1T[kk * ST + ty * 8];
        ulonglong2 p1 = *(ulonglong2*)&z1T[kk * ST + ty * 8 + 4];
        unsigned long long d0 = dup2(w.x), d1 = dup2(w.y);
        unsigned long long d2 = dup2(w.z), d3 = dup2(w.w);
        fma2(acc[0][0], p0.x, d0); fma2(acc[1][0], p0.y, d0);
        fma2(acc[2][0], p1.x, d0); fma2(acc[3][0], p1.y, d0);
        fma2(acc[0][1], p0.x, d1); fma2(acc[1][1], p0.y, d1);
        fma2(acc[2][1], p1.x, d1); fma2(acc[3][1], p1.y, d1);
        fma2(acc[0][2], p0.x, d2); fma2(acc[1][2], p0.y, d2);
        fma2(acc[2][2], p1.x, d2); fma2(acc[3][2], p1.y, d2);
        fma2(acc[0][3], p0.x, d3); fma2(acc[1][3], p0.y, d3);
        fma2(acc[2][3], p1.x, d3); fma2(acc[3][3], p1.y, d3);
    }

    // epilogue: z2 = relu(acc + b2), partial = z2 . W3 over this thread's 4 cols
    float4 b2v = *(float4*)&b2s[tx * 4];
    float4 w3v = *(float4*)&W3s[tx * 4];
    float part[8];
#pragma unroll
    for (int rp = 0; rp < 4; rp++) {
        float2 f0 = upk2(acc[rp][0]);
        float2 f1 = upk2(acc[rp][1]);
        float2 f2 = upk2(acc[rp][2]);
        float2 f3 = upk2(acc[rp][3]);
        part[2 * rp] =
            fmaxf(f0.x + b2v.x, 0.f) * w3v.x + fmaxf(f1.x + b2v.y, 0.f) * w3v.y +
            fmaxf(f2.x + b2v.z, 0.f) * w3v.z + fmaxf(f3.x + b2v.w, 0.f) * w3v.w;
        part[2 * rp + 1] =
            fmaxf(f0.y + b2v.x, 0.f) * w3v.x + fmaxf(f1.y + b2v.y, 0.f) * w3v.y +
            fmaxf(f2.y + b2v.z, 0.f) * w3v.z + fmaxf(f3.y + b2v.w, 0.f) * w3v.w;
    }
#pragma unroll
    for (int i = 0; i < 8; i++) {
#pragma unroll
        for (int o = 8; o; o >>= 1)
            part[i] += __shfl_xor_sync(0xffffffffu, part[i], o);
    }
    if (tx == 0) {
        float b3v = b3[0];
#pragma unroll
        for (int i = 0; i < 8; i++) {
            float x = part[i] + b3v;
            out[e0 + ty * 8 + i] = fmaxf(x, 0.f) + log1pf(expf(-fabsf(x)));
        }
    }
}

// ---------------- launch ----------------
extern "C" void kernel_launch(void* const* d_in, const int* in_sizes, int n_in,
                              void* d_out, int out_size) {
    const float* x      = (const float*)d_in[0];
    const int*   ei     = (const int*)d_in[1];
    const float* ea     = (const float*)d_in[2];
    const float* node_W = (const float*)d_in[3];
    const float* node_b = (const float*)d_in[4];
    const float* sWl    = (const float*)d_in[5];
    const float* sbl    = (const float*)d_in[6];
    const float* sWr    = (const float*)d_in[7];
    const float* ln_g   = (const float*)d_in[8];
    const float* ln_b   = (const float*)d_in[9];
    const float* W1     = (const float*)d_in[10];
    const float* b1     = (const float*)d_in[11];
    const float* W2     = (const float*)d_in[12];
    const float* b2     = (const float*)d_in[13];
    const float* W3     = (const float*)d_in[14];
    const float* b3     = (const float*)d_in[15];
    float* out = (float*)d_out;
    const int* src = ei;
    const int* dstp = ei + N_EDGES;

    float *pA, *pB, *pInv;
    __nv_bfloat16 *pPl, *pPr;
    cudaGetSymbolAddress((void**)&pA, g_bufA);
    cudaGetSymbolAddress((void**)&pB, g_bufB);
    cudaGetSymbolAddress((void**)&pPl, g_Plh);
    cudaGetSymbolAddress((void**)&pPr, g_Prh);
    cudaGetSymbolAddress((void**)&pInv, g_inv);

    cudaMemsetAsync(pInv, 0, N_NODES * sizeof(float));
    k_deg<<<(N_EDGES + 255) / 256, 256>>>(dstp, pInv);
    k_inv<<<(N_NODES + 255) / 256, 256>>>(pInv);

    k_nodeproj<<<(N_NODES * H + 255) / 256, 256>>>(x, node_W, node_b, pA);

    float* hcur = pA;
    float* other = pB;
    for (int l = 0; l < 3; l++) {
        cudaMemsetAsync(other, 0, (size_t)N_NODES * H * sizeof(float));
        k_scatter<<<N_EDGES / 8, 256>>>(src, dstp, hcur, other);
        k_sage<<<(N_NODES + 63) / 64, 256>>>(hcur, other, sWl + l * HH, sbl + l * H,
                                             sWr + l * HH, pInv,
                                             ln_g + l * H, ln_b + l * H);
        float* tmp = hcur; hcur = other; other = tmp;
    }

    k_plpr<<<(N_NODES + 63) / 64, 256>>>(hcur, W1, b1, pPl, pPr);

    int smem_edge = (128 * ST + 128 * 64 + 12 * 128 + 128) * sizeof(float);
    cudaFuncSetAttribute(k_edge, cudaFuncAttributeMaxDynamicSharedMemorySize, smem_edge);
    k_edge<<<N_EDGES / TE, 256, smem_edge>>>(src, dstp, ea, pPl, pPr, W1, W2, b2, W3, b3, out);
}

// round 7
// speedup vs baseline: 1.7316x; 1.1663x over previous
#include <cuda_runtime.h>
#include <cuda_bf16.h>
#include <cstdint>

#define N_NODES 100000
#define N_EDGES 800000
#define H 128
#define HH (H*H)

// ---- scratch (no cudaMalloc allowed) ----
__device__ float g_bufA[N_NODES * H];
__device__ float g_bufB[N_NODES * H];
__device__ __nv_bfloat16 g_Plh[N_NODES * H];
__device__ __nv_bfloat16 g_Prh[N_NODES * H];
__device__ float g_inv[N_NODES];

// ---- packed fp32x2 helpers ----
__device__ __forceinline__ unsigned long long pk2(float x, float y) {
    unsigned long long r;
    asm("mov.b64 %0, {%1, %2};" : "=l"(r) : "f"(x), "f"(y));
    return r;
}
__device__ __forceinline__ unsigned long long dup2(float x) { return pk2(x, x); }
__device__ __forceinline__ void fma2(unsigned long long& d, unsigned long long a,
                                     unsigned long long b) {
    asm("fma.rn.f32x2 %0, %1, %2, %0;" : "+l"(d) : "l"(a), "l"(b));
}
__device__ __forceinline__ float2 upk2(unsigned long long v) {
    float2 f;
    asm("mov.b64 {%0, %1}, %2;" : "=f"(f.x), "=f"(f.y) : "l"(v));
    return f;
}
__device__ __forceinline__ float2 bf2f(unsigned int u) {
    __nv_bfloat162 b = *reinterpret_cast<__nv_bfloat162*>(&u);
    return __bfloat1622float2(b);
}
__device__ __forceinline__ unsigned int f2bf2(float lo, float hi) {
    __nv_bfloat162 b = __float22bfloat162_rn(make_float2(lo, hi));
    return *reinterpret_cast<unsigned int*>(&b);
}
__device__ __forceinline__ uint32_t smem_u32(const void* p) {
    uint32_t a;
    asm("{ .reg .u64 t; cvta.to.shared.u64 t, %1; cvt.u32.u64 %0, t; }" : "=r"(a) : "l"(p));
    return a;
}

// ---------------- degree ----------------
__global__ void k_deg(const int* __restrict__ dst, float* __restrict__ deg) {
    int e = blockIdx.x * 256 + threadIdx.x;
    if (e < N_EDGES) atomicAdd(deg + dst[e], 1.0f);
}
__global__ void k_inv(float* __restrict__ d) {
    int i = blockIdx.x * 256 + threadIdx.x;
    if (i < N_NODES) { float v = d[i]; d[i] = v > 0.f ? 1.f / v : 0.f; }
}

// ---------------- node projection ----------------
__global__ void k_nodeproj(const float* __restrict__ x, const float* __restrict__ W,
                           const float* __restrict__ b, float* __restrict__ h) {
    int idx = blockIdx.x * 256 + threadIdx.x;
    if (idx >= N_NODES * H) return;
    int n = idx >> 7, j = idx & 127;
    float acc = b[j];
#pragma unroll
    for (int k = 0; k < 5; k++) acc = fmaf(x[n * 5 + k], W[k * H + j], acc);
    h[idx] = acc;
}

// ---------------- scatter-add ----------------
__global__ void k_scatter(const int* __restrict__ src, const int* __restrict__ dst,
                          const float* __restrict__ h, float* __restrict__ agg) {
    int w = (blockIdx.x * blockDim.x + threadIdx.x) >> 5;
    int lane = threadIdx.x & 31;
    if (w >= N_EDGES) return;
    int s = src[w], d = dst[w];
    float4 v = ((const float4*)(h + (size_t)s * H))[lane];
    float* p = agg + (size_t)d * H + lane * 4;
    asm volatile("red.global.add.v4.f32 [%0], {%1,%2,%3,%4};"
                 :: "l"(p), "f"(v.x), "f"(v.y), "f"(v.z), "f"(v.w) : "memory");
}

// ---------------- fused SAGE GEMM + LayerNorm + ReLU (f32x2) ----------------
__global__ void __launch_bounds__(256) k_sage(
    const float* __restrict__ hX, float* __restrict__ aggY,
    const float* __restrict__ Wl, const float* __restrict__ bl,
    const float* __restrict__ Wr, const float* __restrict__ inv,
    const float* __restrict__ lg, const float* __restrict__ lb)
{
    __shared__ float Us[32 * 64];
    __shared__ float Vs[32 * 128];
    int t = threadIdx.x;
    int tx = t & 31, ty = t >> 5;
    int row0 = blockIdx.x * 64;
    unsigned long long acc[4][4];
#pragma unroll
    for (int i = 0; i < 4; i++)
#pragma unroll
        for (int m = 0; m < 4; m++) acc[i][m] = 0ull;

    for (int c = 0; c < 8; c++) {
        const float* Usrc = (c < 4) ? aggY : hX;
        const float* Wp = (c < 4) ? Wl : Wr;
        int kbase = (c & 3) * 32;
#pragma unroll
        for (int p0 = 0; p0 < 2; p0++) {
            int p = t + p0 * 256;
            int r = p >> 3, kq = p & 7;
            int row = row0 + r;
            float4 u = make_float4(0.f, 0.f, 0.f, 0.f);
            if (row < N_NODES) {
                u = *(const float4*)(Usrc + (size_t)row * H + kbase + kq * 4);
                if (c < 4) { float iv = inv[row]; u.x *= iv; u.y *= iv; u.z *= iv; u.w *= iv; }
            }
            Us[(kq * 4 + 0) * 64 + r] = u.x;
            Us[(kq * 4 + 1) * 64 + r] = u.y;
            Us[(kq * 4 + 2) * 64 + r] = u.z;
            Us[(kq * 4 + 3) * 64 + r] = u.w;
        }
#pragma unroll
        for (int p0 = 0; p0 < 4; p0++) {
            int p = t + p0 * 256;
            int k = p >> 5, jq = p & 31;
            *(float4*)&Vs[k * 128 + jq * 4] = *(const float4*)(Wp + (kbase + k) * H + jq * 4);
        }
        __syncthreads();
#pragma unroll
        for (int kk = 0; kk < 32; kk++) {
            float4 va = *(float4*)&Vs[kk * 128 + tx * 4];
            ulonglong2 p0 = *(ulonglong2*)&Us[kk * 64 + ty * 8];
            ulonglong2 p1 = *(ulonglong2*)&Us[kk * 64 + ty * 8 + 4];
            unsigned long long d0 = dup2(va.x), d1 = dup2(va.y);
            unsigned long long d2 = dup2(va.z), d3 = dup2(va.w);
            fma2(acc[0][0], p0.x, d0); fma2(acc[1][0], p0.y, d0);
            fma2(acc[2][0], p1.x, d0); fma2(acc[3][0], p1.y, d0);
            fma2(acc[0][1], p0.x, d1); fma2(acc[1][1], p0.y, d1);
            fma2(acc[2][1], p1.x, d1); fma2(acc[3][1], p1.y, d1);
            fma2(acc[0][2], p0.x, d2); fma2(acc[1][2], p0.y, d2);
            fma2(acc[2][2], p1.x, d2); fma2(acc[3][2], p1.y, d2);
            fma2(acc[0][3], p0.x, d3); fma2(acc[1][3], p0.y, d3);
            fma2(acc[2][3], p1.x, d3); fma2(acc[3][3], p1.y, d3);
        }
        __syncthreads();
    }
    float4 bb = *(const float4*)(bl + tx * 4);
    float4 gg = *(const float4*)(lg + tx * 4);
    float4 gbv = *(const float4*)(lb + tx * 4);
#pragma unroll
    for (int rp = 0; rp < 4; rp++) {
        float2 f0 = upk2(acc[rp][0]);
        float2 f1 = upk2(acc[rp][1]);
        float2 f2 = upk2(acc[rp][2]);
        float2 f3 = upk2(acc[rp][3]);
        float r0[4] = {f0.x + bb.x, f1.x + bb.y, f2.x + bb.z, f3.x + bb.w};
        float r1[4] = {f0.y + bb.x, f1.y + bb.y, f2.y + bb.z, f3.y + bb.w};
        float s0 = r0[0] + r0[1] + r0[2] + r0[3];
        float s1 = r1[0] + r1[1] + r1[2] + r1[3];
#pragma unroll
        for (int o = 16; o; o >>= 1) {
            s0 += __shfl_xor_sync(0xffffffffu, s0, o);
            s1 += __shfl_xor_sync(0xffffffffu, s1, o);
        }
        float mu0 = s0 * (1.f / 128.f), mu1 = s1 * (1.f / 128.f);
        float q0 = 0.f, q1 = 0.f;
#pragma unroll
        for (int m = 0; m < 4; m++) {
            r0[m] -= mu0; r1[m] -= mu1;
            q0 = fmaf(r0[m], r0[m], q0);
            q1 = fmaf(r1[m], r1[m], q1);
        }
#pragma unroll
        for (int o = 16; o; o >>= 1) {
            q0 += __shfl_xor_sync(0xffffffffu, q0, o);
            q1 += __shfl_xor_sync(0xffffffffu, q1, o);
        }
        float rs0 = rsqrtf(q0 * (1.f / 128.f) + 1e-5f);
        float rs1 = rsqrtf(q1 * (1.f / 128.f) + 1e-5f);
        int rowa = row0 + ty * 8 + 2 * rp;
        int rowb = rowa + 1;
        if (rowa < N_NODES) {
            float4 o;
            o.x = fmaxf(fmaf(r0[0] * rs0, gg.x, gbv.x), 0.f);
            o.y = fmaxf(fmaf(r0[1] * rs0, gg.y, gbv.y), 0.f);
            o.z = fmaxf(fmaf(r0[2] * rs0, gg.z, gbv.z), 0.f);
            o.w = fmaxf(fmaf(r0[3] * rs0, gg.w, gbv.w), 0.f);
            *(float4*)(aggY + (size_t)rowa * H + tx * 4) = o;
        }
        if (rowb < N_NODES) {
            float4 o;
            o.x = fmaxf(fmaf(r1[0] * rs1, gg.x, gbv.x), 0.f);
            o.y = fmaxf(fmaf(r1[1] * rs1, gg.y, gbv.y), 0.f);
            o.z = fmaxf(fmaf(r1[2] * rs1, gg.z, gbv.z), 0.f);
            o.w = fmaxf(fmaf(r1[3] * rs1, gg.w, gbv.w), 0.f);
            *(float4*)(aggY + (size_t)rowb * H + tx * 4) = o;
        }
    }
}

// ---------------- Pl/Pr dual GEMM (f32x2), bf16 outputs ----------------
__global__ void __launch_bounds__(256) k_plpr(
    const float* __restrict__ h, const float* __restrict__ W1, const float* __restrict__ b1,
    __nv_bfloat16* __restrict__ Pl, __nv_bfloat16* __restrict__ Pr)
{
    __shared__ float Us[32 * 64];
    __shared__ float Vl[32 * 128];
    __shared__ float Vr[32 * 128];
    int t = threadIdx.x;
    int tx = t & 31, ty = t >> 5;
    int row0 = blockIdx.x * 64;
    unsigned long long accl[4][4], accr[4][4];
#pragma unroll
    for (int i = 0; i < 4; i++)
#pragma unroll
        for (int m = 0; m < 4; m++) { accl[i][m] = 0ull; accr[i][m] = 0ull; }

    for (int c = 0; c < 4; c++) {
        int kbase = c * 32;
#pragma unroll
        for (int p0 = 0; p0 < 2; p0++) {
            int p = t + p0 * 256;
            int r = p >> 3, kq = p & 7;
            int row = row0 + r;
            float4 u = make_float4(0.f, 0.f, 0.f, 0.f);
            if (row < N_NODES)
                u = *(const float4*)(h + (size_t)row * H + kbase + kq * 4);
            Us[(kq * 4 + 0) * 64 + r] = u.x;
            Us[(kq * 4 + 1) * 64 + r] = u.y;
            Us[(kq * 4 + 2) * 64 + r] = u.z;
            Us[(kq * 4 + 3) * 64 + r] = u.w;
        }
#pragma unroll
        for (int p0 = 0; p0 < 4; p0++) {
            int p = t + p0 * 256;
            int k = p >> 5, jq = p & 31;
            *(float4*)&Vl[k * 128 + jq * 4] = *(const float4*)(W1 + (kbase + k) * H + jq * 4);
            *(float4*)&Vr[k * 128 + jq * 4] = *(const float4*)(W1 + (128 + kbase + k) * H + jq * 4);
        }
        __syncthreads();
#pragma unroll
        for (int kk = 0; kk < 32; kk++) {
            ulonglong2 p0 = *(ulonglong2*)&Us[kk * 64 + ty * 8];
            ulonglong2 p1 = *(ulonglong2*)&Us[kk * 64 + ty * 8 + 4];
            float4 va = *(float4*)&Vl[kk * 128 + tx * 4];
            float4 vb = *(float4*)&Vr[kk * 128 + tx * 4];
            unsigned long long a0 = dup2(va.x), a1 = dup2(va.y);
            unsigned long long a2 = dup2(va.z), a3 = dup2(va.w);
            fma2(accl[0][0], p0.x, a0); fma2(accl[1][0], p0.y, a0);
            fma2(accl[2][0], p1.x, a0); fma2(accl[3][0], p1.y, a0);
            fma2(accl[0][1], p0.x, a1); fma2(accl[1][1], p0.y, a1);
            fma2(accl[2][1], p1.x, a1); fma2(accl[3][1], p1.y, a1);
            fma2(accl[0][2], p0.x, a2); fma2(accl[1][2], p0.y, a2);
            fma2(accl[2][2], p1.x, a2); fma2(accl[3][2], p1.y, a2);
            fma2(accl[0][3], p0.x, a3); fma2(accl[1][3], p0.y, a3);
            fma2(accl[2][3], p1.x, a3); fma2(accl[3][3], p1.y, a3);
            unsigned long long c0 = dup2(vb.x), c1 = dup2(vb.y);
            unsigned long long c2 = dup2(vb.z), c3 = dup2(vb.w);
            fma2(accr[0][0], p0.x, c0); fma2(accr[1][0], p0.y, c0);
            fma2(accr[2][0], p1.x, c0); fma2(accr[3][0], p1.y, c0);
            fma2(accr[0][1], p0.x, c1); fma2(accr[1][1], p0.y, c1);
            fma2(accr[2][1], p1.x, c1); fma2(accr[3][1], p1.y, c1);
            fma2(accr[0][2], p0.x, c2); fma2(accr[1][2], p0.y, c2);
            fma2(accr[2][2], p1.x, c2); fma2(accr[3][2], p1.y, c2);
            fma2(accr[0][3], p0.x, c3); fma2(accr[1][3], p0.y, c3);
            fma2(accr[2][3], p1.x, c3); fma2(accr[3][3], p1.y, c3);
        }
        __syncthreads();
    }
    float4 bb = *(const float4*)(b1 + tx * 4);
#pragma unroll
    for (int rp = 0; rp < 4; rp++) {
        float2 f0 = upk2(accl[rp][0]);
        float2 f1 = upk2(accl[rp][1]);
        float2 f2 = upk2(accl[rp][2]);
        float2 f3 = upk2(accl[rp][3]);
        float2 g0 = upk2(accr[rp][0]);
        float2 g1 = upk2(accr[rp][1]);
        float2 g2 = upk2(accr[rp][2]);
        float2 g3 = upk2(accr[rp][3]);
        int rowa = row0 + ty * 8 + 2 * rp;
        int rowb = rowa + 1;
        if (rowa < N_NODES) {
            *(unsigned*)(Pl + (size_t)rowa * H + tx * 4)     = f2bf2(f0.x + bb.x, f1.x + bb.y);
            *(unsigned*)(Pl + (size_t)rowa * H + tx * 4 + 2) = f2bf2(f2.x + bb.z, f3.x + bb.w);
            *(unsigned*)(Pr + (size_t)rowa * H + tx * 4)     = f2bf2(g0.x, g1.x);
            *(unsigned*)(Pr + (size_t)rowa * H + tx * 4 + 2) = f2bf2(g2.x, g3.x);
        }
        if (rowb < N_NODES) {
            *(unsigned*)(Pl + (size_t)rowb * H + tx * 4)     = f2bf2(f0.y + bb.x, f1.y + bb.y);
            *(unsigned*)(Pl + (size_t)rowb * H + tx * 4 + 2) = f2bf2(f2.y + bb.z, f3.y + bb.w);
            *(unsigned*)(Pr + (size_t)rowb * H + tx * 4)     = f2bf2(g0.y, g1.y);
            *(unsigned*)(Pr + (size_t)rowb * H + tx * 4 + 2) = f2bf2(g2.y, g3.y);
        }
    }
}

// ---------------- fused edge MLP; phase2 on HMMA (mma.sync bf16) ----------------
// TE=128 edges/block, 256 threads (8 warps).
// Phase1: 2 threads/edge compute z1 = relu(Pl[src]+Pr[dst]+ea@W1e) in fp32 (FFMA2),
//         store bf16 row-major z1[128][K=128] (stride 136 bf16) via uint4.
// Phase2: warp w owns edges w*16..w*16+15. mma.m16n8k16 row.col bf16->f32:
//         per k-step (8): ldmatrix.x4 A; per n-tile (8): ldmatrix.x2 B from W2^T.
// Epilogue: per-thread 2 rows x 16 cols -> relu+b2, dot W3, quad reduce, softplus.
#define TE 128
#define ZST 136            // bf16 elements per z1 row (272 bytes)
// smem byte offsets
#define EZ1_OFF   0                        // 128*272 = 34816
#define EW2T_OFF  34816                    // 64*272  = 17408
#define EW1_OFF   52224                    // 12*128 f32 = 6144
#define EW3_OFF   58368                    // 64 f32
#define EB2_OFF   58624                    // 64 f32
#define ESM_TOTAL 58880

__global__ void __launch_bounds__(256) k_edge(
    const int* __restrict__ src, const int* __restrict__ dst,
    const float* __restrict__ ea, const __nv_bfloat16* __restrict__ Pl,
    const __nv_bfloat16* __restrict__ Pr, const float* __restrict__ W1,
    const float* __restrict__ W2, const float* __restrict__ b2,
    const float* __restrict__ W3, const float* __restrict__ b3,
    float* __restrict__ out)
{
    extern __shared__ char smc[];
    uint32_t sb = smem_u32(smc);

    float* W1es = (float*)(smc + EW1_OFF);
    float* W3s  = (float*)(smc + EW3_OFF);
    float* b2s  = (float*)(smc + EB2_OFF);

    int t = threadIdx.x;

    // weights: W1e slice, W3, b2
    for (int i = t; i < 12 * 128 / 4; i += 256)
        ((float4*)W1es)[i] = ((const float4*)(W1 + 256 * H))[i];
    if (t < 64) { W3s[t] = W3[t]; b2s[t] = b2[t]; }

    // W2^T -> bf16 [n=64][k=128], stride ZST
    for (int i = t; i < 4096; i += 256) {
        int n = i & 63;
        int kp = i >> 6;   // k-pair 0..63
        float f0 = W2[(2 * kp) * 64 + n];
        float f1 = W2[(2 * kp + 1) * 64 + n];
        *(unsigned*)(smc + EW2T_OFF + (n * ZST + 2 * kp) * 2) = f2bf2(f0, f1);
    }

    int e0 = blockIdx.x * TE;
    // ---- phase 1: two threads per edge, each 64 features
    {
        int el = t >> 1;               // local edge 0..127
        int jh = t & 1;                // feature half
        int eg = e0 + el;
        int s = src[eg], d = dst[eg];
        unsigned long long eadup[12];
#pragma unroll
        for (int k = 0; k < 12; k++) eadup[k] = dup2(ea[(size_t)eg * 12 + k]);

        const uint4* pl4 = (const uint4*)(Pl + (size_t)s * H);
        const uint4* pr4 = (const uint4*)(Pr + (size_t)d * H);
#pragma unroll
        for (int g = 0; g < 8; g++) {
            int grp = jh * 8 + g;      // 8 k-values: cols grp*8..grp*8+7
            uint4 a = pl4[grp];
            uint4 b = pr4[grp];
            float2 pa, pb;
            unsigned long long s01, s23, s45, s67;
            pa = bf2f(a.x); pb = bf2f(b.x); s01 = pk2(pa.x + pb.x, pa.y + pb.y);
            pa = bf2f(a.y); pb = bf2f(b.y); s23 = pk2(pa.x + pb.x, pa.y + pb.y);
            pa = bf2f(a.z); pb = bf2f(b.z); s45 = pk2(pa.x + pb.x, pa.y + pb.y);
            pa = bf2f(a.w); pb = bf2f(b.w); s67 = pk2(pa.x + pb.x, pa.y + pb.y);
            int jb = grp * 8;
#pragma unroll
            for (int k = 0; k < 12; k++) {
                ulonglong2 w0 = *(const ulonglong2*)&W1es[k * 128 + jb];
                ulonglong2 w1 = *(const ulonglong2*)&W1es[k * 128 + jb + 4];
                fma2(s01, w0.x, eadup[k]);
                fma2(s23, w0.y, eadup[k]);
                fma2(s45, w1.x, eadup[k]);
                fma2(s67, w1.y, eadup[k]);
            }
            float2 f01 = upk2(s01), f23 = upk2(s23), f45 = upk2(s45), f67 = upk2(s67);
            uint4 pkd;
            pkd.x = f2bf2(fmaxf(f01.x, 0.f), fmaxf(f01.y, 0.f));
            pkd.y = f2bf2(fmaxf(f23.x, 0.f), fmaxf(f23.y, 0.f));
            pkd.z = f2bf2(fmaxf(f45.x, 0.f), fmaxf(f45.y, 0.f));
            pkd.w = f2bf2(fmaxf(f67.x, 0.f), fmaxf(f67.y, 0.f));
            *(uint4*)(smc + EZ1_OFF + el * (ZST * 2) + jb * 2) = pkd;
        }
    }
    __syncthreads();

    // ---- phase 2: HMMA GEMM, warp tile M=16 x N=64, K=128
    int lane = t & 31, warp = t >> 5;
    int m0 = warp * 16;
    float acc[8][4];
#pragma unroll
    for (int nt = 0; nt < 8; nt++)
#pragma unroll
        for (int m = 0; m < 4; m++) acc[nt][m] = 0.f;

    // A lane address: row m0 + (lane&15), k-halfbyte (lane>>4)*16
    uint32_t a_base = sb + EZ1_OFF + (uint32_t)(m0 + (lane & 15)) * (ZST * 2)
                      + (uint32_t)(lane >> 4) * 16;
    // B lane address: row (lane&7), k-half ((lane>>3)&1)*16  (per n-tile add nt*8 rows)
    uint32_t b_base = sb + EW2T_OFF + (uint32_t)(lane & 7) * (ZST * 2)
                      + (uint32_t)((lane >> 3) & 1) * 16;

#pragma unroll
    for (int ks = 0; ks < 8; ks++) {
        uint32_t a0, a1, a2, a3;
        asm volatile("ldmatrix.sync.aligned.m8n8.x4.shared.b16 {%0,%1,%2,%3}, [%4];"
                     : "=r"(a0), "=r"(a1), "=r"(a2), "=r"(a3)
                     : "r"(a_base + ks * 32));
#pragma unroll
        for (int nt = 0; nt < 8; nt++) {
            uint32_t b0, b1;
            asm volatile("ldmatrix.sync.aligned.m8n8.x2.shared.b16 {%0,%1}, [%2];"
                         : "=r"(b0), "=r"(b1)
                         : "r"(b_base + (uint32_t)nt * 8 * (ZST * 2) + ks * 32));
            asm volatile(
                "mma.sync.aligned.m16n8k16.row.col.f32.bf16.bf16.f32 "
                "{%0,%1,%2,%3}, {%4,%5,%6,%7}, {%8,%9}, {%0,%1,%2,%3};"
                : "+f"(acc[nt][0]), "+f"(acc[nt][1]), "+f"(acc[nt][2]), "+f"(acc[nt][3])
                : "r"(a0), "r"(a1), "r"(a2), "r"(a3), "r"(b0), "r"(b1));
        }
    }

    // ---- epilogue: thread holds rows (m0 + lane/4) and (+8); cols 2*(lane%4)+{0,1} per tile
    int qr = lane >> 2;        // 0..7
    int qc = (lane & 3) * 2;
    float p0 = 0.f, p1 = 0.f;
#pragma unroll
    for (int nt = 0; nt < 8; nt++) {
        int c0 = nt * 8 + qc, c1 = c0 + 1;
        float w30 = W3s[c0], w31 = W3s[c1];
        float bb0 = b2s[c0], bb1 = b2s[c1];
        p0 = fmaf(fmaxf(acc[nt][0] + bb0, 0.f), w30, p0);
        p0 = fmaf(fmaxf(acc[nt][1] + bb1, 0.f), w31, p0);
        p1 = fmaf(fmaxf(acc[nt][2] + bb0, 0.f), w30, p1);
        p1 = fmaf(fmaxf(acc[nt][3] + bb1, 0.f), w31, p1);
    }
    // reduce across the 4 lanes sharing a row (lane%4)
    p0 += __shfl_xor_sync(0xffffffffu, p0, 1);
    p0 += __shfl_xor_sync(0xffffffffu, p0, 2);
    p1 += __shfl_xor_sync(0xffffffffu, p1, 1);
    p1 += __shfl_xor_sync(0xffffffffu, p1, 2);
    if ((lane & 3) == 0) {
        float b3v = b3[0];
        float x0 = p0 + b3v;
        float x1 = p1 + b3v;
        out[e0 + m0 + qr]     = fmaxf(x0, 0.f) + log1pf(expf(-fabsf(x0)));
        out[e0 + m0 + qr + 8] = fmaxf(x1, 0.f) + log1pf(expf(-fabsf(x1)));
    }
}

// ---------------- launch ----------------
extern "C" void kernel_launch(void* const* d_in, const int* in_sizes, int n_in,
                              void* d_out, int out_size) {
    const float* x      = (const float*)d_in[0];
    const int*   ei     = (const int*)d_in[1];
    const float* ea     = (const float*)d_in[2];
    const float* node_W = (const float*)d_in[3];
    const float* node_b = (const float*)d_in[4];
    const float* sWl    = (const float*)d_in[5];
    const float* sbl    = (const float*)d_in[6];
    const float* sWr    = (const float*)d_in[7];
    const float* ln_g   = (const float*)d_in[8];
    const float* ln_b   = (const float*)d_in[9];
    const float* W1     = (const float*)d_in[10];
    const float* b1     = (const float*)d_in[11];
    const float* W2     = (const float*)d_in[12];
    const float* b2     = (const float*)d_in[13];
    const float* W3     = (const float*)d_in[14];
    const float* b3     = (const float*)d_in[15];
    float* out = (float*)d_out;
    const int* src = ei;
    const int* dstp = ei + N_EDGES;

    float *pA, *pB, *pInv;
    __nv_bfloat16 *pPl, *pPr;
    cudaGetSymbolAddress((void**)&pA, g_bufA);
    cudaGetSymbolAddress((void**)&pB, g_bufB);
    cudaGetSymbolAddress((void**)&pPl, g_Plh);
    cudaGetSymbolAddress((void**)&pPr, g_Prh);
    cudaGetSymbolAddress((void**)&pInv, g_inv);

    cudaMemsetAsync(pInv, 0, N_NODES * sizeof(float));
    k_deg<<<(N_EDGES + 255) / 256, 256>>>(dstp, pInv);
    k_inv<<<(N_NODES + 255) / 256, 256>>>(pInv);

    k_nodeproj<<<(N_NODES * H + 255) / 256, 256>>>(x, node_W, node_b, pA);

    float* hcur = pA;
    float* other = pB;
    for (int l = 0; l < 3; l++) {
        cudaMemsetAsync(other, 0, (size_t)N_NODES * H * sizeof(float));
        k_scatter<<<N_EDGES / 8, 256>>>(src, dstp, hcur, other);
        k_sage<<<(N_NODES + 63) / 64, 256>>>(hcur, other, sWl + l * HH, sbl + l * H,
                                             sWr + l * HH, pInv,
                                             ln_g + l * H, ln_b + l * H);
        float* tmp = hcur; hcur = other; other = tmp;
    }

    k_plpr<<<(N_NODES + 63) / 64, 256>>>(hcur, W1, b1, pPl, pPr);

    cudaFuncSetAttribute(k_edge, cudaFuncAttributeMaxDynamicSharedMemorySize, ESM_TOTAL);
    k_edge<<<N_EDGES / TE, 256, ESM_TOTAL>>>(src, dstp, ea, pPl, pPr, W1, W2, b2, W3, b3, out);
}

// round 9
// speedup vs baseline: 2.5177x; 1.4539x over previous
#include <cuda_runtime.h>
#include <cuda_bf16.h>
#include <cstdint>

#define N_NODES 100000
#define N_EDGES 800000
#define H 128
#define HH (H*H)

// ---- scratch (no cudaMalloc allowed) ----
__device__ float g_bufA[N_NODES * H];
__device__ float g_bufB[N_NODES * H];
__device__ __nv_bfloat16 g_Plh[N_NODES * H];
__device__ __nv_bfloat16 g_Prh[N_NODES * H];
__device__ float g_inv[N_NODES];
__device__ __nv_bfloat16 g_WsT[3 * H * 256];   // [l][n=128][k=256] : k<128 Wl^T, k>=128 Wr^T
__device__ __nv_bfloat16 g_W1T[256 * H];       // [n'=256][k=128]   : n'<128 Pl cols, else Pr

// ---- packed fp32x2 helpers ----
__device__ __forceinline__ unsigned long long pk2(float x, float y) {
    unsigned long long r;
    asm("mov.b64 %0, {%1, %2};" : "=l"(r) : "f"(x), "f"(y));
    return r;
}
__device__ __forceinline__ unsigned long long dup2(float x) { return pk2(x, x); }
__device__ __forceinline__ void fma2(unsigned long long& d, unsigned long long a,
                                     unsigned long long b) {
    asm("fma.rn.f32x2 %0, %1, %2, %0;" : "+l"(d) : "l"(a), "l"(b));
}
__device__ __forceinline__ float2 upk2(unsigned long long v) {
    float2 f;
    asm("mov.b64 {%0, %1}, %2;" : "=f"(f.x), "=f"(f.y) : "l"(v));
    return f;
}
__device__ __forceinline__ float2 bf2f(unsigned int u) {
    __nv_bfloat162 b = *reinterpret_cast<__nv_bfloat162*>(&u);
    return __bfloat1622float2(b);
}
__device__ __forceinline__ unsigned int f2bf2(float lo, float hi) {
    __nv_bfloat162 b = __float22bfloat162_rn(make_float2(lo, hi));
    return *reinterpret_cast<unsigned int*>(&b);
}
__device__ __forceinline__ uint32_t smem_u32(const void* p) {
    uint32_t a;
    asm("{ .reg .u64 t; cvta.to.shared.u64 t, %1; cvt.u32.u64 %0, t; }" : "=r"(a) : "l"(p));
    return a;
}

// ---- mma helpers (pattern verified in R7 edge kernel) ----
__device__ __forceinline__ void ldmA(uint32_t& a0, uint32_t& a1, uint32_t& a2, uint32_t& a3,
                                     uint32_t addr) {
    asm volatile("ldmatrix.sync.aligned.m8n8.x4.shared.b16 {%0,%1,%2,%3}, [%4];"
                 : "=r"(a0), "=r"(a1), "=r"(a2), "=r"(a3) : "r"(addr));
}
__device__ __forceinline__ void ldmB(uint32_t& b0, uint32_t& b1, uint32_t addr) {
    asm volatile("ldmatrix.sync.aligned.m8n8.x2.shared.b16 {%0,%1}, [%2];"
                 : "=r"(b0), "=r"(b1) : "r"(addr));
}
__device__ __forceinline__ void mma16816(float* c, uint32_t a0, uint32_t a1, uint32_t a2,
                                         uint32_t a3, uint32_t b0, uint32_t b1) {
    asm volatile(
        "mma.sync.aligned.m16n8k16.row.col.f32.bf16.bf16.f32 "
        "{%0,%1,%2,%3}, {%4,%5,%6,%7}, {%8,%9}, {%0,%1,%2,%3};"
        : "+f"(c[0]), "+f"(c[1]), "+f"(c[2]), "+f"(c[3])
        : "r"(a0), "r"(a1), "r"(a2), "r"(a3), "r"(b0), "r"(b1));
}

// ---------------- degree ----------------
__global__ void k_deg(const int* __restrict__ dst, float* __restrict__ deg) {
    int e = blockIdx.x * 256 + threadIdx.x;
    if (e < N_EDGES) atomicAdd(deg + dst[e], 1.0f);
}
__global__ void k_inv(float* __restrict__ d) {
    int i = blockIdx.x * 256 + threadIdx.x;
    if (i < N_NODES) { float v = d[i]; d[i] = v > 0.f ? 1.f / v : 0.f; }
}

// ---------------- weight prep: transposed bf16 copies (runs once per launch) ----------
__global__ void k_wprep(const float* __restrict__ sWl, const float* __restrict__ sWr,
                        const float* __restrict__ W1,
                        __nv_bfloat16* __restrict__ WsT, __nv_bfloat16* __restrict__ W1T) {
    int i = blockIdx.x * 256 + threadIdx.x;
    if (i < 3 * 128 * 256) {
        int l = i / (128 * 256);
        int rem = i - l * (128 * 256);
        int n = rem >> 8;
        int k = rem & 255;
        float v = (k < 128) ? sWl[l * HH + k * H + n] : sWr[l * HH + (k - 128) * H + n];
        WsT[i] = __float2bfloat16(v);
    }
    if (i < 256 * 128) {
        int n = i >> 7, k = i & 127;
        float v = (n < 128) ? W1[k * H + n] : W1[(128 + k) * H + (n - 128)];
        W1T[i] = __float2bfloat16(v);
    }
}

// ---------------- node projection ----------------
__global__ void k_nodeproj(const float* __restrict__ x, const float* __restrict__ W,
                           const float* __restrict__ b, float* __restrict__ h) {
    int idx = blockIdx.x * 256 + threadIdx.x;
    if (idx >= N_NODES * H) return;
    int n = idx >> 7, j = idx & 127;
    float acc = b[j];
#pragma unroll
    for (int k = 0; k < 5; k++) acc = fmaf(x[n * 5 + k], W[k * H + j], acc);
    h[idx] = acc;
}

// ---------------- scatter-add ----------------
__global__ void k_scatter(const int* __restrict__ src, const int* __restrict__ dst,
                          const float* __restrict__ h, float* __restrict__ agg) {
    int w = (blockIdx.x * blockDim.x + threadIdx.x) >> 5;
    int lane = threadIdx.x & 31;
    if (w >= N_EDGES) return;
    int s = src[w], d = dst[w];
    float4 v = ((const float4*)(h + (size_t)s * H))[lane];
    float* p = agg + (size_t)d * H + lane * 4;
    asm volatile("red.global.add.v4.f32 [%0], {%1,%2,%3,%4};"
                 :: "l"(p), "f"(v.x), "f"(v.y), "f"(v.z), "f"(v.w) : "memory");
}

// ---------------- SAGE on HMMA: t = (agg*inv | h) @ [Wl;Wr] + bl, then LN+ReLU ------
// BM=128, N=128, K=256 in 4 chunks of 64. 256 threads, warp w owns rows w*16..+15.
#define SG_AS 0            // 128*144 = 18432 B
#define SG_WS 18432        // 128*144 = 18432 B
#define SG_LN 36864        // 384 f32 = 1536 B
#define SG_SM 38400
__global__ void __launch_bounds__(256) k_sage_mma(
    const float* __restrict__ hX, float* __restrict__ aggY,
    const __nv_bfloat16* __restrict__ WsTl, const float* __restrict__ bl,
    const float* __restrict__ inv,
    const float* __restrict__ lg, const float* __restrict__ lb)
{
    extern __shared__ char smc[];
    uint32_t sb = smem_u32(smc);
    int t = threadIdx.x, lane = t & 31, warp = t >> 5;
    int row0 = blockIdx.x * 128;
    float* lns = (float*)(smc + SG_LN);
    if (t < 128) { lns[t] = bl[t]; lns[128 + t] = lg[t]; lns[256 + t] = lb[t]; }

    float acc[16][4];
#pragma unroll
    for (int nt = 0; nt < 16; nt++)
#pragma unroll
        for (int m = 0; m < 4; m++) acc[nt][m] = 0.f;

    for (int c = 0; c < 4; c++) {
        const float* Usrc = (c < 2) ? aggY : hX;
        int kcol = (c & 1) * 64;
        __syncthreads();
#pragma unroll
        for (int p = 0; p < 8; p++) {
            int id = t + p * 256;          // 0..2047
            int r = id >> 4, fq = id & 15; // 16 float4 per 64-col row
            int row = row0 + r;
            float4 u = make_float4(0.f, 0.f, 0.f, 0.f);
            if (row < N_NODES) {
                u = *(const float4*)(Usrc + (size_t)row * H + kcol + fq * 4);
                if (c < 2) { float iv = inv[row]; u.x *= iv; u.y *= iv; u.z *= iv; u.w *= iv; }
            }
            uint2 pkd;
            pkd.x = f2bf2(u.x, u.y);
            pkd.y = f2bf2(u.z, u.w);
            *(uint2*)(smc + SG_AS + r * 144 + fq * 8) = pkd;
        }
#pragma unroll
        for (int p = 0; p < 4; p++) {
            int id = t + p * 256;          // 0..1023
            int n = id >> 3, q = id & 7;   // 8 uint4 per 64-col (128 B) row
            uint4 w = *(const uint4*)(WsTl + n * 256 + c * 64 + q * 8);
            *(uint4*)(smc + SG_WS + n * 144 + q * 16) = w;
        }
        __syncthreads();
        uint32_t a_base = sb + SG_AS + (uint32_t)(warp * 16 + (lane & 15)) * 144
                          + (uint32_t)(lane >> 4) * 16;
        uint32_t b_base = sb + SG_WS + (uint32_t)(lane & 7) * 144
                          + (uint32_t)((lane >> 3) & 1) * 16;
#pragma unroll
        for (int ks = 0; ks < 4; ks++) {
            uint32_t a0, a1, a2, a3;
            ldmA(a0, a1, a2, a3, a_base + ks * 32);
#pragma unroll
            for (int nt = 0; nt < 16; nt++) {
                uint32_t b0, b1;
                ldmB(b0, b1, b_base + (uint32_t)nt * 8 * 144 + ks * 32);
                mma16816(acc[nt], a0, a1, a2, a3, b0, b1);
            }
        }
    }

    // epilogue: +bl, LayerNorm over quad lanes, affine+ReLU, store
    int qr = lane >> 2, qc = (lane & 3) * 2;
    int r0 = row0 + warp * 16 + qr;
    int r1 = r0 + 8;
    float s0 = 0.f, s1 = 0.f;
#pragma unroll
    for (int nt = 0; nt < 16; nt++) {
        int c0 = nt * 8 + qc;
        float bb0 = lns[c0], bb1 = lns[c0 + 1];
        acc[nt][0] += bb0; acc[nt][1] += bb1;
        acc[nt][2] += bb0; acc[nt][3] += bb1;
        s0 += acc[nt][0] + acc[nt][1];
        s1 += acc[nt][2] + acc[nt][3];
    }
    s0 += __shfl_xor_sync(0xffffffffu, s0, 1);
    s0 += __shfl_xor_sync(0xffffffffu, s0, 2);
    s1 += __shfl_xor_sync(0xffffffffu, s1, 1);
    s1 += __shfl_xor_sync(0xffffffffu, s1, 2);
    float mu0 = s0 * (1.f / 128.f), mu1 = s1 * (1.f / 128.f);
    float q0 = 0.f, q1 = 0.f;
#pragma unroll
    for (int nt = 0; nt < 16; nt++) {
        float d0 = acc[nt][0] - mu0, d1 = acc[nt][1] - mu0;
        float d2 = acc[nt][2] - mu1, d3 = acc[nt][3] - mu1;
        q0 = fmaf(d0, d0, q0); q0 = fmaf(d1, d1, q0);
        q1 = fmaf(d2, d2, q1); q1 = fmaf(d3, d3, q1);
    }
    q0 += __shfl_xor_sync(0xffffffffu, q0, 1);
    q0 += __shfl_xor_sync(0xffffffffu, q0, 2);
    q1 += __shfl_xor_sync(0xffffffffu, q1, 1);
    q1 += __shfl_xor_sync(0xffffffffu, q1, 2);
    float rs0 = rsqrtf(q0 * (1.f / 128.f) + 1e-5f);
    float rs1 = rsqrtf(q1 * (1.f / 128.f) + 1e-5f);
#pragma unroll
    for (int nt = 0; nt < 16; nt++) {
        int c0 = nt * 8 + qc;
        float g0 = lns[128 + c0], g1 = lns[128 + c0 + 1];
        float o0 = lns[256 + c0], o1 = lns[256 + c0 + 1];
        if (r0 < N_NODES) {
            float2 v;
            v.x = fmaxf(fmaf((acc[nt][0] - mu0) * rs0, g0, o0), 0.f);
            v.y = fmaxf(fmaf((acc[nt][1] - mu0) * rs0, g1, o1), 0.f);
            *(float2*)(aggY + (size_t)r0 * H + c0) = v;
        }
        if (r1 < N_NODES) {
            float2 v;
            v.x = fmaxf(fmaf((acc[nt][2] - mu1) * rs1, g0, o0), 0.f);
            v.y = fmaxf(fmaf((acc[nt][3] - mu1) * rs1, g1, o1), 0.f);
            *(float2*)(aggY + (size_t)r1 * H + c0) = v;
        }
    }
}

// ---------------- Pl/Pr on HMMA: [Pl|Pr] = h @ W1T', bf16 outputs ----------------
// BM=64; warps 0-3 -> Pl rows (wm*16), warps 4-7 -> Pr same rows. K=128 whole.
#define PP_AS 0            // 64*272 = 17408 B
#define PP_WS 17408        // 256*272 = 69632 B
#define PP_B1 87040        // 128 f32
#define PP_SM 87552
__global__ void __launch_bounds__(256) k_plpr_mma(
    const float* __restrict__ h, const __nv_bfloat16* __restrict__ W1T,
    const float* __restrict__ b1,
    __nv_bfloat16* __restrict__ Pl, __nv_bfloat16* __restrict__ Pr)
{
    extern __shared__ char smc[];
    uint32_t sb = smem_u32(smc);
    int t = threadIdx.x, lane = t & 31, warp = t >> 5;
    int row0 = blockIdx.x * 64;
    int half = warp >> 2;      // 0 = Pl, 1 = Pr
    int wm = warp & 3;
    float* b1s = (float*)(smc + PP_B1);
    if (t < 128) b1s[t] = b1[t];

    // A: h rows row0..row0+63, K=128, f32 -> bf16, stride 272 B
#pragma unroll
    for (int p = 0; p < 8; p++) {
        int id = t + p * 256;            // 0..2047
        int r = id >> 5, fq = id & 31;   // 32 float4 per row
        int row = row0 + r;
        float4 u = make_float4(0.f, 0.f, 0.f, 0.f);
        if (row < N_NODES)
            u = *(const float4*)(h + (size_t)row * H + fq * 4);
        uint2 pkd;
        pkd.x = f2bf2(u.x, u.y);
        pkd.y = f2bf2(u.z, u.w);
        *(uint2*)(smc + PP_AS + r * 272 + fq * 8) = pkd;
    }
    // W: g_W1T [256][128] bf16 -> smem stride 272.  FULL row = 256 B = 16 uint4 (R8 bug: was 8)
#pragma unroll
    for (int p = 0; p < 16; p++) {
        int id = t + p * 256;            // 0..4095
        int n = id >> 4, q = id & 15;    // 16 uint4 per row
        uint4 w = *(const uint4*)(W1T + n * 128 + q * 8);
        *(uint4*)(smc + PP_WS + n * 272 + q * 16) = w;
    }
    __syncthreads();

    float acc[16][4];
#pragma unroll
    for (int nt = 0; nt < 16; nt++)
#pragma unroll
        for (int m = 0; m < 4; m++) acc[nt][m] = 0.f;

    uint32_t a_base = sb + PP_AS + (uint32_t)(wm * 16 + (lane & 15)) * 272
                      + (uint32_t)(lane >> 4) * 16;
    uint32_t b_base = sb + PP_WS + (uint32_t)half * 128 * 272
                      + (uint32_t)(lane & 7) * 272 + (uint32_t)((lane >> 3) & 1) * 16;
#pragma unroll
    for (int ks = 0; ks < 8; ks++) {
        uint32_t a0, a1, a2, a3;
        ldmA(a0, a1, a2, a3, a_base + ks * 32);
#pragma unroll
        for (int nt = 0; nt < 16; nt++) {
            uint32_t b0, b1v;
            ldmB(b0, b1v, b_base + (uint32_t)nt * 8 * 272 + ks * 32);
            mma16816(acc[nt], a0, a1, a2, a3, b0, b1v);
        }
    }

    int qr = lane >> 2, qc = (lane & 3) * 2;
    int r0 = row0 + wm * 16 + qr;
    int r1 = r0 + 8;
    __nv_bfloat16* outp = half ? Pr : Pl;
#pragma unroll
    for (int nt = 0; nt < 16; nt++) {
        int c0 = nt * 8 + qc;
        float add0 = half ? 0.f : b1s[c0];
        float add1 = half ? 0.f : b1s[c0 + 1];
        if (r0 < N_NODES)
            *(unsigned*)(outp + (size_t)r0 * H + c0) = f2bf2(acc[nt][0] + add0, acc[nt][1] + add1);
        if (r1 < N_NODES)
            *(unsigned*)(outp + (size_t)r1 * H + c0) = f2bf2(acc[nt][2] + add0, acc[nt][3] + add1);
    }
}

// ---------------- fused edge MLP; phase2 on HMMA (verified R7) ----------------
#define TE 128
#define ZST 136
#define EZ1_OFF   0
#define EW2T_OFF  34816
#define EW1_OFF   52224
#define EW3_OFF   58368
#define EB2_OFF   58624
#define ESM_TOTAL 58880

__global__ void __launch_bounds__(256) k_edge(
    const int* __restrict__ src, const int* __restrict__ dst,
    const float* __restrict__ ea, const __nv_bfloat16* __restrict__ Pl,
    const __nv_bfloat16* __restrict__ Pr, const float* __restrict__ W1,
    const float* __restrict__ W2, const float* __restrict__ b2,
    const float* __restrict__ W3, const float* __restrict__ b3,
    float* __restrict__ out)
{
    extern __shared__ char smc[];
    uint32_t sb = smem_u32(smc);

    float* W1es = (float*)(smc + EW1_OFF);
    float* W3s  = (float*)(smc + EW3_OFF);
    float* b2s  = (float*)(smc + EB2_OFF);

    int t = threadIdx.x;

    for (int i = t; i < 12 * 128 / 4; i += 256)
        ((float4*)W1es)[i] = ((const float4*)(W1 + 256 * H))[i];
    if (t < 64) { W3s[t] = W3[t]; b2s[t] = b2[t]; }

    for (int i = t; i < 4096; i += 256) {
        int n = i & 63;
        int kp = i >> 6;
        float f0 = W2[(2 * kp) * 64 + n];
        float f1 = W2[(2 * kp + 1) * 64 + n];
        *(unsigned*)(smc + EW2T_OFF + (n * ZST + 2 * kp) * 2) = f2bf2(f0, f1);
    }

    int e0 = blockIdx.x * TE;
    {
        int el = t >> 1;
        int jh = t & 1;
        int eg = e0 + el;
        int s = src[eg], d = dst[eg];
        unsigned long long eadup[12];
#pragma unroll
        for (int k = 0; k < 12; k++) eadup[k] = dup2(ea[(size_t)eg * 12 + k]);

        const uint4* pl4 = (const uint4*)(Pl + (size_t)s * H);
        const uint4* pr4 = (const uint4*)(Pr + (size_t)d * H);
#pragma unroll
        for (int g = 0; g < 8; g++) {
            int grp = jh * 8 + g;
            uint4 a = pl4[grp];
            uint4 b = pr4[grp];
            float2 pa, pb;
            unsigned long long s01, s23, s45, s67;
            pa = bf2f(a.x); pb = bf2f(b.x); s01 = pk2(pa.x + pb.x, pa.y + pb.y);
            pa = bf2f(a.y); pb = bf2f(b.y); s23 = pk2(pa.x + pb.x, pa.y + pb.y);
            pa = bf2f(a.z); pb = bf2f(b.z); s45 = pk2(pa.x + pb.x, pa.y + pb.y);
            pa = bf2f(a.w); pb = bf2f(b.w); s67 = pk2(pa.x + pb.x, pa.y + pb.y);
            int jb = grp * 8;
#pragma unroll
            for (int k = 0; k < 12; k++) {
                ulonglong2 w0 = *(const ulonglong2*)&W1es[k * 128 + jb];
                ulonglong2 w1 = *(const ulonglong2*)&W1es[k * 128 + jb + 4];
                fma2(s01, w0.x, eadup[k]);
                fma2(s23, w0.y, eadup[k]);
                fma2(s45, w1.x, eadup[k]);
                fma2(s67, w1.y, eadup[k]);
            }
            float2 f01 = upk2(s01), f23 = upk2(s23), f45 = upk2(s45), f67 = upk2(s67);
            uint4 pkd;
            pkd.x = f2bf2(fmaxf(f01.x, 0.f), fmaxf(f01.y, 0.f));
            pkd.y = f2bf2(fmaxf(f23.x, 0.f), fmaxf(f23.y, 0.f));
            pkd.z = f2bf2(fmaxf(f45.x, 0.f), fmaxf(f45.y, 0.f));
            pkd.w = f2bf2(fmaxf(f67.x, 0.f), fmaxf(f67.y, 0.f));
            *(uint4*)(smc + EZ1_OFF + el * (ZST * 2) + jb * 2) = pkd;
        }
    }
    __syncthreads();

    int lane = t & 31, warp = t >> 5;
    int m0 = warp * 16;
    float acc[8][4];
#pragma unroll
    for (int nt = 0; nt < 8; nt++)
#pragma unroll
        for (int m = 0; m < 4; m++) acc[nt][m] = 0.f;

    uint32_t a_base = sb + EZ1_OFF + (uint32_t)(m0 + (lane & 15)) * (ZST * 2)
                      + (uint32_t)(lane >> 4) * 16;
    uint32_t b_base = sb + EW2T_OFF + (uint32_t)(lane & 7) * (ZST * 2)
                      + (uint32_t)((lane >> 3) & 1) * 16;

#pragma unroll
    for (int ks = 0; ks < 8; ks++) {
        uint32_t a0, a1, a2, a3;
        ldmA(a0, a1, a2, a3, a_base + ks * 32);
#pragma unroll
        for (int nt = 0; nt < 8; nt++) {
            uint32_t b0, b1v;
            ldmB(b0, b1v, b_base + (uint32_t)nt * 8 * (ZST * 2) + ks * 32);
            mma16816(acc[nt], a0, a1, a2, a3, b0, b1v);
        }
    }

    int qr = lane >> 2;
    int qc = (lane & 3) * 2;
    float p0 = 0.f, p1 = 0.f;
#pragma unroll
    for (int nt = 0; nt < 8; nt++) {
        int c0 = nt * 8 + qc, c1 = c0 + 1;
        float w30 = W3s[c0], w31 = W3s[c1];
        float bb0 = b2s[c0], bb1 = b2s[c1];
        p0 = fmaf(fmaxf(acc[nt][0] + bb0, 0.f), w30, p0);
        p0 = fmaf(fmaxf(acc[nt][1] + bb1, 0.f), w31, p0);
        p1 = fmaf(fmaxf(acc[nt][2] + bb0, 0.f), w30, p1);
        p1 = fmaf(fmaxf(acc[nt][3] + bb1, 0.f), w31, p1);
    }
    p0 += __shfl_xor_sync(0xffffffffu, p0, 1);
    p0 += __shfl_xor_sync(0xffffffffu, p0, 2);
    p1 += __shfl_xor_sync(0xffffffffu, p1, 1);
    p1 += __shfl_xor_sync(0xffffffffu, p1, 2);
    if ((lane & 3) == 0) {
        float b3v = b3[0];
        float x0 = p0 + b3v;
        float x1 = p1 + b3v;
        out[e0 + m0 + qr]     = fmaxf(x0, 0.f) + log1pf(expf(-fabsf(x0)));
        out[e0 + m0 + qr + 8] = fmaxf(x1, 0.f) + log1pf(expf(-fabsf(x1)));
    }
}

// ---------------- launch ----------------
extern "C" void kernel_launch(void* const* d_in, const int* in_sizes, int n_in,
                              void* d_out, int out_size) {
    const float* x      = (const float*)d_in[0];
    const int*   ei     = (const int*)d_in[1];
    const float* ea     = (const float*)d_in[2];
    const float* node_W = (const float*)d_in[3];
    const float* node_b = (const float*)d_in[4];
    const float* sWl    = (const float*)d_in[5];
    const float* sbl    = (const float*)d_in[6];
    const float* sWr    = (const float*)d_in[7];
    const float* ln_g   = (const float*)d_in[8];
    const float* ln_b   = (const float*)d_in[9];
    const float* W1     = (const float*)d_in[10];
    const float* b1     = (const float*)d_in[11];
    const float* W2     = (const float*)d_in[12];
    const float* b2     = (const float*)d_in[13];
    const float* W3     = (const float*)d_in[14];
    const float* b3     = (const float*)d_in[15];
    float* out = (float*)d_out;
    const int* src = ei;
    const int* dstp = ei + N_EDGES;

    float *pA, *pB, *pInv;
    __nv_bfloat16 *pPl, *pPr, *pWsT, *pW1T;
    cudaGetSymbolAddress((void**)&pA, g_bufA);
    cudaGetSymbolAddress((void**)&pB, g_bufB);
    cudaGetSymbolAddress((void**)&pPl, g_Plh);
    cudaGetSymbolAddress((void**)&pPr, g_Prh);
    cudaGetSymbolAddress((void**)&pInv, g_inv);
    cudaGetSymbolAddress((void**)&pWsT, g_WsT);
    cudaGetSymbolAddress((void**)&pW1T, g_W1T);

    cudaMemsetAsync(pInv, 0, N_NODES * sizeof(float));
    k_deg<<<(N_EDGES + 255) / 256, 256>>>(dstp, pInv);
    k_inv<<<(N_NODES + 255) / 256, 256>>>(pInv);
    k_wprep<<<(3 * 128 * 256 + 255) / 256, 256>>>(sWl, sWr, W1, pWsT, pW1T);

    k_nodeproj<<<(N_NODES * H + 255) / 256, 256>>>(x, node_W, node_b, pA);

    cudaFuncSetAttribute(k_sage_mma, cudaFuncAttributeMaxDynamicSharedMemorySize, SG_SM);
    cudaFuncSetAttribute(k_plpr_mma, cudaFuncAttributeMaxDynamicSharedMemorySize, PP_SM);
    cudaFuncSetAttribute(k_edge, cudaFuncAttributeMaxDynamicSharedMemorySize, ESM_TOTAL);

    float* hcur = pA;
    float* other = pB;
    for (int l = 0; l < 3; l++) {
        cudaMemsetAsync(other, 0, (size_t)N_NODES * H * sizeof(float));
        k_scatter<<<N_EDGES / 8, 256>>>(src, dstp, hcur, other);
        k_sage_mma<<<(N_NODES + 127) / 128, 256, SG_SM>>>(
            hcur, other, pWsT + (size_t)l * 128 * 256, sbl + l * H, pInv,
            ln_g + l * H, ln_b + l * H);
        float* tmp = hcur; hcur = other; other = tmp;
    }

    k_plpr_mma<<<(N_NODES + 63) / 64, 256, PP_SM>>>(hcur, pW1T, b1, pPl, pPr);

    k_edge<<<N_EDGES / TE, 256, ESM_TOTAL>>>(src, dstp, ea, pPl, pPr, W1, W2, b2, W3, b3, out);
}

// round 10
// speedup vs baseline: 3.2869x; 1.3055x over previous
#include <cuda_runtime.h>
#include <cuda_fp16.h>
#include <cstdint>

#define N_NODES 100000
#define N_EDGES 800000
#define H 128
#define HH (H*H)

// ---- scratch (no cudaMalloc allowed) ----
__device__ __half g_bufA[N_NODES * H];
__device__ __half g_bufB[N_NODES * H];
__device__ __half g_Plh[N_NODES * H];
__device__ __half g_Prh[N_NODES * H];
__device__ float g_inv[N_NODES];
__device__ __half g_WsT[3 * H * 256];   // [l][n=128][k=256] : k<128 Wl^T, k>=128 Wr^T
__device__ __half g_W1T[256 * H];       // [n'=256][k=128]   : n'<128 Pl cols, else Pr

// ---- packed fp32x2 helpers ----
__device__ __forceinline__ unsigned long long pk2(float x, float y) {
    unsigned long long r;
    asm("mov.b64 %0, {%1, %2};" : "=l"(r) : "f"(x), "f"(y));
    return r;
}
__device__ __forceinline__ unsigned long long dup2(float x) { return pk2(x, x); }
__device__ __forceinline__ void fma2(unsigned long long& d, unsigned long long a,
                                     unsigned long long b) {
    asm("fma.rn.f32x2 %0, %1, %2, %0;" : "+l"(d) : "l"(a), "l"(b));
}
__device__ __forceinline__ float2 upk2(unsigned long long v) {
    float2 f;
    asm("mov.b64 {%0, %1}, %2;" : "=f"(f.x), "=f"(f.y) : "l"(v));
    return f;
}
// fp16 pack/unpack
__device__ __forceinline__ float2 h2f(unsigned int u) {
    __half2 h = *reinterpret_cast<__half2*>(&u);
    return __half22float2(h);
}
__device__ __forceinline__ unsigned int f2h2(float lo, float hi) {
    __half2 h = __floats2half2_rn(lo, hi);
    return *reinterpret_cast<unsigned int*>(&h);
}
__device__ __forceinline__ uint32_t smem_u32(const void* p) {
    uint32_t a;
    asm("{ .reg .u64 t; cvta.to.shared.u64 t, %1; cvt.u32.u64 %0, t; }" : "=r"(a) : "l"(p));
    return a;
}

// ---- mma helpers (fragment pattern verified R7/R9; dtype now f16) ----
__device__ __forceinline__ void ldmA(uint32_t& a0, uint32_t& a1, uint32_t& a2, uint32_t& a3,
                                     uint32_t addr) {
    asm volatile("ldmatrix.sync.aligned.m8n8.x4.shared.b16 {%0,%1,%2,%3}, [%4];"
                 : "=r"(a0), "=r"(a1), "=r"(a2), "=r"(a3) : "r"(addr));
}
__device__ __forceinline__ void ldmB(uint32_t& b0, uint32_t& b1, uint32_t addr) {
    asm volatile("ldmatrix.sync.aligned.m8n8.x2.shared.b16 {%0,%1}, [%2];"
                 : "=r"(b0), "=r"(b1) : "r"(addr));
}
__device__ __forceinline__ void mma16816(float* c, uint32_t a0, uint32_t a1, uint32_t a2,
                                         uint32_t a3, uint32_t b0, uint32_t b1) {
    asm volatile(
        "mma.sync.aligned.m16n8k16.row.col.f32.f16.f16.f32 "
        "{%0,%1,%2,%3}, {%4,%5,%6,%7}, {%8,%9}, {%0,%1,%2,%3};"
        : "+f"(c[0]), "+f"(c[1]), "+f"(c[2]), "+f"(c[3])
        : "r"(a0), "r"(a1), "r"(a2), "r"(a3), "r"(b0), "r"(b1));
}

// ---------------- degree ----------------
__global__ void k_deg(const int* __restrict__ dst, float* __restrict__ deg) {
    int e = blockIdx.x * 256 + threadIdx.x;
    if (e < N_EDGES) atomicAdd(deg + dst[e], 1.0f);
}
__global__ void k_inv(float* __restrict__ d) {
    int i = blockIdx.x * 256 + threadIdx.x;
    if (i < N_NODES) { float v = d[i]; d[i] = v > 0.f ? 1.f / v : 0.f; }
}

// ---------------- weight prep: transposed fp16 copies ----------------
__global__ void k_wprep(const float* __restrict__ sWl, const float* __restrict__ sWr,
                        const float* __restrict__ W1,
                        __half* __restrict__ WsT, __half* __restrict__ W1T) {
    int i = blockIdx.x * 256 + threadIdx.x;
    if (i < 3 * 128 * 256) {
        int l = i / (128 * 256);
        int rem = i - l * (128 * 256);
        int n = rem >> 8;
        int k = rem & 255;
        float v = (k < 128) ? sWl[l * HH + k * H + n] : sWr[l * HH + (k - 128) * H + n];
        WsT[i] = __float2half_rn(v);
    }
    if (i < 256 * 128) {
        int n = i >> 7, k = i & 127;
        float v = (n < 128) ? W1[k * H + n] : W1[(128 + k) * H + (n - 128)];
        W1T[i] = __float2half_rn(v);
    }
}

// ---------------- node projection -> fp16 h ----------------
__global__ void k_nodeproj(const float* __restrict__ x, const float* __restrict__ W,
                           const float* __restrict__ b, __half* __restrict__ h) {
    int idx = blockIdx.x * 256 + threadIdx.x;   // n*64 + col-pair
    if (idx >= N_NODES * 64) return;
    int n = idx >> 6, jp = idx & 63;
    int j0 = jp * 2;
    float a0 = b[j0], a1 = b[j0 + 1];
#pragma unroll
    for (int k = 0; k < 5; k++) {
        float xv = x[n * 5 + k];
        a0 = fmaf(xv, W[k * H + j0], a0);
        a1 = fmaf(xv, W[k * H + j0 + 1], a1);
    }
    *(unsigned*)(h + (size_t)n * H + j0) = f2h2(a0, a1);
}

// ---------------- scatter-add in fp16: 16 lanes/edge, v4.f16x2 red ----------------
__global__ void k_scatter(const int* __restrict__ src, const int* __restrict__ dst,
                          const __half* __restrict__ h, __half* __restrict__ agg) {
    int g = blockIdx.x * 256 + threadIdx.x;
    int e = g >> 4, l = g & 15;
    if (e >= N_EDGES) return;
    int s = src[e], d = dst[e];
    uint4 v = ((const uint4*)(h + (size_t)s * H))[l];
    __half* p = agg + (size_t)d * H + l * 8;
    asm volatile("red.global.add.noftz.v4.f16x2 [%0], {%1,%2,%3,%4};"
                 :: "l"(p), "r"(v.x), "r"(v.y), "r"(v.z), "r"(v.w) : "memory");
}

// ---------------- SAGE on HMMA fp16: t = (agg*inv | h) @ [Wl;Wr] + bl, LN+ReLU ------
// BM=128, N=128, K=256 in 4 chunks of 64. 256 threads, warp w owns rows w*16..+15.
#define SG_AS 0            // 128*144 = 18432 B
#define SG_WS 18432        // 128*144 = 18432 B
#define SG_LN 36864        // 384 f32 = 1536 B
#define SG_SM 38400
__global__ void __launch_bounds__(256) k_sage_mma(
    const __half* __restrict__ hX, __half* __restrict__ aggY,
    const __half* __restrict__ WsTl, const float* __restrict__ bl,
    const float* __restrict__ inv,
    const float* __restrict__ lg, const float* __restrict__ lb)
{
    extern __shared__ char smc[];
    uint32_t sb = smem_u32(smc);
    int t = threadIdx.x, lane = t & 31, warp = t >> 5;
    int row0 = blockIdx.x * 128;
    float* lns = (float*)(smc + SG_LN);
    if (t < 128) { lns[t] = bl[t]; lns[128 + t] = lg[t]; lns[256 + t] = lb[t]; }

    float acc[16][4];
#pragma unroll
    for (int nt = 0; nt < 16; nt++)
#pragma unroll
        for (int m = 0; m < 4; m++) acc[nt][m] = 0.f;

    for (int c = 0; c < 4; c++) {
        const __half* Usrc = (c < 2) ? aggY : hX;
        int kcol = (c & 1) * 64;
        __syncthreads();
        // A stage: 128 rows x 64 cols fp16 = 16 KB; 2048 ids x uint2(4 halfs)
#pragma unroll
        for (int p = 0; p < 8; p++) {
            int id = t + p * 256;
            int r = id >> 4, fq = id & 15;
            int row = row0 + r;
            uint2 v = make_uint2(0u, 0u);
            if (row < N_NODES) {
                v = *(const uint2*)(Usrc + (size_t)row * H + kcol + fq * 4);
                if (c < 2) {
                    float iv = inv[row];
                    float2 f0 = h2f(v.x), f1 = h2f(v.y);
                    v.x = f2h2(f0.x * iv, f0.y * iv);
                    v.y = f2h2(f1.x * iv, f1.y * iv);
                }
            }
            *(uint2*)(smc + SG_AS + r * 144 + fq * 8) = v;
        }
        // B stage: 128 n-rows x 64 k = 16 KB; raw copy
#pragma unroll
        for (int p = 0; p < 4; p++) {
            int id = t + p * 256;
            int n = id >> 3, q = id & 7;   // 8 uint4 per 64-col (128 B) row
            uint4 w = *(const uint4*)(WsTl + n * 256 + c * 64 + q * 8);
            *(uint4*)(smc + SG_WS + n * 144 + q * 16) = w;
        }
        __syncthreads();
        uint32_t a_base = sb + SG_AS + (uint32_t)(warp * 16 + (lane & 15)) * 144
                          + (uint32_t)(lane >> 4) * 16;
        uint32_t b_base = sb + SG_WS + (uint32_t)(lane & 7) * 144
                          + (uint32_t)((lane >> 3) & 1) * 16;
#pragma unroll
        for (int ks = 0; ks < 4; ks++) {
            uint32_t a0, a1, a2, a3;
            ldmA(a0, a1, a2, a3, a_base + ks * 32);
#pragma unroll
            for (int nt = 0; nt < 16; nt++) {
                uint32_t b0, b1;
                ldmB(b0, b1, b_base + (uint32_t)nt * 8 * 144 + ks * 32);
                mma16816(acc[nt], a0, a1, a2, a3, b0, b1);
            }
        }
    }

    // epilogue: +bl, LayerNorm over quad lanes, affine+ReLU, fp16 store
    int qr = lane >> 2, qc = (lane & 3) * 2;
    int r0 = row0 + warp * 16 + qr;
    int r1 = r0 + 8;
    float s0 = 0.f, s1 = 0.f;
#pragma unroll
    for (int nt = 0; nt < 16; nt++) {
        int c0 = nt * 8 + qc;
        float bb0 = lns[c0], bb1 = lns[c0 + 1];
        acc[nt][0] += bb0; acc[nt][1] += bb1;
        acc[nt][2] += bb0; acc[nt][3] += bb1;
        s0 += acc[nt][0] + acc[nt][1];
        s1 += acc[nt][2] + acc[nt][3];
    }
    s0 += __shfl_xor_sync(0xffffffffu, s0, 1);
    s0 += __shfl_xor_sync(0xffffffffu, s0, 2);
    s1 += __shfl_xor_sync(0xffffffffu, s1, 1);
    s1 += __shfl_xor_sync(0xffffffffu, s1, 2);
    float mu0 = s0 * (1.f / 128.f), mu1 = s1 * (1.f / 128.f);
    float q0 = 0.f, q1 = 0.f;
#pragma unroll
    for (int nt = 0; nt < 16; nt++) {
        float d0 = acc[nt][0] - mu0, d1 = acc[nt][1] - mu0;
        float d2 = acc[nt][2] - mu1, d3 = acc[nt][3] - mu1;
        q0 = fmaf(d0, d0, q0); q0 = fmaf(d1, d1, q0);
        q1 = fmaf(d2, d2, q1); q1 = fmaf(d3, d3, q1);
    }
    q0 += __shfl_xor_sync(0xffffffffu, q0, 1);
    q0 += __shfl_xor_sync(0xffffffffu, q0, 2);
    q1 += __shfl_xor_sync(0xffffffffu, q1, 1);
    q1 += __shfl_xor_sync(0xffffffffu, q1, 2);
    float rs0 = rsqrtf(q0 * (1.f / 128.f) + 1e-5f);
    float rs1 = rsqrtf(q1 * (1.f / 128.f) + 1e-5f);
#pragma unroll
    for (int nt = 0; nt < 16; nt++) {
        int c0 = nt * 8 + qc;
        float g0 = lns[128 + c0], g1 = lns[128 + c0 + 1];
        float o0 = lns[256 + c0], o1 = lns[256 + c0 + 1];
        if (r0 < N_NODES) {
            *(unsigned*)(aggY + (size_t)r0 * H + c0) = f2h2(
                fmaxf(fmaf((acc[nt][0] - mu0) * rs0, g0, o0), 0.f),
                fmaxf(fmaf((acc[nt][1] - mu0) * rs0, g1, o1), 0.f));
        }
        if (r1 < N_NODES) {
            *(unsigned*)(aggY + (size_t)r1 * H + c0) = f2h2(
                fmaxf(fmaf((acc[nt][2] - mu1) * rs1, g0, o0), 0.f),
                fmaxf(fmaf((acc[nt][3] - mu1) * rs1, g1, o1), 0.f));
        }
    }
}

// ---------------- Pl/Pr on HMMA fp16: [Pl|Pr] = h @ W1T', fp16 outputs ----------------
// BM=64; warps 0-3 -> Pl rows (wm*16), warps 4-7 -> Pr same rows. K=128 whole.
#define PP_AS 0            // 64*272 = 17408 B
#define PP_WS 17408        // 256*272 = 69632 B
#define PP_B1 87040        // 128 f32
#define PP_SM 87552
__global__ void __launch_bounds__(256) k_plpr_mma(
    const __half* __restrict__ h, const __half* __restrict__ W1T,
    const float* __restrict__ b1,
    __half* __restrict__ Pl, __half* __restrict__ Pr)
{
    extern __shared__ char smc[];
    uint32_t sb = smem_u32(smc);
    int t = threadIdx.x, lane = t & 31, warp = t >> 5;
    int row0 = blockIdx.x * 64;
    int half_ = warp >> 2;      // 0 = Pl, 1 = Pr
    int wm = warp & 3;
    float* b1s = (float*)(smc + PP_B1);
    if (t < 128) b1s[t] = b1[t];

    // A: h rows row0..row0+63, K=128 fp16 = 256 B/row; raw copy, 1024 ids x uint4
#pragma unroll
    for (int p = 0; p < 4; p++) {
        int id = t + p * 256;            // 0..1023
        int r = id >> 4, fq = id & 15;   // 16 uint4 per row
        int row = row0 + r;
        uint4 v = make_uint4(0u, 0u, 0u, 0u);
        if (row < N_NODES)
            v = *(const uint4*)(h + (size_t)row * H + fq * 8);
        *(uint4*)(smc + PP_AS + r * 272 + fq * 16) = v;
    }
    // W: g_W1T [256][128] fp16 -> smem stride 272; full row = 256 B = 16 uint4
#pragma unroll
    for (int p = 0; p < 16; p++) {
        int id = t + p * 256;            // 0..4095
        int n = id >> 4, q = id & 15;
        uint4 w = *(const uint4*)(W1T + n * 128 + q * 8);
        *(uint4*)(smc + PP_WS + n * 272 + q * 16) = w;
    }
    __syncthreads();

    float acc[16][4];
#pragma unroll
    for (int nt = 0; nt < 16; nt++)
#pragma unroll
        for (int m = 0; m < 4; m++) acc[nt][m] = 0.f;

    uint32_t a_base = sb + PP_AS + (uint32_t)(wm * 16 + (lane & 15)) * 272
                      + (uint32_t)(lane >> 4) * 16;
    uint32_t b_base = sb + PP_WS + (uint32_t)half_ * 128 * 272
                      + (uint32_t)(lane & 7) * 272 + (uint32_t)((lane >> 3) & 1) * 16;
#pragma unroll
    for (int ks = 0; ks < 8; ks++) {
        uint32_t a0, a1, a2, a3;
        ldmA(a0, a1, a2, a3, a_base + ks * 32);
#pragma unroll
        for (int nt = 0; nt < 16; nt++) {
            uint32_t b0, b1v;
            ldmB(b0, b1v, b_base + (uint32_t)nt * 8 * 272 + ks * 32);
            mma16816(acc[nt], a0, a1, a2, a3, b0, b1v);
        }
    }

    int qr = lane >> 2, qc = (lane & 3) * 2;
    int r0 = row0 + wm * 16 + qr;
    int r1 = r0 + 8;
    __half* outp = half_ ? Pr : Pl;
#pragma unroll
    for (int nt = 0; nt < 16; nt++) {
        int c0 = nt * 8 + qc;
        float add0 = half_ ? 0.f : b1s[c0];
        float add1 = half_ ? 0.f : b1s[c0 + 1];
        if (r0 < N_NODES)
            *(unsigned*)(outp + (size_t)r0 * H + c0) = f2h2(acc[nt][0] + add0, acc[nt][1] + add1);
        if (r1 < N_NODES)
            *(unsigned*)(outp + (size_t)r1 * H + c0) = f2h2(acc[nt][2] + add0, acc[nt][3] + add1);
    }
}

// ---------------- fused edge MLP; phase2 on HMMA fp16 ----------------
#define TE 128
#define ZST 136
#define EZ1_OFF   0
#define EW2T_OFF  34816
#define EW1_OFF   52224
#define EW3_OFF   58368
#define EB2_OFF   58624
#define ESM_TOTAL 58880

__global__ void __launch_bounds__(256) k_edge(
    const int* __restrict__ src, const int* __restrict__ dst,
    const float* __restrict__ ea, const __half* __restrict__ Pl,
    const __half* __restrict__ Pr, const float* __restrict__ W1,
    const float* __restrict__ W2, const float* __restrict__ b2,
    const float* __restrict__ W3, const float* __restrict__ b3,
    float* __restrict__ out)
{
    extern __shared__ char smc[];
    uint32_t sb = smem_u32(smc);

    float* W1es = (float*)(smc + EW1_OFF);
    float* W3s  = (float*)(smc + EW3_OFF);
    float* b2s  = (float*)(smc + EB2_OFF);

    int t = threadIdx.x;

    for (int i = t; i < 12 * 128 / 4; i += 256)
        ((float4*)W1es)[i] = ((const float4*)(W1 + 256 * H))[i];
    if (t < 64) { W3s[t] = W3[t]; b2s[t] = b2[t]; }

    for (int i = t; i < 4096; i += 256) {
        int n = i & 63;
        int kp = i >> 6;
        float f0 = W2[(2 * kp) * 64 + n];
        float f1 = W2[(2 * kp + 1) * 64 + n];
        *(unsigned*)(smc + EW2T_OFF + (n * ZST + 2 * kp) * 2) = f2h2(f0, f1);
    }

    int e0 = blockIdx.x * TE;
    {
        int el = t >> 1;
        int jh = t & 1;
        int eg = e0 + el;
        int s = src[eg], d = dst[eg];
        unsigned long long eadup[12];
#pragma unroll
        for (int k = 0; k < 12; k++) eadup[k] = dup2(ea[(size_t)eg * 12 + k]);

        const uint4* pl4 = (const uint4*)(Pl + (size_t)s * H);
        const uint4* pr4 = (const uint4*)(Pr + (size_t)d * H);
#pragma unroll
        for (int g = 0; g < 8; g++) {
            int grp = jh * 8 + g;
            uint4 a = pl4[grp];
            uint4 b = pr4[grp];
            float2 pa, pb;
            unsigned long long s01, s23, s45, s67;
            pa = h2f(a.x); pb = h2f(b.x); s01 = pk2(pa.x + pb.x, pa.y + pb.y);
            pa = h2f(a.y); pb = h2f(b.y); s23 = pk2(pa.x + pb.x, pa.y + pb.y);
            pa = h2f(a.z); pb = h2f(b.z); s45 = pk2(pa.x + pb.x, pa.y + pb.y);
            pa = h2f(a.w); pb = h2f(b.w); s67 = pk2(pa.x + pb.x, pa.y + pb.y);
            int jb = grp * 8;
#pragma unroll
            for (int k = 0; k < 12; k++) {
                ulonglong2 w0 = *(const ulonglong2*)&W1es[k * 128 + jb];
                ulonglong2 w1 = *(const ulonglong2*)&W1es[k * 128 + jb + 4];
                fma2(s01, w0.x, eadup[k]);
                fma2(s23, w0.y, eadup[k]);
                fma2(s45, w1.x, eadup[k]);
                fma2(s67, w1.y, eadup[k]);
            }
            float2 f01 = upk2(s01), f23 = upk2(s23), f45 = upk2(s45), f67 = upk2(s67);
            uint4 pkd;
            pkd.x = f2h2(fmaxf(f01.x, 0.f), fmaxf(f01.y, 0.f));
            pkd.y = f2h2(fmaxf(f23.x, 0.f), fmaxf(f23.y, 0.f));
            pkd.z = f2h2(fmaxf(f45.x, 0.f), fmaxf(f45.y, 0.f));
            pkd.w = f2h2(fmaxf(f67.x, 0.f), fmaxf(f67.y, 0.f));
            *(uint4*)(smc + EZ1_OFF + el * (ZST * 2) + jb * 2) = pkd;
        }
    }
    __syncthreads();

    int lane = t & 31, warp = t >> 5;
    int m0 = warp * 16;
    float acc[8][4];
#pragma unroll
    for (int nt = 0; nt < 8; nt++)
#pragma unroll
        for (int m = 0; m < 4; m++) acc[nt][m] = 0.f;

    uint32_t a_base = sb + EZ1_OFF + (uint32_t)(m0 + (lane & 15)) * (ZST * 2)
                      + (uint32_t)(lane >> 4) * 16;
    uint32_t b_base = sb + EW2T_OFF + (uint32_t)(lane & 7) * (ZST * 2)
                      + (uint32_t)((lane >> 3) & 1) * 16;

#pragma unroll
    for (int ks = 0; ks < 8; ks++) {
        uint32_t a0, a1, a2, a3;
        ldmA(a0, a1, a2, a3, a_base + ks * 32);
#pragma unroll
        for (int nt = 0; nt < 8; nt++) {
            uint32_t b0, b1v;
            ldmB(b0, b1v, b_base + (uint32_t)nt * 8 * (ZST * 2) + ks * 32);
            mma16816(acc[nt], a0, a1, a2, a3, b0, b1v);
        }
    }

    int qr = lane >> 2;
    int qc = (lane & 3) * 2;
    float p0 = 0.f, p1 = 0.f;
#pragma unroll
    for (int nt = 0; nt < 8; nt++) {
        int c0 = nt * 8 + qc, c1 = c0 + 1;
        float w30 = W3s[c0], w31 = W3s[c1];
        float bb0 = b2s[c0], bb1 = b2s[c1];
        p0 = fmaf(fmaxf(acc[nt][0] + bb0, 0.f), w30, p0);
        p0 = fmaf(fmaxf(acc[nt][1] + bb1, 0.f), w31, p0);
        p1 = fmaf(fmaxf(acc[nt][2] + bb0, 0.f), w30, p1);
        p1 = fmaf(fmaxf(acc[nt][3] + bb1, 0.f), w31, p1);
    }
    p0 += __shfl_xor_sync(0xffffffffu, p0, 1);
    p0 += __shfl_xor_sync(0xffffffffu, p0, 2);
    p1 += __shfl_xor_sync(0xffffffffu, p1, 1);
    p1 += __shfl_xor_sync(0xffffffffu, p1, 2);
    if ((lane & 3) == 0) {
        float b3v = b3[0];
        float x0 = p0 + b3v;
        float x1 = p1 + b3v;
        out[e0 + m0 + qr]     = fmaxf(x0, 0.f) + log1pf(expf(-fabsf(x0)));
        out[e0 + m0 + qr + 8] = fmaxf(x1, 0.f) + log1pf(expf(-fabsf(x1)));
    }
}

// ---------------- launch ----------------
extern "C" void kernel_launch(void* const* d_in, const int* in_sizes, int n_in,
                              void* d_out, int out_size) {
    const float* x      = (const float*)d_in[0];
    const int*   ei     = (const int*)d_in[1];
    const float* ea     = (const float*)d_in[2];
    const float* node_W = (const float*)d_in[3];
    const float* node_b = (const float*)d_in[4];
    const float* sWl    = (const float*)d_in[5];
    const float* sbl    = (const float*)d_in[6];
    const float* sWr    = (const float*)d_in[7];
    const float* ln_g   = (const float*)d_in[8];
    const float* ln_b   = (const float*)d_in[9];
    const float* W1     = (const float*)d_in[10];
    const float* b1     = (const float*)d_in[11];
    const float* W2     = (const float*)d_in[12];
    const float* b2     = (const float*)d_in[13];
    const float* W3     = (const float*)d_in[14];
    const float* b3     = (const float*)d_in[15];
    float* out = (float*)d_out;
    const int* src = ei;
    const int* dstp = ei + N_EDGES;

    float *pInv;
    __half *pA, *pB, *pPl, *pPr, *pWsT, *pW1T;
    cudaGetSymbolAddress((void**)&pA, g_bufA);
    cudaGetSymbolAddress((void**)&pB, g_bufB);
    cudaGetSymbolAddress((void**)&pPl, g_Plh);
    cudaGetSymbolAddress((void**)&pPr, g_Prh);
    cudaGetSymbolAddress((void**)&pInv, g_inv);
    cudaGetSymbolAddress((void**)&pWsT, g_WsT);
    cudaGetSymbolAddress((void**)&pW1T, g_W1T);

    cudaMemsetAsync(pInv, 0, N_NODES * sizeof(float));
    k_deg<<<(N_EDGES + 255) / 256, 256>>>(dstp, pInv);
    k_inv<<<(N_NODES + 255) / 256, 256>>>(pInv);
    k_wprep<<<(3 * 128 * 256 + 255) / 256, 256>>>(sWl, sWr, W1, pWsT, pW1T);

    k_nodeproj<<<(N_NODES * 64 + 255) / 256, 256>>>(x, node_W, node_b, pA);

    cudaFuncSetAttribute(k_sage_mma, cudaFuncAttributeMaxDynamicSharedMemorySize, SG_SM);
    cudaFuncSetAttribute(k_plpr_mma, cudaFuncAttributeMaxDynamicSharedMemorySize, PP_SM);
    cudaFuncSetAttribute(k_edge, cudaFuncAttributeMaxDynamicSharedMemorySize, ESM_TOTAL);

    __half* hcur = pA;
    __half* other = pB;
    for (int l = 0; l < 3; l++) {
        cudaMemsetAsync(other, 0, (size_t)N_NODES * H * sizeof(__half));
        k_scatter<<<(N_EDGES * 16 + 255) / 256, 256>>>(src, dstp, hcur, other);
        k_sage_mma<<<(N_NODES + 127) / 128, 256, SG_SM>>>(
            hcur, other, pWsT + (size_t)l * 128 * 256, sbl + l * H, pInv,
            ln_g + l * H, ln_b + l * H);
        __half* tmp = hcur; hcur = other; other = tmp;
    }

    k_plpr_mma<<<(N_NODES + 63) / 64, 256, PP_SM>>>(hcur, pW1T, b1, pPl, pPr);

    k_edge<<<N_EDGES / TE, 256, ESM_TOTAL>>>(src, dstp, ea, pPl, pPr, W1, W2, b2, W3, b3, out);
}

// round 11
// speedup vs baseline: 3.6320x; 1.1050x over previous
#include <cuda_runtime.h>
#include <cuda_fp16.h>
#include <cstdint>

#define N_NODES 100000
#define N_EDGES 800000
#define H 128
#define HH (H*H)
#define NB ((N_NODES + 255) / 256)   // 391 scan blocks

// ---- scratch (no cudaMalloc allowed) ----
__device__ __half g_bufA[N_NODES * H];
__device__ __half g_bufB[N_NODES * H];
__device__ __half g_Plh[N_NODES * H];
__device__ __half g_Prh[N_NODES * H];
__device__ float g_inv[N_NODES];
__device__ __half g_WsT[3 * H * 256];   // [l][n=128][k=256] : k<128 Wl^T, k>=128 Wr^T
__device__ __half g_W1T[256 * H];       // [n'=256][k=128]   : n'<128 Pl cols, else Pr
// CSR scratch
__device__ int g_degi[N_NODES];
__device__ int g_loc[N_NODES];
__device__ int g_bsum[512];
__device__ int g_boff[512];
__device__ int g_off[N_NODES + 1];
__device__ int g_cur[N_NODES];
__device__ int g_csr[N_EDGES];

// ---- packed fp32x2 helpers ----
__device__ __forceinline__ unsigned long long pk2(float x, float y) {
    unsigned long long r;
    asm("mov.b64 %0, {%1, %2};" : "=l"(r) : "f"(x), "f"(y));
    return r;
}
__device__ __forceinline__ unsigned long long dup2(float x) { return pk2(x, x); }
__device__ __forceinline__ void fma2(unsigned long long& d, unsigned long long a,
                                     unsigned long long b) {
    asm("fma.rn.f32x2 %0, %1, %2, %0;" : "+l"(d) : "l"(a), "l"(b));
}
__device__ __forceinline__ float2 upk2(unsigned long long v) {
    float2 f;
    asm("mov.b64 {%0, %1}, %2;" : "=f"(f.x), "=f"(f.y) : "l"(v));
    return f;
}
// fp16 pack/unpack
__device__ __forceinline__ float2 h2f(unsigned int u) {
    __half2 h = *reinterpret_cast<__half2*>(&u);
    return __half22float2(h);
}
__device__ __forceinline__ unsigned int f2h2(float lo, float hi) {
    __half2 h = __floats2half2_rn(lo, hi);
    return *reinterpret_cast<unsigned int*>(&h);
}
__device__ __forceinline__ uint32_t smem_u32(const void* p) {
    uint32_t a;
    asm("{ .reg .u64 t; cvta.to.shared.u64 t, %1; cvt.u32.u64 %0, t; }" : "=r"(a) : "l"(p));
    return a;
}

// ---- mma helpers (verified R7/R9/R10) ----
__device__ __forceinline__ void ldmA(uint32_t& a0, uint32_t& a1, uint32_t& a2, uint32_t& a3,
                                     uint32_t addr) {
    asm volatile("ldmatrix.sync.aligned.m8n8.x4.shared.b16 {%0,%1,%2,%3}, [%4];"
                 : "=r"(a0), "=r"(a1), "=r"(a2), "=r"(a3) : "r"(addr));
}
__device__ __forceinline__ void ldmB(uint32_t& b0, uint32_t& b1, uint32_t addr) {
    asm volatile("ldmatrix.sync.aligned.m8n8.x2.shared.b16 {%0,%1}, [%2];"
                 : "=r"(b0), "=r"(b1) : "r"(addr));
}
__device__ __forceinline__ void mma16816(float* c, uint32_t a0, uint32_t a1, uint32_t a2,
                                         uint32_t a3, uint32_t b0, uint32_t b1) {
    asm volatile(
        "mma.sync.aligned.m16n8k16.row.col.f32.f16.f16.f32 "
        "{%0,%1,%2,%3}, {%4,%5,%6,%7}, {%8,%9}, {%0,%1,%2,%3};"
        : "+f"(c[0]), "+f"(c[1]), "+f"(c[2]), "+f"(c[3])
        : "r"(a0), "r"(a1), "r"(a2), "r"(a3), "r"(b0), "r"(b1));
}

// ---------------- degree (int) + inv ----------------
__global__ void k_deg(const int* __restrict__ dst, int* __restrict__ degi) {
    int e = blockIdx.x * 256 + threadIdx.x;
    if (e < N_EDGES) atomicAdd(degi + dst[e], 1);
}
__global__ void k_inv(const int* __restrict__ degi, float* __restrict__ inv) {
    int i = blockIdx.x * 256 + threadIdx.x;
    if (i < N_NODES) { int v = degi[i]; inv[i] = v > 0 ? 1.f / (float)v : 0.f; }
}

// ---------------- CSR build: block scan + fill ----------------
__global__ void k_scan1(const int* __restrict__ degi, int* __restrict__ loc,
                        int* __restrict__ bsum) {
    __shared__ int sm[256];
    int tid = threadIdx.x;
    int gid = blockIdx.x * 256 + tid;
    int v = (gid < N_NODES) ? degi[gid] : 0;
    sm[tid] = v;
    __syncthreads();
#pragma unroll
    for (int o = 1; o < 256; o <<= 1) {
        int y = (tid >= o) ? sm[tid - o] : 0;
        __syncthreads();
        sm[tid] += y;
        __syncthreads();
    }
    if (gid < N_NODES) loc[gid] = sm[tid] - v;   // exclusive within block
    if (tid == 255) bsum[blockIdx.x] = sm[255];
}
__global__ void k_scan2(const int* __restrict__ bsum, int* __restrict__ boff) {
    __shared__ int sm[512];
    int tid = threadIdx.x;
    int v = (tid < NB) ? bsum[tid] : 0;
    sm[tid] = v;
    __syncthreads();
#pragma unroll
    for (int o = 1; o < 512; o <<= 1) {
        int y = (tid >= o) ? sm[tid - o] : 0;
        __syncthreads();
        sm[tid] += y;
        __syncthreads();
    }
    if (tid < NB) boff[tid] = sm[tid] - v;       // exclusive block offsets
}
__global__ void k_scan3(const int* __restrict__ loc, const int* __restrict__ boff,
                        int* __restrict__ off, int* __restrict__ cur) {
    int gid = blockIdx.x * 256 + threadIdx.x;
    if (gid < N_NODES) {
        int o = loc[gid] + boff[gid >> 8];
        off[gid] = o;
        cur[gid] = o;
    }
    if (gid == 0) off[N_NODES] = N_EDGES;
}
__global__ void k_csrfill(const int* __restrict__ src, const int* __restrict__ dst,
                          int* __restrict__ cur, int* __restrict__ csr) {
    int e = blockIdx.x * 256 + threadIdx.x;
    if (e < N_EDGES) {
        int d = dst[e];
        int slot = atomicAdd(cur + d, 1);
        csr[slot] = src[e];
    }
}

// ---------------- weight prep: transposed fp16 copies ----------------
__global__ void k_wprep(const float* __restrict__ sWl, const float* __restrict__ sWr,
                        const float* __restrict__ W1,
                        __half* __restrict__ WsT, __half* __restrict__ W1T) {
    int i = blockIdx.x * 256 + threadIdx.x;
    if (i < 3 * 128 * 256) {
        int l = i / (128 * 256);
        int rem = i - l * (128 * 256);
        int n = rem >> 8;
        int k = rem & 255;
        float v = (k < 128) ? sWl[l * HH + k * H + n] : sWr[l * HH + (k - 128) * H + n];
        WsT[i] = __float2half_rn(v);
    }
    if (i < 256 * 128) {
        int n = i >> 7, k = i & 127;
        float v = (n < 128) ? W1[k * H + n] : W1[(128 + k) * H + (n - 128)];
        W1T[i] = __float2half_rn(v);
    }
}

// ---------------- node projection -> fp16 h (W in smem, 16 threads/node) ------------
__global__ void __launch_bounds__(256) k_nodeproj(
    const float* __restrict__ x, const float* __restrict__ W,
    const float* __restrict__ b, __half* __restrict__ h) {
    __shared__ float Ws[5 * 128];
    __shared__ float bs[128];
    int t = threadIdx.x;
    if (t < 128) bs[t] = b[t];
    for (int i = t; i < 640; i += 256) Ws[i] = W[i];
    __syncthreads();
    int id = blockIdx.x * 256 + t;
    int node = id >> 4;
    if (node >= N_NODES) return;
    int c0 = (id & 15) * 8;
    float xv[5];
#pragma unroll
    for (int k = 0; k < 5; k++) xv[k] = x[node * 5 + k];
    float a[8];
#pragma unroll
    for (int j = 0; j < 8; j++) a[j] = bs[c0 + j];
#pragma unroll
    for (int k = 0; k < 5; k++)
#pragma unroll
        for (int j = 0; j < 8; j++)
            a[j] = fmaf(xv[k], Ws[k * 128 + c0 + j], a[j]);
    uint4 o;
    o.x = f2h2(a[0], a[1]); o.y = f2h2(a[2], a[3]);
    o.z = f2h2(a[4], a[5]); o.w = f2h2(a[6], a[7]);
    *(uint4*)(h + (size_t)node * H + c0) = o;
}

// ---------------- CSR gather mean: agg[n] = (1/deg) * sum_{s in nbrs(n)} h[s] --------
// warp per node; lane owns 4 halves; fp32 accumulation.
__global__ void k_gather(const int* __restrict__ off, const int* __restrict__ csr,
                         const __half* __restrict__ h, const float* __restrict__ inv,
                         __half* __restrict__ agg) {
    int node = (blockIdx.x * blockDim.x + threadIdx.x) >> 5;
    int lane = threadIdx.x & 31;
    if (node >= N_NODES) return;
    int b = off[node], e = off[node + 1];
    float a0 = 0.f, a1 = 0.f, a2 = 0.f, a3 = 0.f;
    for (int i = b; i < e; i++) {
        int s = csr[i];
        uint2 v = ((const uint2*)(h + (size_t)s * H))[lane];
        float2 f0 = h2f(v.x), f1 = h2f(v.y);
        a0 += f0.x; a1 += f0.y; a2 += f1.x; a3 += f1.y;
    }
    float iv = inv[node];
    uint2 o;
    o.x = f2h2(a0 * iv, a1 * iv);
    o.y = f2h2(a2 * iv, a3 * iv);
    ((uint2*)(agg + (size_t)node * H))[lane] = o;
}

// ---------------- SAGE on HMMA fp16: t = (mean | h) @ [Wl;Wr] + bl, LN+ReLU ----------
// BM=128, N=128, K=256 in 4 chunks of 64. mean already includes 1/deg.
#define SG_AS 0            // 128*144 = 18432 B
#define SG_WS 18432        // 128*144 = 18432 B
#define SG_LN 36864        // 384 f32 = 1536 B
#define SG_SM 38400
__global__ void __launch_bounds__(256) k_sage_mma(
    const __half* __restrict__ hX, __half* __restrict__ aggY,
    const __half* __restrict__ WsTl, const float* __restrict__ bl,
    const float* __restrict__ lg, const float* __restrict__ lb)
{
    extern __shared__ char smc[];
    uint32_t sb = smem_u32(smc);
    int t = threadIdx.x, lane = t & 31, warp = t >> 5;
    int row0 = blockIdx.x * 128;
    float* lns = (float*)(smc + SG_LN);
    if (t < 128) { lns[t] = bl[t]; lns[128 + t] = lg[t]; lns[256 + t] = lb[t]; }

    float acc[16][4];
#pragma unroll
    for (int nt = 0; nt < 16; nt++)
#pragma unroll
        for (int m = 0; m < 4; m++) acc[nt][m] = 0.f;

    for (int c = 0; c < 4; c++) {
        const __half* Usrc = (c < 2) ? aggY : hX;
        int kcol = (c & 1) * 64;
        __syncthreads();
        // A stage: 128 rows x 64 cols fp16; raw copy
#pragma unroll
        for (int p = 0; p < 8; p++) {
            int id = t + p * 256;
            int r = id >> 4, fq = id & 15;
            int row = row0 + r;
            uint2 v = make_uint2(0u, 0u);
            if (row < N_NODES)
                v = *(const uint2*)(Usrc + (size_t)row * H + kcol + fq * 4);
            *(uint2*)(smc + SG_AS + r * 144 + fq * 8) = v;
        }
        // B stage: raw copy
#pragma unroll
        for (int p = 0; p < 4; p++) {
            int id = t + p * 256;
            int n = id >> 3, q = id & 7;
            uint4 w = *(const uint4*)(WsTl + n * 256 + c * 64 + q * 8);
            *(uint4*)(smc + SG_WS + n * 144 + q * 16) = w;
        }
        __syncthreads();
        uint32_t a_base = sb + SG_AS + (uint32_t)(warp * 16 + (lane & 15)) * 144
                          + (uint32_t)(lane >> 4) * 16;
        uint32_t b_base = sb + SG_WS + (uint32_t)(lane & 7) * 144
                          + (uint32_t)((lane >> 3) & 1) * 16;
#pragma unroll
        for (int ks = 0; ks < 4; ks++) {
            uint32_t a0, a1, a2, a3;
            ldmA(a0, a1, a2, a3, a_base + ks * 32);
#pragma unroll
            for (int nt = 0; nt < 16; nt++) {
                uint32_t b0, b1;
                ldmB(b0, b1, b_base + (uint32_t)nt * 8 * 144 + ks * 32);
                mma16816(acc[nt], a0, a1, a2, a3, b0, b1);
            }
        }
    }

    // epilogue: +bl, LayerNorm over quad lanes, affine+ReLU, fp16 store
    int qr = lane >> 2, qc = (lane & 3) * 2;
    int r0 = row0 + warp * 16 + qr;
    int r1 = r0 + 8;
    float s0 = 0.f, s1 = 0.f;
#pragma unroll
    for (int nt = 0; nt < 16; nt++) {
        int c0 = nt * 8 + qc;
        float bb0 = lns[c0], bb1 = lns[c0 + 1];
        acc[nt][0] += bb0; acc[nt][1] += bb1;
        acc[nt][2] += bb0; acc[nt][3] += bb1;
        s0 += acc[nt][0] + acc[nt][1];
        s1 += acc[nt][2] + acc[nt][3];
    }
    s0 += __shfl_xor_sync(0xffffffffu, s0, 1);
    s0 += __shfl_xor_sync(0xffffffffu, s0, 2);
    s1 += __shfl_xor_sync(0xffffffffu, s1, 1);
    s1 += __shfl_xor_sync(0xffffffffu, s1, 2);
    float mu0 = s0 * (1.f / 128.f), mu1 = s1 * (1.f / 128.f);
    float q0 = 0.f, q1 = 0.f;
#pragma unroll
    for (int nt = 0; nt < 16; nt++) {
        float d0 = acc[nt][0] - mu0, d1 = acc[nt][1] - mu0;
        float d2 = acc[nt][2] - mu1, d3 = acc[nt][3] - mu1;
        q0 = fmaf(d0, d0, q0); q0 = fmaf(d1, d1, q0);
        q1 = fmaf(d2, d2, q1); q1 = fmaf(d3, d3, q1);
    }
    q0 += __shfl_xor_sync(0xffffffffu, q0, 1);
    q0 += __shfl_xor_sync(0xffffffffu, q0, 2);
    q1 += __shfl_xor_sync(0xffffffffu, q1, 1);
    q1 += __shfl_xor_sync(0xffffffffu, q1, 2);
    float rs0 = rsqrtf(q0 * (1.f / 128.f) + 1e-5f);
    float rs1 = rsqrtf(q1 * (1.f / 128.f) + 1e-5f);
#pragma unroll
    for (int nt = 0; nt < 16; nt++) {
        int c0 = nt * 8 + qc;
        float g0 = lns[128 + c0], g1 = lns[128 + c0 + 1];
        float o0 = lns[256 + c0], o1 = lns[256 + c0 + 1];
        if (r0 < N_NODES) {
            *(unsigned*)(aggY + (size_t)r0 * H + c0) = f2h2(
                fmaxf(fmaf((acc[nt][0] - mu0) * rs0, g0, o0), 0.f),
                fmaxf(fmaf((acc[nt][1] - mu0) * rs0, g1, o1), 0.f));
        }
        if (r1 < N_NODES) {
            *(unsigned*)(aggY + (size_t)r1 * H + c0) = f2h2(
                fmaxf(fmaf((acc[nt][2] - mu1) * rs1, g0, o0), 0.f),
                fmaxf(fmaf((acc[nt][3] - mu1) * rs1, g1, o1), 0.f));
        }
    }
}

// ---------------- Pl/Pr on HMMA fp16 (verified R10) ----------------
#define PP_AS 0            // 64*272 = 17408 B
#define PP_WS 17408        // 256*272 = 69632 B
#define PP_B1 87040        // 128 f32
#define PP_SM 87552
__global__ void __launch_bounds__(256) k_plpr_mma(
    const __half* __restrict__ h, const __half* __restrict__ W1T,
    const float* __restrict__ b1,
    __half* __restrict__ Pl, __half* __restrict__ Pr)
{
    extern __shared__ char smc[];
    uint32_t sb = smem_u32(smc);
    int t = threadIdx.x, lane = t & 31, warp = t >> 5;
    int row0 = blockIdx.x * 64;
    int half_ = warp >> 2;
    int wm = warp & 3;
    float* b1s = (float*)(smc + PP_B1);
    if (t < 128) b1s[t] = b1[t];

#pragma unroll
    for (int p = 0; p < 4; p++) {
        int id = t + p * 256;
        int r = id >> 4, fq = id & 15;
        int row = row0 + r;
        uint4 v = make_uint4(0u, 0u, 0u, 0u);
        if (row < N_NODES)
            v = *(const uint4*)(h + (size_t)row * H + fq * 8);
        *(uint4*)(smc + PP_AS + r * 272 + fq * 16) = v;
    }
#pragma unroll
    for (int p = 0; p < 16; p++) {
        int id = t + p * 256;
        int n = id >> 4, q = id & 15;
        uint4 w = *(const uint4*)(W1T + n * 128 + q * 8);
        *(uint4*)(smc + PP_WS + n * 272 + q * 16) = w;
    }
    __syncthreads();

    float acc[16][4];
#pragma unroll
    for (int nt = 0; nt < 16; nt++)
#pragma unroll
        for (int m = 0; m < 4; m++) acc[nt][m] = 0.f;

    uint32_t a_base = sb + PP_AS + (uint32_t)(wm * 16 + (lane & 15)) * 272
                      + (uint32_t)(lane >> 4) * 16;
    uint32_t b_base = sb + PP_WS + (uint32_t)half_ * 128 * 272
                      + (uint32_t)(lane & 7) * 272 + (uint32_t)((lane >> 3) & 1) * 16;
#pragma unroll
    for (int ks = 0; ks < 8; ks++) {
        uint32_t a0, a1, a2, a3;
        ldmA(a0, a1, a2, a3, a_base + ks * 32);
#pragma unroll
        for (int nt = 0; nt < 16; nt++) {
            uint32_t b0, b1v;
            ldmB(b0, b1v, b_base + (uint32_t)nt * 8 * 272 + ks * 32);
            mma16816(acc[nt], a0, a1, a2, a3, b0, b1v);
        }
    }

    int qr = lane >> 2, qc = (lane & 3) * 2;
    int r0 = row0 + wm * 16 + qr;
    int r1 = r0 + 8;
    __half* outp = half_ ? Pr : Pl;
#pragma unroll
    for (int nt = 0; nt < 16; nt++) {
        int c0 = nt * 8 + qc;
        float add0 = half_ ? 0.f : b1s[c0];
        float add1 = half_ ? 0.f : b1s[c0 + 1];
        if (r0 < N_NODES)
            *(unsigned*)(outp + (size_t)r0 * H + c0) = f2h2(acc[nt][0] + add0, acc[nt][1] + add1);
        if (r1 < N_NODES)
            *(unsigned*)(outp + (size_t)r1 * H + c0) = f2h2(acc[nt][2] + add0, acc[nt][3] + add1);
    }
}

// ---------------- fused edge MLP; phase2 on HMMA fp16 (verified R10) ----------------
#define TE 128
#define ZST 136
#define EZ1_OFF   0
#define EW2T_OFF  34816
#define EW1_OFF   52224
#define EW3_OFF   58368
#define EB2_OFF   58624
#define ESM_TOTAL 58880

__global__ void __launch_bounds__(256) k_edge(
    const int* __restrict__ src, const int* __restrict__ dst,
    const float* __restrict__ ea, const __half* __restrict__ Pl,
    const __half* __restrict__ Pr, const float* __restrict__ W1,
    const float* __restrict__ W2, const float* __restrict__ b2,
    const float* __restrict__ W3, const float* __restrict__ b3,
    float* __restrict__ out)
{
    extern __shared__ char smc[];
    uint32_t sb = smem_u32(smc);

    float* W1es = (float*)(smc + EW1_OFF);
    float* W3s  = (float*)(smc + EW3_OFF);
    float* b2s  = (float*)(smc + EB2_OFF);

    int t = threadIdx.x;

    for (int i = t; i < 12 * 128 / 4; i += 256)
        ((float4*)W1es)[i] = ((const float4*)(W1 + 256 * H))[i];
    if (t < 64) { W3s[t] = W3[t]; b2s[t] = b2[t]; }

    for (int i = t; i < 4096; i += 256) {
        int n = i & 63;
        int kp = i >> 6;
        float f0 = W2[(2 * kp) * 64 + n];
        float f1 = W2[(2 * kp + 1) * 64 + n];
        *(unsigned*)(smc + EW2T_OFF + (n * ZST + 2 * kp) * 2) = f2h2(f0, f1);
    }

    int e0 = blockIdx.x * TE;
    {
        int el = t >> 1;
        int jh = t & 1;
        int eg = e0 + el;
        int s = src[eg], d = dst[eg];
        unsigned long long eadup[12];
#pragma unroll
        for (int k = 0; k < 12; k++) eadup[k] = dup2(ea[(size_t)eg * 12 + k]);

        const uint4* pl4 = (const uint4*)(Pl + (size_t)s * H);
        const uint4* pr4 = (const uint4*)(Pr + (size_t)d * H);
#pragma unroll
        for (int g = 0; g < 8; g++) {
            int grp = jh * 8 + g;
            uint4 a = pl4[grp];
            uint4 b = pr4[grp];
            float2 pa, pb;
            unsigned long long s01, s23, s45, s67;
            pa = h2f(a.x); pb = h2f(b.x); s01 = pk2(pa.x + pb.x, pa.y + pb.y);
            pa = h2f(a.y); pb = h2f(b.y); s23 = pk2(pa.x + pb.x, pa.y + pb.y);
            pa = h2f(a.z); pb = h2f(b.z); s45 = pk2(pa.x + pb.x, pa.y + pb.y);
            pa = h2f(a.w); pb = h2f(b.w); s67 = pk2(pa.x + pb.x, pa.y + pb.y);
            int jb = grp * 8;
#pragma unroll
            for (int k = 0; k < 12; k++) {
                ulonglong2 w0 = *(const ulonglong2*)&W1es[k * 128 + jb];
                ulonglong2 w1 = *(const ulonglong2*)&W1es[k * 128 + jb + 4];
                fma2(s01, w0.x, eadup[k]);
                fma2(s23, w0.y, eadup[k]);
                fma2(s45, w1.x, eadup[k]);
                fma2(s67, w1.y, eadup[k]);
            }
            float2 f01 = upk2(s01), f23 = upk2(s23), f45 = upk2(s45), f67 = upk2(s67);
            uint4 pkd;
            pkd.x = f2h2(fmaxf(f01.x, 0.f), fmaxf(f01.y, 0.f));
            pkd.y = f2h2(fmaxf(f23.x, 0.f), fmaxf(f23.y, 0.f));
            pkd.z = f2h2(fmaxf(f45.x, 0.f), fmaxf(f45.y, 0.f));
            pkd.w = f2h2(fmaxf(f67.x, 0.f), fmaxf(f67.y, 0.f));
            *(uint4*)(smc + EZ1_OFF + el * (ZST * 2) + jb * 2) = pkd;
        }
    }
    __syncthreads();

    int lane = t & 31, warp = t >> 5;
    int m0 = warp * 16;
    float acc[8][4];
#pragma unroll
    for (int nt = 0; nt < 8; nt++)
#pragma unroll
        for (int m = 0; m < 4; m++) acc[nt][m] = 0.f;

    uint32_t a_base = sb + EZ1_OFF + (uint32_t)(m0 + (lane & 15)) * (ZST * 2)
                      + (uint32_t)(lane >> 4) * 16;
    uint32_t b_base = sb + EW2T_OFF + (uint32_t)(lane & 7) * (ZST * 2)
                      + (uint32_t)((lane >> 3) & 1) * 16;

#pragma unroll
    for (int ks = 0; ks < 8; ks++) {
        uint32_t a0, a1, a2, a3;
        ldmA(a0, a1, a2, a3, a_base + ks * 32);
#pragma unroll
        for (int nt = 0; nt < 8; nt++) {
            uint32_t b0, b1v;
            ldmB(b0, b1v, b_base + (uint32_t)nt * 8 * (ZST * 2) + ks * 32);
            mma16816(acc[nt], a0, a1, a2, a3, b0, b1v);
        }
    }

    int qr = lane >> 2;
    int qc = (lane & 3) * 2;
    float p0 = 0.f, p1 = 0.f;
#pragma unroll
    for (int nt = 0; nt < 8; nt++) {
        int c0 = nt * 8 + qc, c1 = c0 + 1;
        float w30 = W3s[c0], w31 = W3s[c1];
        float bb0 = b2s[c0], bb1 = b2s[c1];
        p0 = fmaf(fmaxf(acc[nt][0] + bb0, 0.f), w30, p0);
        p0 = fmaf(fmaxf(acc[nt][1] + bb1, 0.f), w31, p0);
        p1 = fmaf(fmaxf(acc[nt][2] + bb0, 0.f), w30, p1);
        p1 = fmaf(fmaxf(acc[nt][3] + bb1, 0.f), w31, p1);
    }
    p0 += __shfl_xor_sync(0xffffffffu, p0, 1);
    p0 += __shfl_xor_sync(0xffffffffu, p0, 2);
    p1 += __shfl_xor_sync(0xffffffffu, p1, 1);
    p1 += __shfl_xor_sync(0xffffffffu, p1, 2);
    if ((lane & 3) == 0) {
        float b3v = b3[0];
        float x0 = p0 + b3v;
        float x1 = p1 + b3v;
        out[e0 + m0 + qr]     = fmaxf(x0, 0.f) + log1pf(expf(-fabsf(x0)));
        out[e0 + m0 + qr + 8] = fmaxf(x1, 0.f) + log1pf(expf(-fabsf(x1)));
    }
}

// ---------------- launch ----------------
extern "C" void kernel_launch(void* const* d_in, const int* in_sizes, int n_in,
                              void* d_out, int out_size) {
    const float* x      = (const float*)d_in[0];
    const int*   ei     = (const int*)d_in[1];
    const float* ea     = (const float*)d_in[2];
    const float* node_W = (const float*)d_in[3];
    const float* node_b = (const float*)d_in[4];
    const float* sWl    = (const float*)d_in[5];
    const float* sbl    = (const float*)d_in[6];
    const float* sWr    = (const float*)d_in[7];
    const float* ln_g   = (const float*)d_in[8];
    const float* ln_b   = (const float*)d_in[9];
    const float* W1     = (const float*)d_in[10];
    const float* b1     = (const float*)d_in[11];
    const float* W2     = (const float*)d_in[12];
    const float* b2     = (const float*)d_in[13];
    const float* W3     = (const float*)d_in[14];
    const float* b3     = (const float*)d_in[15];
    float* out = (float*)d_out;
    const int* src = ei;
    const int* dstp = ei + N_EDGES;

    float* pInv;
    __half *pA, *pB, *pPl, *pPr, *pWsT, *pW1T;
    int *pDegi, *pLoc, *pBsum, *pBoff, *pOff, *pCur, *pCsr;
    cudaGetSymbolAddress((void**)&pA, g_bufA);
    cudaGetSymbolAddress((void**)&pB, g_bufB);
    cudaGetSymbolAddress((void**)&pPl, g_Plh);
    cudaGetSymbolAddress((void**)&pPr, g_Prh);
    cudaGetSymbolAddress((void**)&pInv, g_inv);
    cudaGetSymbolAddress((void**)&pWsT, g_WsT);
    cudaGetSymbolAddress((void**)&pW1T, g_W1T);
    cudaGetSymbolAddress((void**)&pDegi, g_degi);
    cudaGetSymbolAddress((void**)&pLoc, g_loc);
    cudaGetSymbolAddress((void**)&pBsum, g_bsum);
    cudaGetSymbolAddress((void**)&pBoff, g_boff);
    cudaGetSymbolAddress((void**)&pOff, g_off);
    cudaGetSymbolAddress((void**)&pCur, g_cur);
    cudaGetSymbolAddress((void**)&pCsr, g_csr);

    // CSR build
    cudaMemsetAsync(pDegi, 0, N_NODES * sizeof(int));
    k_deg<<<(N_EDGES + 255) / 256, 256>>>(dstp, pDegi);
    k_inv<<<(N_NODES + 255) / 256, 256>>>(pDegi, pInv);
    k_scan1<<<NB, 256>>>(pDegi, pLoc, pBsum);
    k_scan2<<<1, 512>>>(pBsum, pBoff);
    k_scan3<<<(N_NODES + 255) / 256, 256>>>(pLoc, pBoff, pOff, pCur);
    k_csrfill<<<(N_EDGES + 255) / 256, 256>>>(src, dstp, pCur, pCsr);

    k_wprep<<<(3 * 128 * 256 + 255) / 256, 256>>>(sWl, sWr, W1, pWsT, pW1T);
    k_nodeproj<<<(N_NODES * 16 + 255) / 256, 256>>>(x, node_W, node_b, pA);

    cudaFuncSetAttribute(k_sage_mma, cudaFuncAttributeMaxDynamicSharedMemorySize, SG_SM);
    cudaFuncSetAttribute(k_plpr_mma, cudaFuncAttributeMaxDynamicSharedMemorySize, PP_SM);
    cudaFuncSetAttribute(k_edge, cudaFuncAttributeMaxDynamicSharedMemorySize, ESM_TOTAL);

    __half* hcur = pA;
    __half* other = pB;
    for (int l = 0; l < 3; l++) {
        k_gather<<<(N_NODES * 32 + 255) / 256, 256>>>(pOff, pCsr, hcur, pInv, other);
        k_sage_mma<<<(N_NODES + 127) / 128, 256, SG_SM>>>(
            hcur, other, pWsT + (size_t)l * 128 * 256, sbl + l * H,
            ln_g + l * H, ln_b + l * H);
        __half* tmp = hcur; hcur = other; other = tmp;
    }

    k_plpr_mma<<<(N_NODES + 63) / 64, 256, PP_SM>>>(hcur, pW1T, b1, pPl, pPr);

    k_edge<<<N_EDGES / TE, 256, ESM_TOTAL>>>(src, dstp, ea, pPl, pPr, W1, W2, b2, W3, b3, out);
}

// round 13
// speedup vs baseline: 3.8398x; 1.0572x over previous
#include <cuda_runtime.h>
#include <cuda_fp16.h>
#include <cstdint>

#define N_NODES 100000
#define N_EDGES 800000
#define H 128
#define HH (H*H)
#define NB ((N_NODES + 255) / 256)   // 391 scan blocks

// ---- scratch (no cudaMalloc allowed) ----
__device__ __half g_bufA[N_NODES * H];
__device__ __half g_bufB[N_NODES * H];
__device__ __half g_Plh[N_NODES * H];
__device__ __half g_Prh[N_NODES * H];
__device__ __half g_WsT[3 * H * 256];   // [l][n=128][k=256] : k<128 Wl^T, k>=128 Wr^T
__device__ __half g_W1T[256 * H];       // [n'=256][k=128]   : n'<128 Pl cols, else Pr
__device__ __half g_W2T[64 * H];        // [n=64][k=128] fp16 W2^T
// CSR scratch
__device__ int g_degi[N_NODES];
__device__ int g_loc[N_NODES];
__device__ int g_bsum[512];
__device__ int g_boff[512];
__device__ int g_off[N_NODES + 1];
__device__ int g_cur[N_NODES];
__device__ int g_csr[N_EDGES];

// ---- packed fp32x2 helpers ----
__device__ __forceinline__ unsigned long long pk2(float x, float y) {
    unsigned long long r;
    asm("mov.b64 %0, {%1, %2};" : "=l"(r) : "f"(x), "f"(y));
    return r;
}
__device__ __forceinline__ unsigned long long dup2(float x) { return pk2(x, x); }
__device__ __forceinline__ void fma2(unsigned long long& d, unsigned long long a,
                                     unsigned long long b) {
    asm("fma.rn.f32x2 %0, %1, %2, %0;" : "+l"(d) : "l"(a), "l"(b));
}
__device__ __forceinline__ float2 upk2(unsigned long long v) {
    float2 f;
    asm("mov.b64 {%0, %1}, %2;" : "=f"(f.x), "=f"(f.y) : "l"(v));
    return f;
}
// fp16 pack/unpack
__device__ __forceinline__ float2 h2f(unsigned int u) {
    __half2 h = *reinterpret_cast<__half2*>(&u);
    return __half22float2(h);
}
__device__ __forceinline__ unsigned int f2h2(float lo, float hi) {
    __half2 h = __floats2half2_rn(lo, hi);
    return *reinterpret_cast<unsigned int*>(&h);
}
__device__ __forceinline__ uint32_t smem_u32(const void* p) {
    uint32_t a;
    asm("{ .reg .u64 t; cvta.to.shared.u64 t, %1; cvt.u32.u64 %0, t; }" : "=r"(a) : "l"(p));
    return a;
}

// ---- mma helpers (verified R7/R9/R10/R11) ----
__device__ __forceinline__ void ldmA(uint32_t& a0, uint32_t& a1, uint32_t& a2, uint32_t& a3,
                                     uint32_t addr) {
    asm volatile("ldmatrix.sync.aligned.m8n8.x4.shared.b16 {%0,%1,%2,%3}, [%4];"
                 : "=r"(a0), "=r"(a1), "=r"(a2), "=r"(a3) : "r"(addr));
}
__device__ __forceinline__ void ldmB(uint32_t& b0, uint32_t& b1, uint32_t addr) {
    asm volatile("ldmatrix.sync.aligned.m8n8.x2.shared.b16 {%0,%1}, [%2];"
                 : "=r"(b0), "=r"(b1) : "r"(addr));
}
__device__ __forceinline__ void mma16816(float* c, uint32_t a0, uint32_t a1, uint32_t a2,
                                         uint32_t a3, uint32_t b0, uint32_t b1) {
    asm volatile(
        "mma.sync.aligned.m16n8k16.row.col.f32.f16.f16.f32 "
        "{%0,%1,%2,%3}, {%4,%5,%6,%7}, {%8,%9}, {%0,%1,%2,%3};"
        : "+f"(c[0]), "+f"(c[1]), "+f"(c[2]), "+f"(c[3])
        : "r"(a0), "r"(a1), "r"(a2), "r"(a3), "r"(b0), "r"(b1));
}

// ---------------- degree ----------------
__global__ void k_deg(const int* __restrict__ dst, int* __restrict__ degi) {
    int e = blockIdx.x * 256 + threadIdx.x;
    if (e < N_EDGES) atomicAdd(degi + dst[e], 1);
}

// ---------------- CSR build: block scan + fill ----------------
__global__ void k_scan1(const int* __restrict__ degi, int* __restrict__ loc,
                        int* __restrict__ bsum) {
    __shared__ int sm[256];
    int tid = threadIdx.x;
    int gid = blockIdx.x * 256 + tid;
    int v = (gid < N_NODES) ? degi[gid] : 0;
    sm[tid] = v;
    __syncthreads();
#pragma unroll
    for (int o = 1; o < 256; o <<= 1) {
        int y = (tid >= o) ? sm[tid - o] : 0;
        __syncthreads();
        sm[tid] += y;
        __syncthreads();
    }
    if (gid < N_NODES) loc[gid] = sm[tid] - v;
    if (tid == 255) bsum[blockIdx.x] = sm[255];
}
__global__ void k_scan2(const int* __restrict__ bsum, int* __restrict__ boff) {
    __shared__ int sm[512];
    int tid = threadIdx.x;
    int v = (tid < NB) ? bsum[tid] : 0;
    sm[tid] = v;
    __syncthreads();
#pragma unroll
    for (int o = 1; o < 512; o <<= 1) {
        int y = (tid >= o) ? sm[tid - o] : 0;
        __syncthreads();
        sm[tid] += y;
        __syncthreads();
    }
    if (tid < NB) boff[tid] = sm[tid] - v;
}
__global__ void k_scan3(const int* __restrict__ loc, const int* __restrict__ boff,
                        int* __restrict__ off, int* __restrict__ cur) {
    int gid = blockIdx.x * 256 + threadIdx.x;
    if (gid < N_NODES) {
        int o = loc[gid] + boff[gid >> 8];
        off[gid] = o;
        cur[gid] = o;
    }
    if (gid == 0) off[N_NODES] = N_EDGES;
}
__global__ void k_csrfill(const int* __restrict__ src, const int* __restrict__ dst,
                          int* __restrict__ cur, int* __restrict__ csr) {
    int e = blockIdx.x * 256 + threadIdx.x;
    if (e < N_EDGES) {
        int d = dst[e];
        int slot = atomicAdd(cur + d, 1);
        csr[slot] = src[e];
    }
}

// ---------------- weight prep: transposed fp16 copies (incl. W2^T) ----------------
__global__ void k_wprep(const float* __restrict__ sWl, const float* __restrict__ sWr,
                        const float* __restrict__ W1, const float* __restrict__ W2,
                        __half* __restrict__ WsT, __half* __restrict__ W1T,
                        __half* __restrict__ W2T) {
    int i = blockIdx.x * 256 + threadIdx.x;
    if (i < 3 * 128 * 256) {
        int l = i / (128 * 256);
        int rem = i - l * (128 * 256);
        int n = rem >> 8;
        int k = rem & 255;
        float v = (k < 128) ? sWl[l * HH + k * H + n] : sWr[l * HH + (k - 128) * H + n];
        WsT[i] = __float2half_rn(v);
    }
    if (i < 256 * 128) {
        int n = i >> 7, k = i & 127;
        float v = (n < 128) ? W1[k * H + n] : W1[(128 + k) * H + (n - 128)];
        W1T[i] = __float2half_rn(v);
    }
    if (i < 64 * 128) {
        int n = i >> 7, k = i & 127;
        W2T[i] = __float2half_rn(W2[k * 64 + n]);
    }
}

// ---------------- node projection -> fp16 h ----------------
__global__ void __launch_bounds__(256) k_nodeproj(
    const float* __restrict__ x, const float* __restrict__ W,
    const float* __restrict__ b, __half* __restrict__ h) {
    __shared__ float Ws[5 * 128];
    __shared__ float bs[128];
    int t = threadIdx.x;
    if (t < 128) bs[t] = b[t];
    for (int i = t; i < 640; i += 256) Ws[i] = W[i];
    __syncthreads();
    int id = blockIdx.x * 256 + t;
    int node = id >> 4;
    if (node >= N_NODES) return;
    int c0 = (id & 15) * 8;
    float xv[5];
#pragma unroll
    for (int k = 0; k < 5; k++) xv[k] = x[node * 5 + k];
    float a[8];
#pragma unroll
    for (int j = 0; j < 8; j++) a[j] = bs[c0 + j];
#pragma unroll
    for (int k = 0; k < 5; k++)
#pragma unroll
        for (int j = 0; j < 8; j++)
            a[j] = fmaf(xv[k], Ws[k * 128 + c0 + j], a[j]);
    uint4 o;
    o.x = f2h2(a[0], a[1]); o.y = f2h2(a[2], a[3]);
    o.z = f2h2(a[4], a[5]); o.w = f2h2(a[6], a[7]);
    *(uint4*)(h + (size_t)node * H + c0) = o;
}

// ---------------- CSR gather mean (inv fused from offsets) ----------------
__global__ void k_gather(const int* __restrict__ off, const int* __restrict__ csr,
                         const __half* __restrict__ h, __half* __restrict__ agg) {
    int node = (blockIdx.x * blockDim.x + threadIdx.x) >> 5;
    int lane = threadIdx.x & 31;
    if (node >= N_NODES) return;
    int b = off[node], e = off[node + 1];
    float a0 = 0.f, a1 = 0.f, a2 = 0.f, a3 = 0.f;
    for (int i = b; i < e; i++) {
        int s = csr[i];
        uint2 v = ((const uint2*)(h + (size_t)s * H))[lane];
        float2 f0 = h2f(v.x), f1 = h2f(v.y);
        a0 += f0.x; a1 += f0.y; a2 += f1.x; a3 += f1.y;
    }
    float iv = (e > b) ? 1.f / (float)(e - b) : 0.f;
    uint2 o;
    o.x = f2h2(a0 * iv, a1 * iv);
    o.y = f2h2(a2 * iv, a3 * iv);
    ((uint2*)(agg + (size_t)node * H))[lane] = o;
}

// ---------------- SAGE on HMMA fp16 (verified R11) ----------------
#define SG_AS 0            // 128*144 = 18432 B
#define SG_WS 18432        // 128*144 = 18432 B
#define SG_LN 36864        // 384 f32 = 1536 B
#define SG_SM 38400
__global__ void __launch_bounds__(256) k_sage_mma(
    const __half* __restrict__ hX, __half* __restrict__ aggY,
    const __half* __restrict__ WsTl, const float* __restrict__ bl,
    const float* __restrict__ lg, const float* __restrict__ lb)
{
    extern __shared__ char smc[];
    uint32_t sb = smem_u32(smc);
    int t = threadIdx.x, lane = t & 31, warp = t >> 5;
    int row0 = blockIdx.x * 128;
    float* lns = (float*)(smc + SG_LN);
    if (t < 128) { lns[t] = bl[t]; lns[128 + t] = lg[t]; lns[256 + t] = lb[t]; }

    float acc[16][4];
#pragma unroll
    for (int nt = 0; nt < 16; nt++)
#pragma unroll
        for (int m = 0; m < 4; m++) acc[nt][m] = 0.f;

    for (int c = 0; c < 4; c++) {
        const __half* Usrc = (c < 2) ? aggY : hX;
        int kcol = (c & 1) * 64;
        __syncthreads();
#pragma unroll
        for (int p = 0; p < 8; p++) {
            int id = t + p * 256;
            int r = id >> 4, fq = id & 15;
            int row = row0 + r;
            uint2 v = make_uint2(0u, 0u);
            if (row < N_NODES)
                v = *(const uint2*)(Usrc + (size_t)row * H + kcol + fq * 4);
            *(uint2*)(smc + SG_AS + r * 144 + fq * 8) = v;
        }
#pragma unroll
        for (int p = 0; p < 4; p++) {
            int id = t + p * 256;
            int n = id >> 3, q = id & 7;
            uint4 w = *(const uint4*)(WsTl + n * 256 + c * 64 + q * 8);
            *(uint4*)(smc + SG_WS + n * 144 + q * 16) = w;
        }
        __syncthreads();
        uint32_t a_base = sb + SG_AS + (uint32_t)(warp * 16 + (lane & 15)) * 144
                          + (uint32_t)(lane >> 4) * 16;
        uint32_t b_base = sb + SG_WS + (uint32_t)(lane & 7) * 144
                          + (uint32_t)((lane >> 3) & 1) * 16;
#pragma unroll
        for (int ks = 0; ks < 4; ks++) {
            uint32_t a0, a1, a2, a3;
            ldmA(a0, a1, a2, a3, a_base + ks * 32);
#pragma unroll
            for (int nt = 0; nt < 16; nt++) {
                uint32_t b0, b1;
                ldmB(b0, b1, b_base + (uint32_t)nt * 8 * 144 + ks * 32);
                mma16816(acc[nt], a0, a1, a2, a3, b0, b1);
            }
        }
    }

    int qr = lane >> 2, qc = (lane & 3) * 2;
    int r0 = row0 + warp * 16 + qr;
    int r1 = r0 + 8;
    float s0 = 0.f, s1 = 0.f;
#pragma unroll
    for (int nt = 0; nt < 16; nt++) {
        int c0 = nt * 8 + qc;
        float bb0 = lns[c0], bb1 = lns[c0 + 1];
        acc[nt][0] += bb0; acc[nt][1] += bb1;
        acc[nt][2] += bb0; acc[nt][3] += bb1;
        s0 += acc[nt][0] + acc[nt][1];
        s1 += acc[nt][2] + acc[nt][3];
    }
    s0 += __shfl_xor_sync(0xffffffffu, s0, 1);
    s0 += __shfl_xor_sync(0xffffffffu, s0, 2);
    s1 += __shfl_xor_sync(0xffffffffu, s1, 1);
    s1 += __shfl_xor_sync(0xffffffffu, s1, 2);
    float mu0 = s0 * (1.f / 128.f), mu1 = s1 * (1.f / 128.f);
    float q0 = 0.f, q1 = 0.f;
#pragma unroll
    for (int nt = 0; nt < 16; nt++) {
        float d0 = acc[nt][0] - mu0, d1 = acc[nt][1] - mu0;
        float d2 = acc[nt][2] - mu1, d3 = acc[nt][3] - mu1;
        q0 = fmaf(d0, d0, q0); q0 = fmaf(d1, d1, q0);
        q1 = fmaf(d2, d2, q1); q1 = fmaf(d3, d3, q1);
    }
    q0 += __shfl_xor_sync(0xffffffffu, q0, 1);
    q0 += __shfl_xor_sync(0xffffffffu, q0, 2);
    q1 += __shfl_xor_sync(0xffffffffu, q1, 1);
    q1 += __shfl_xor_sync(0xffffffffu, q1, 2);
    float rs0 = rsqrtf(q0 * (1.f / 128.f) + 1e-5f);
    float rs1 = rsqrtf(q1 * (1.f / 128.f) + 1e-5f);
#pragma unroll
    for (int nt = 0; nt < 16; nt++) {
        int c0 = nt * 8 + qc;
        float g0 = lns[128 + c0], g1 = lns[128 + c0 + 1];
        float o0 = lns[256 + c0], o1 = lns[256 + c0 + 1];
        if (r0 < N_NODES) {
            *(unsigned*)(aggY + (size_t)r0 * H + c0) = f2h2(
                fmaxf(fmaf((acc[nt][0] - mu0) * rs0, g0, o0), 0.f),
                fmaxf(fmaf((acc[nt][1] - mu0) * rs0, g1, o1), 0.f));
        }
        if (r1 < N_NODES) {
            *(unsigned*)(aggY + (size_t)r1 * H + c0) = f2h2(
                fmaxf(fmaf((acc[nt][2] - mu1) * rs1, g0, o0), 0.f),
                fmaxf(fmaf((acc[nt][3] - mu1) * rs1, g1, o1), 0.f));
        }
    }
}

// ---------------- Pl/Pr on HMMA fp16 (verified R10/R11) ----------------
#define PP_AS 0            // 64*272 = 17408 B
#define PP_WS 17408        // 256*272 = 69632 B
#define PP_B1 87040        // 128 f32
#define PP_SM 87552
__global__ void __launch_bounds__(256) k_plpr_mma(
    const __half* __restrict__ h, const __half* __restrict__ W1T,
    const float* __restrict__ b1,
    __half* __restrict__ Pl, __half* __restrict__ Pr)
{
    extern __shared__ char smc[];
    uint32_t sb = smem_u32(smc);
    int t = threadIdx.x, lane = t & 31, warp = t >> 5;
    int row0 = blockIdx.x * 64;
    int half_ = warp >> 2;
    int wm = warp & 3;
    float* b1s = (float*)(smc + PP_B1);
    if (t < 128) b1s[t] = b1[t];

#pragma unroll
    for (int p = 0; p < 4; p++) {
        int id = t + p * 256;
        int r = id >> 4, fq = id & 15;
        int row = row0 + r;
        uint4 v = make_uint4(0u, 0u, 0u, 0u);
        if (row < N_NODES)
            v = *(const uint4*)(h + (size_t)row * H + fq * 8);
        *(uint4*)(smc + PP_AS + r * 272 + fq * 16) = v;
    }
#pragma unroll
    for (int p = 0; p < 16; p++) {
        int id = t + p * 256;
        int n = id >> 4, q = id & 15;
        uint4 w = *(const uint4*)(W1T + n * 128 + q * 8);
        *(uint4*)(smc + PP_WS + n * 272 + q * 16) = w;
    }
    __syncthreads();

    float acc[16][4];
#pragma unroll
    for (int nt = 0; nt < 16; nt++)
#pragma unroll
        for (int m = 0; m < 4; m++) acc[nt][m] = 0.f;

    uint32_t a_base = sb + PP_AS + (uint32_t)(wm * 16 + (lane & 15)) * 272
                      + (uint32_t)(lane >> 4) * 16;
    uint32_t b_base = sb + PP_WS + (uint32_t)half_ * 128 * 272
                      + (uint32_t)(lane & 7) * 272 + (uint32_t)((lane >> 3) & 1) * 16;
#pragma unroll
    for (int ks = 0; ks < 8; ks++) {
        uint32_t a0, a1, a2, a3;
        ldmA(a0, a1, a2, a3, a_base + ks * 32);
#pragma unroll
        for (int nt = 0; nt < 16; nt++) {
            uint32_t b0, b1v;
            ldmB(b0, b1v, b_base + (uint32_t)nt * 8 * 272 + ks * 32);
            mma16816(acc[nt], a0, a1, a2, a3, b0, b1v);
        }
    }

    int qr = lane >> 2, qc = (lane & 3) * 2;
    int r0 = row0 + wm * 16 + qr;
    int r1 = r0 + 8;
    __half* outp = half_ ? Pr : Pl;
#pragma unroll
    for (int nt = 0; nt < 16; nt++) {
        int c0 = nt * 8 + qc;
        float add0 = half_ ? 0.f : b1s[c0];
        float add1 = half_ ? 0.f : b1s[c0 + 1];
        if (r0 < N_NODES)
            *(unsigned*)(outp + (size_t)r0 * H + c0) = f2h2(acc[nt][0] + add0, acc[nt][1] + add1);
        if (r1 < N_NODES)
            *(unsigned*)(outp + (size_t)r1 * H + c0) = f2h2(acc[nt][2] + add0, acc[nt][3] + add1);
    }
}

// ---------------- fused edge MLP; TE=256, 512 threads, pre-converted W2T ------------
#define TE 256
#define ZST 136
#define EZ1_OFF   0                        // 256*272 = 69632
#define EW2T_OFF  69632                    // 64*272  = 17408
#define EW1_OFF   87040                    // 12*128 f32 = 6144
#define EW3_OFF   93184                    // 64 f32
#define EB2_OFF   93440                    // 64 f32
#define ESM_TOTAL 93696

__global__ void __launch_bounds__(512) k_edge(
    const int* __restrict__ src, const int* __restrict__ dst,
    const float* __restrict__ ea, const __half* __restrict__ Pl,
    const __half* __restrict__ Pr, const float* __restrict__ W1,
    const __half* __restrict__ W2T, const float* __restrict__ b2,
    const float* __restrict__ W3, const float* __restrict__ b3,
    float* __restrict__ out)
{
    extern __shared__ char smc[];
    uint32_t sb = smem_u32(smc);

    float* W1es = (float*)(smc + EW1_OFF);
    float* W3s  = (float*)(smc + EW3_OFF);
    float* b2s  = (float*)(smc + EB2_OFF);

    int t = threadIdx.x;

    // stage weights: W1e (fp32), W2T (fp16 raw copy), W3, b2
    for (int i = t; i < 12 * 128 / 4; i += 512)
        ((float4*)W1es)[i] = ((const float4*)(W1 + 256 * H))[i];
    if (t < 64) { W3s[t] = W3[t]; b2s[t] = b2[t]; }
#pragma unroll
    for (int p = 0; p < 2; p++) {
        int id = t + p * 512;               // 0..1023
        int n = id >> 4, q = id & 15;       // 16 uint4 per 128-k row
        uint4 w = *(const uint4*)(W2T + n * 128 + q * 8);
        *(uint4*)(smc + EW2T_OFF + n * 272 + q * 16) = w;
    }

    int e0 = blockIdx.x * TE;
    // ---- phase 1: two threads per edge (512 threads = 256 edges)
    {
        int el = t >> 1;               // 0..255
        int jh = t & 1;
        int eg = e0 + el;
        int s = src[eg], d = dst[eg];
        unsigned long long eadup[12];
#pragma unroll
        for (int k = 0; k < 12; k++) eadup[k] = dup2(ea[(size_t)eg * 12 + k]);

        __syncthreads();   // weights staged by ALL warps before any W1es read (R12 race fix)

        const uint4* pl4 = (const uint4*)(Pl + (size_t)s * H);
        const uint4* pr4 = (const uint4*)(Pr + (size_t)d * H);
#pragma unroll
        for (int g = 0; g < 8; g++) {
            int grp = jh * 8 + g;
            uint4 a = pl4[grp];
            uint4 b = pr4[grp];
            float2 pa, pb;
            unsigned long long s01, s23, s45, s67;
            pa = h2f(a.x); pb = h2f(b.x); s01 = pk2(pa.x + pb.x, pa.y + pb.y);
            pa = h2f(a.y); pb = h2f(b.y); s23 = pk2(pa.x + pb.x, pa.y + pb.y);
            pa = h2f(a.z); pb = h2f(b.z); s45 = pk2(pa.x + pb.x, pa.y + pb.y);
            pa = h2f(a.w); pb = h2f(b.w); s67 = pk2(pa.x + pb.x, pa.y + pb.y);
            int jb = grp * 8;
#pragma unroll
            for (int k = 0; k < 12; k++) {
                ulonglong2 w0 = *(const ulonglong2*)&W1es[k * 128 + jb];
                ulonglong2 w1 = *(const ulonglong2*)&W1es[k * 128 + jb + 4];
                fma2(s01, w0.x, eadup[k]);
                fma2(s23, w0.y, eadup[k]);
                fma2(s45, w1.x, eadup[k]);
                fma2(s67, w1.y, eadup[k]);
            }
            float2 f01 = upk2(s01), f23 = upk2(s23), f45 = upk2(s45), f67 = upk2(s67);
            uint4 pkd;
            pkd.x = f2h2(fmaxf(f01.x, 0.f), fmaxf(f01.y, 0.f));
            pkd.y = f2h2(fmaxf(f23.x, 0.f), fmaxf(f23.y, 0.f));
            pkd.z = f2h2(fmaxf(f45.x, 0.f), fmaxf(f45.y, 0.f));
            pkd.w = f2h2(fmaxf(f67.x, 0.f), fmaxf(f67.y, 0.f));
            *(uint4*)(smc + EZ1_OFF + el * (ZST * 2) + jb * 2) = pkd;
        }
    }
    __syncthreads();

    // ---- phase 2: HMMA, 16 warps x (M=16, N=64), K=128
    int lane = t & 31, warp = t >> 5;
    int m0 = warp * 16;
    float acc[8][4];
#pragma unroll
    for (int nt = 0; nt < 8; nt++)
#pragma unroll
        for (int m = 0; m < 4; m++) acc[nt][m] = 0.f;

    uint32_t a_base = sb + EZ1_OFF + (uint32_t)(m0 + (lane & 15)) * (ZST * 2)
                      + (uint32_t)(lane >> 4) * 16;
    uint32_t b_base = sb + EW2T_OFF + (uint32_t)(lane & 7) * (ZST * 2)
                      + (uint32_t)((lane >> 3) & 1) * 16;

#pragma unroll
    for (int ks = 0; ks < 8; ks++) {
        uint32_t a0, a1, a2, a3;
        ldmA(a0, a1, a2, a3, a_base + ks * 32);
#pragma unroll
        for (int nt = 0; nt < 8; nt++) {
            uint32_t b0, b1v;
            ldmB(b0, b1v, b_base + (uint32_t)nt * 8 * (ZST * 2) + ks * 32);
            mma16816(acc[nt], a0, a1, a2, a3, b0, b1v);
        }
    }

    int qr = lane >> 2;
    int qc = (lane & 3) * 2;
    float p0 = 0.f, p1 = 0.f;
#pragma unroll
    for (int nt = 0; nt < 8; nt++) {
        int c0 = nt * 8 + qc, c1 = c0 + 1;
        float w30 = W3s[c0], w31 = W3s[c1];
        float bb0 = b2s[c0], bb1 = b2s[c1];
        p0 = fmaf(fmaxf(acc[nt][0] + bb0, 0.f), w30, p0);
        p0 = fmaf(fmaxf(acc[nt][1] + bb1, 0.f), w31, p0);
        p1 = fmaf(fmaxf(acc[nt][2] + bb0, 0.f), w30, p1);
        p1 = fmaf(fmaxf(acc[nt][3] + bb1, 0.f), w31, p1);
    }
    p0 += __shfl_xor_sync(0xffffffffu, p0, 1);
    p0 += __shfl_xor_sync(0xffffffffu, p0, 2);
    p1 += __shfl_xor_sync(0xffffffffu, p1, 1);
    p1 += __shfl_xor_sync(0xffffffffu, p1, 2);
    if ((lane & 3) == 0) {
        float b3v = b3[0];
        float x0 = p0 + b3v;
        float x1 = p1 + b3v;
        out[e0 + m0 + qr]     = fmaxf(x0, 0.f) + log1pf(expf(-fabsf(x0)));
        out[e0 + m0 + qr + 8] = fmaxf(x1, 0.f) + log1pf(expf(-fabsf(x1)));
    }
}

// ---------------- launch ----------------
extern "C" void kernel_launch(void* const* d_in, const int* in_sizes, int n_in,
                              void* d_out, int out_size) {
    const float* x      = (const float*)d_in[0];
    const int*   ei     = (const int*)d_in[1];
    const float* ea     = (const float*)d_in[2];
    const float* node_W = (const float*)d_in[3];
    const float* node_b = (const float*)d_in[4];
    const float* sWl    = (const float*)d_in[5];
    const float* sbl    = (const float*)d_in[6];
    const float* sWr    = (const float*)d_in[7];
    const float* ln_g   = (const float*)d_in[8];
    const float* ln_b   = (const float*)d_in[9];
    const float* W1     = (const float*)d_in[10];
    const float* b1     = (const float*)d_in[11];
    const float* W2     = (const float*)d_in[12];
    const float* b2     = (const float*)d_in[13];
    const float* W3     = (const float*)d_in[14];
    const float* b3     = (const float*)d_in[15];
    float* out = (float*)d_out;
    const int* src = ei;
    const int* dstp = ei + N_EDGES;

    __half *pA, *pB, *pPl, *pPr, *pWsT, *pW1T, *pW2T;
    int *pDegi, *pLoc, *pBsum, *pBoff, *pOff, *pCur, *pCsr;
    cudaGetSymbolAddress((void**)&pA, g_bufA);
    cudaGetSymbolAddress((void**)&pB, g_bufB);
    cudaGetSymbolAddress((void**)&pPl, g_Plh);
    cudaGetSymbolAddress((void**)&pPr, g_Prh);
    cudaGetSymbolAddress((void**)&pWsT, g_WsT);
    cudaGetSymbolAddress((void**)&pW1T, g_W1T);
    cudaGetSymbolAddress((void**)&pW2T, g_W2T);
    cudaGetSymbolAddress((void**)&pDegi, g_degi);
    cudaGetSymbolAddress((void**)&pLoc, g_loc);
    cudaGetSymbolAddress((void**)&pBsum, g_bsum);
    cudaGetSymbolAddress((void**)&pBoff, g_boff);
    cudaGetSymbolAddress((void**)&pOff, g_off);
    cudaGetSymbolAddress((void**)&pCur, g_cur);
    cudaGetSymbolAddress((void**)&pCsr, g_csr);

    // CSR build
    cudaMemsetAsync(pDegi, 0, N_NODES * sizeof(int));
    k_deg<<<(N_EDGES + 255) / 256, 256>>>(dstp, pDegi);
    k_scan1<<<NB, 256>>>(pDegi, pLoc, pBsum);
    k_scan2<<<1, 512>>>(pBsum, pBoff);
    k_scan3<<<(N_NODES + 255) / 256, 256>>>(pLoc, pBoff, pOff, pCur);
    k_csrfill<<<(N_EDGES + 255) / 256, 256>>>(src, dstp, pCur, pCsr);

    k_wprep<<<(3 * 128 * 256 + 255) / 256, 256>>>(sWl, sWr, W1, W2, pWsT, pW1T, pW2T);
    k_nodeproj<<<(N_NODES * 16 + 255) / 256, 256>>>(x, node_W, node_b, pA);

    cudaFuncSetAttribute(k_sage_mma, cudaFuncAttributeMaxDynamicSharedMemorySize, SG_SM);
    cudaFuncSetAttribute(k_plpr_mma, cudaFuncAttributeMaxDynamicSharedMemorySize, PP_SM);
    cudaFuncSetAttribute(k_edge, cudaFuncAttributeMaxDynamicSharedMemorySize, ESM_TOTAL);

    __half* hcur = pA;
    __half* other = pB;
    for (int l = 0; l < 3; l++) {
        k_gather<<<(N_NODES * 32 + 255) / 256, 256>>>(pOff, pCsr, hcur, other);
        k_sage_mma<<<(N_NODES + 127) / 128, 256, SG_SM>>>(
            hcur, other, pWsT + (size_t)l * 128 * 256, sbl + l * H,
            ln_g + l * H, ln_b + l * H);
        __half* tmp = hcur; hcur = other; other = tmp;
    }

    k_plpr_mma<<<(N_NODES + 63) / 64, 256, PP_SM>>>(hcur, pW1T, b1, pPl, pPr);

    k_edge<<<N_EDGES / TE, 512, ESM_TOTAL>>>(src, dstp, ea, pPl, pPr, W1, pW2T, b2, W3, b3, out);
}